// round 6
// baseline (speedup 1.0000x reference)
#include <cuda_runtime.h>
#include <cuda_bf16.h>
#include <math.h>

// Problem constants
#define B_SZ 4
#define NSEQ 2048
#define CDIM 1024
#define NHEAD 16
#define HD 64
#define MROWS 8192
#define QKVDIM 3072
#define BHTOT 64

// ---------------------------------------------------------------------------
// Static device scratch (allocation-free kernel_launch)
// ---------------------------------------------------------------------------
__device__ __nv_bfloat16 g_ahi[MROWS * CDIM];     // x splits, later att splits
__device__ __nv_bfloat16 g_alo[MROWS * CDIM];
__device__ __nv_bfloat16 g_wqkvhi[QKVDIM * CDIM];
__device__ __nv_bfloat16 g_wqkvlo[QKVDIM * CDIM];
__device__ __nv_bfloat16 g_wprojhi[CDIM * CDIM];
__device__ __nv_bfloat16 g_wprojlo[CDIM * CDIM];
__device__ __nv_bfloat16 g_qhi[BHTOT * NSEQ * HD];
__device__ __nv_bfloat16 g_qlo[BHTOT * NSEQ * HD];
__device__ __nv_bfloat16 g_khi[BHTOT * NSEQ * HD];
__device__ __nv_bfloat16 g_klo[BHTOT * NSEQ * HD];
__device__ __nv_bfloat16 g_vhi[BHTOT * NSEQ * HD];
__device__ __nv_bfloat16 g_vlo[BHTOT * NSEQ * HD];

// ---------------------------------------------------------------------------
// Helpers
// ---------------------------------------------------------------------------
__device__ __forceinline__ unsigned smem_u32(const void* p) {
    unsigned a;
    asm("{ .reg .u64 t; cvta.to.shared.u64 t, %1; cvt.u32.u64 %0, t; }"
        : "=r"(a) : "l"(p));
    return a;
}

__device__ __forceinline__ void ldsm4(unsigned* r, unsigned a) {
    asm volatile("ldmatrix.sync.aligned.m8n8.x4.shared.b16 {%0,%1,%2,%3}, [%4];"
        : "=r"(r[0]), "=r"(r[1]), "=r"(r[2]), "=r"(r[3]) : "r"(a));
}
__device__ __forceinline__ void ldsm4t(unsigned* r, unsigned a) {
    asm volatile("ldmatrix.sync.aligned.m8n8.x4.trans.shared.b16 {%0,%1,%2,%3}, [%4];"
        : "=r"(r[0]), "=r"(r[1]), "=r"(r[2]), "=r"(r[3]) : "r"(a));
}
__device__ __forceinline__ void mma16816(float* d, const unsigned* a,
                                         unsigned b0, unsigned b1) {
    asm volatile(
        "mma.sync.aligned.m16n8k16.row.col.f32.bf16.bf16.f32 "
        "{%0,%1,%2,%3}, {%4,%5,%6,%7}, {%8,%9}, {%0,%1,%2,%3};"
        : "+f"(d[0]), "+f"(d[1]), "+f"(d[2]), "+f"(d[3])
        : "r"(a[0]), "r"(a[1]), "r"(a[2]), "r"(a[3]), "r"(b0), "r"(b1));
}

#define CP16(sa, g) \
    asm volatile("cp.async.cg.shared.global [%0], [%1], 16;" :: "r"(sa), "l"(g))
#define CP_COMMIT() asm volatile("cp.async.commit_group;")
#define CP_WAIT1()  asm volatile("cp.async.wait_group 1;")
#define CP_WAIT0()  asm volatile("cp.async.wait_group 0;")

// chunk swizzle: 128B rows, 8 x 16B chunks
__device__ __forceinline__ unsigned swz(int row, int chunk) {
    return (unsigned)(row * 128 + ((chunk ^ (row & 7)) * 16));
}

// FMA-only exp (no MUFU, no CVT). Valid for |x| <= ~80 (clamped below).
__device__ __forceinline__ float fast_exp(float x) {
    x = fmaxf(x, -80.f);
    float t = fmaf(x, 1.442695041f, 12582912.f);
    int ebits = __float_as_int(t) << 23;
    float fi = t - 12582912.f;
    float f = fmaf(x, 1.442695041f, -fi);
    float p = 1.3333558e-3f;
    p = fmaf(p, f, 9.6181291e-3f);
    p = fmaf(p, f, 5.5504109e-2f);
    p = fmaf(p, f, 2.4022651e-1f);
    p = fmaf(p, f, 6.9314718e-1f);
    p = fmaf(p, f, 1.0f);
    return __int_as_float(__float_as_int(p) + ebits);
}

__device__ __forceinline__ void split_pair(float x, float y,
                                           unsigned& hi, unsigned& lo) {
    __nv_bfloat16 hx = __float2bfloat16(x), hy = __float2bfloat16(y);
    float rx = x - __bfloat162float(hx);
    float ry = y - __bfloat162float(hy);
    __nv_bfloat162 H(hx, hy);
    __nv_bfloat162 L(__float2bfloat16(rx), __float2bfloat16(ry));
    hi = *reinterpret_cast<unsigned*>(&H);
    lo = *reinterpret_cast<unsigned*>(&L);
}

// ---------------------------------------------------------------------------
// float -> (bf16 hi, bf16 lo) split
// ---------------------------------------------------------------------------
__global__ __launch_bounds__(256) void split_hi_lo(
    const float* __restrict__ src, __nv_bfloat16* __restrict__ hi,
    __nv_bfloat16* __restrict__ lo, int n4)
{
    int i = blockIdx.x * 256 + threadIdx.x;
    if (i >= n4) return;
    float4 v = reinterpret_cast<const float4*>(src)[i];
    unsigned h01, l01, h23, l23;
    split_pair(v.x, v.y, h01, l01);
    split_pair(v.z, v.w, h23, l23);
    reinterpret_cast<unsigned*>(hi)[2 * i]     = h01;
    reinterpret_cast<unsigned*>(hi)[2 * i + 1] = h23;
    reinterpret_cast<unsigned*>(lo)[2 * i]     = l01;
    reinterpret_cast<unsigned*>(lo)[2 * i + 1] = l23;
}

// ---------------------------------------------------------------------------
// HMMA GEMM (NT): C[m,n] = sum_k A[m,k]*B[n,k], hi/lo 3-pass fused.
// 128x128 tile, BK=32 stage; hi (chunks 0-3) and lo (chunks 4-7) interleaved
// in the same 128B smem rows -> standard swizzle, conflict-free ldmatrix.
// 3-stage cp.async pipeline, 96KB smem -> 2 CTAs/SM. 256 threads.
// MODE 0: proj epilogue (bias, fp32 C).  MODE 1: fused RMSNorm+RoPE+split.
// ---------------------------------------------------------------------------
#define GS_STAGE 32768
#define GEMM_SMEM 98304
#define NSTAGES 32                   // K=1024 / 32

template <int MODE>
__global__ __launch_bounds__(256, 2) void gemm_hmma(
    const __nv_bfloat16* __restrict__ Ahi, const __nv_bfloat16* __restrict__ Alo,
    const __nv_bfloat16* __restrict__ Bhi, const __nv_bfloat16* __restrict__ Blo,
    const float* __restrict__ bias, float* __restrict__ C, int N,
    const float* __restrict__ cosb, const float* __restrict__ sinb,
    const float* __restrict__ qw, const float* __restrict__ kw,
    __nv_bfloat16* __restrict__ Qh, __nv_bfloat16* __restrict__ Ql,
    __nv_bfloat16* __restrict__ Kh, __nv_bfloat16* __restrict__ Kl,
    __nv_bfloat16* __restrict__ Vh, __nv_bfloat16* __restrict__ Vl)
{
    extern __shared__ __align__(128) char smc[];
    const unsigned sb = smem_u32(smc);
    const int t = threadIdx.x, lane = t & 31, wid = t >> 5;
    const int wm = wid & 1, wn = wid >> 1;
    const int m0 = blockIdx.y * 128, n0 = blockIdx.x * 128;
    const int K = 1024;
    const int grp = lane >> 3, ri = lane & 7;

    float acc[4][4][4];
#pragma unroll
    for (int a = 0; a < 4; a++)
#pragma unroll
        for (int b = 0; b < 4; b++)
#pragma unroll
            for (int c = 0; c < 4; c++) acc[a][b][c] = 0.f;

    // stage loader: A rows [hi ch0-3 | lo ch4-7], B rows likewise; 8 chunks/thread
    auto issue = [&](int s, int buf) {
        const int k0 = s * 32;
        const unsigned stb = sb + buf * GS_STAGE;
#pragma unroll
        for (int i = 0; i < 4; i++) {
            int idx = i * 256 + t;
            int r = idx >> 3, ch = idx & 7;
            const __nv_bfloat16* ga = (ch < 4 ? Ahi : Alo) +
                (size_t)(m0 + r) * K + k0 + (ch & 3) * 8;
            CP16(stb + swz(r, ch), ga);
            const __nv_bfloat16* gb = (ch < 4 ? Bhi : Blo) +
                (size_t)(n0 + r) * K + k0 + (ch & 3) * 8;
            CP16(stb + 16384 + swz(r, ch), gb);
        }
    };

    issue(0, 0); CP_COMMIT();
    issue(1, 1); CP_COMMIT();

    for (int it = 0; it < NSTAGES; it++) {
        if (it == NSTAGES - 1) { CP_WAIT0(); } else { CP_WAIT1(); }
        __syncthreads();
        if (it + 2 < NSTAGES) {
            issue(it + 2, (it + 2) % 3);
            CP_COMMIT();
        }
        const unsigned ab = sb + (it % 3) * GS_STAGE;
        const unsigned bb = ab + 16384;
#pragma unroll
        for (int k4 = 0; k4 < 2; k4++) {
            unsigned ah[4][4], al[4][4], bh[2][4], bl[2][4];
#pragma unroll
            for (int mt = 0; mt < 4; mt++) {
                int r = wm * 64 + mt * 16 + (grp & 1) * 8 + ri;
                int ch = k4 * 2 + (grp >> 1);
                ldsm4(ah[mt], ab + swz(r, ch));
                ldsm4(al[mt], ab + swz(r, ch + 4));
            }
#pragma unroll
            for (int np = 0; np < 2; np++) {
                int r = wn * 32 + np * 16 + ((grp >> 1) & 1) * 8 + ri;
                int ch = k4 * 2 + (grp & 1);
                ldsm4(bh[np], bb + swz(r, ch));
                ldsm4(bl[np], bb + swz(r, ch + 4));
            }
#pragma unroll
            for (int mt = 0; mt < 4; mt++)
#pragma unroll
                for (int np = 0; np < 2; np++) {
                    mma16816(acc[mt][2 * np],     ah[mt], bh[np][0], bh[np][1]);
                    mma16816(acc[mt][2 * np + 1], ah[mt], bh[np][2], bh[np][3]);
                }
#pragma unroll
            for (int mt = 0; mt < 4; mt++)
#pragma unroll
                for (int np = 0; np < 2; np++) {
                    mma16816(acc[mt][2 * np],     ah[mt], bl[np][0], bl[np][1]);
                    mma16816(acc[mt][2 * np + 1], ah[mt], bl[np][2], bl[np][3]);
                }
#pragma unroll
            for (int mt = 0; mt < 4; mt++)
#pragma unroll
                for (int np = 0; np < 2; np++) {
                    mma16816(acc[mt][2 * np],     al[mt], bh[np][0], bh[np][1]);
                    mma16816(acc[mt][2 * np + 1], al[mt], bh[np][2], bh[np][3]);
                }
        }
    }

    if (MODE == 0) {
        // ---- proj epilogue: bias + fp32 store ----
#pragma unroll
        for (int mt = 0; mt < 4; mt++)
#pragma unroll
            for (int nt = 0; nt < 4; nt++) {
                int col = n0 + wn * 32 + nt * 8 + (lane & 3) * 2;
                int r0 = m0 + wm * 64 + mt * 16 + (lane >> 2);
                float bx = bias[col], by = bias[col + 1];
                float2 v0 = make_float2(acc[mt][nt][0] + bx, acc[mt][nt][1] + by);
                float2 v1 = make_float2(acc[mt][nt][2] + bx, acc[mt][nt][3] + by);
                *reinterpret_cast<float2*>(&C[(size_t)r0 * N + col]) = v0;
                *reinterpret_cast<float2*>(&C[(size_t)(r0 + 8) * N + col]) = v1;
            }
    } else {
        // ---- fused prep epilogue: accs -> smem tile -> norm/rope/split ----
        __syncthreads();                 // all MMAs done; smem reusable
        float* tile = reinterpret_cast<float*>(smc);
#pragma unroll
        for (int mt = 0; mt < 4; mt++)
#pragma unroll
            for (int nt = 0; nt < 4; nt++) {
                int col = wn * 32 + nt * 8 + (lane & 3) * 2;
                int r0 = wm * 64 + mt * 16 + (lane >> 2);
                tile[r0 * 129 + col]           = acc[mt][nt][0];
                tile[r0 * 129 + col + 1]       = acc[mt][nt][1];
                tile[(r0 + 8) * 129 + col]     = acc[mt][nt][2];
                tile[(r0 + 8) * 129 + col + 1] = acc[mt][nt][3];
            }
        __syncthreads();
        if (t < 128) {
            const int m = m0 + t;
            const int bidx = m >> 11, n = m & 2047;
            const int sec = n0 >> 10;          // 0=q, 1=k, 2=v
            const int cw = n0 & 1023;
            const float* trow = tile + t * 129;
#pragma unroll
            for (int hh = 0; hh < 2; hh++) {
                const int h = (cw >> 6) + hh;
                const float* v = trow + hh * 64;
                size_t dst = (((size_t)(bidx * NHEAD + h)) * NSEQ + n) * HD;
                float outv[64];
#pragma unroll
                for (int d = 0; d < 64; d++) outv[d] = v[d];
                if (sec != 2) {
                    float ss = 0.f;
#pragma unroll
                    for (int d = 0; d < 64; d++) ss = fmaf(outv[d], outv[d], ss);
                    const float inv = rsqrtf(ss * (1.f / 64.f) + 1e-6f);
                    const float* W = (sec == 0) ? qw : kw;
                    const float scl = (sec == 0) ? 0.125f : 1.f;
#pragma unroll
                    for (int d = 0; d < 32; d++) {
                        float a = outv[d] * inv * W[d];
                        float bq = outv[d + 32] * inv * W[d + 32];
                        float c1 = cosb[(n << 6) + d], s1 = sinb[(n << 6) + d];
                        float c2 = cosb[(n << 6) + d + 32], s2 = sinb[(n << 6) + d + 32];
                        outv[d]      = (a * c1 - bq * s1) * scl;
                        outv[d + 32] = (bq * c2 + a * s2) * scl;
                    }
                }
                __nv_bfloat16 *H, *L;
                if (sec == 0)      { H = Qh; L = Ql; }
                else if (sec == 1) { H = Kh; L = Kl; }
                else               { H = Vh; L = Vl; }
#pragma unroll
                for (int d = 0; d < 64; d += 8) {
                    unsigned h0, l0, h1, l1, h2, l2, h3, l3;
                    split_pair(outv[d],     outv[d + 1], h0, l0);
                    split_pair(outv[d + 2], outv[d + 3], h1, l1);
                    split_pair(outv[d + 4], outv[d + 5], h2, l2);
                    split_pair(outv[d + 6], outv[d + 7], h3, l3);
                    uint4 Hv; Hv.x = h0; Hv.y = h1; Hv.z = h2; Hv.w = h3;
                    uint4 Lv; Lv.x = l0; Lv.y = l1; Lv.z = l2; Lv.w = l3;
                    *reinterpret_cast<uint4*>(&H[dst + d]) = Hv;
                    *reinterpret_cast<uint4*>(&L[dst + d]) = Lv;
                }
            }
        }
    }
}

// ---------------------------------------------------------------------------
// Flash attention on HMMA. 256 threads (8 warps, m16 each -> 128 q rows).
// KV tiles of 64, cp.async double-buffered. NO online max: RMS-normed q,k
// with RoPE give |s| <= 32, exp/sums stay well inside fp32 range.
// SMEM: Qhi 16K | Qlo 16K | stage{Khi,Klo,Vhi,Vlo}x2 = 32K + 64K = 96K
// ---------------------------------------------------------------------------
#define FA_SMEM 98304

__global__ __launch_bounds__(256, 2) void flash_hmma(
    const __nv_bfloat16* __restrict__ Qh, const __nv_bfloat16* __restrict__ Ql,
    const __nv_bfloat16* __restrict__ Kh, const __nv_bfloat16* __restrict__ Kl,
    const __nv_bfloat16* __restrict__ Vh, const __nv_bfloat16* __restrict__ Vl,
    __nv_bfloat16* __restrict__ Ohi, __nv_bfloat16* __restrict__ Olo)
{
    extern __shared__ __align__(128) char smc[];
    const unsigned sb = smem_u32(smc);
    const int t = threadIdx.x, lane = t & 31, w = t >> 5;
    const int bh = blockIdx.x, qt = blockIdx.y;
    const int b = bh >> 4, h = bh & 15;
    const int grp = lane >> 3, ri = lane & 7;

    const size_t qoff = ((size_t)bh * NSEQ + qt * 128) * HD;
    const size_t kvoff = (size_t)bh * NSEQ * HD;

    const __nv_bfloat16* mats[4] = {Kh, Kl, Vh, Vl};

    auto issue = [&](int j, int s) {
        const unsigned stb = sb + 32768 + s * 32768;
#pragma unroll
        for (int m = 0; m < 4; m++) {
            const __nv_bfloat16* g = mats[m] + kvoff + (size_t)(j * 64) * HD;
            const unsigned mb = stb + m * 8192;
#pragma unroll
            for (int i = 0; i < 2; i++) {
                int idx = i * 256 + t;
                int r = idx >> 3, ch = idx & 7;
                CP16(mb + swz(r, ch), g + (size_t)r * HD + ch * 8);
            }
        }
    };

    issue(0, 0);
    CP_COMMIT();

    // Q tiles -> smem (swizzled)
    {
#pragma unroll
        for (int i = 0; i < 4; i++) {
            int idx = i * 256 + t;
            int r = idx >> 3, ch = idx & 7;
            *reinterpret_cast<uint4*>(smc + swz(r, ch)) =
                *reinterpret_cast<const uint4*>(Qh + qoff + (size_t)r * HD + ch * 8);
            *reinterpret_cast<uint4*>(smc + 16384 + swz(r, ch)) =
                *reinterpret_cast<const uint4*>(Ql + qoff + (size_t)r * HD + ch * 8);
        }
    }
    __syncthreads();

    unsigned qh[4][4], ql[4][4];
#pragma unroll
    for (int kt = 0; kt < 4; kt++) {
        int r = w * 16 + (grp & 1) * 8 + ri;
        int ch = kt * 2 + (grp >> 1);
        ldsm4(qh[kt], sb + swz(r, ch));
        ldsm4(ql[kt], sb + 16384 + swz(r, ch));
    }

    float o[8][4];
#pragma unroll
    for (int d = 0; d < 8; d++)
#pragma unroll
        for (int c = 0; c < 4; c++) o[d][c] = 0.f;
    float l0r = 0.f, l1r = 0.f;

    for (int j = 0; j < NSEQ / 64; j++) {
        if (j + 1 < NSEQ / 64) {
            issue(j + 1, (j + 1) & 1);
            CP_COMMIT();
            CP_WAIT1();
        } else {
            CP_WAIT0();
        }
        __syncthreads();
        const unsigned stb = sb + 32768 + (j & 1) * 32768;

        // ---- S = Q K^T (3-pass hi/lo) ----
        float s[8][4];
#pragma unroll
        for (int nt = 0; nt < 8; nt++)
#pragma unroll
            for (int c = 0; c < 4; c++) s[nt][c] = 0.f;

#pragma unroll
        for (int kt = 0; kt < 4; kt++) {
#pragma unroll
            for (int np = 0; np < 4; np++) {
                int r = np * 16 + ((grp >> 1) & 1) * 8 + ri;
                int ch = kt * 2 + (grp & 1);
                unsigned kh[4], kl[4];
                ldsm4(kh, stb + swz(r, ch));
                ldsm4(kl, stb + 8192 + swz(r, ch));
                mma16816(s[2 * np],     qh[kt], kh[0], kh[1]);
                mma16816(s[2 * np + 1], qh[kt], kh[2], kh[3]);
                mma16816(s[2 * np],     qh[kt], kl[0], kl[1]);
                mma16816(s[2 * np + 1], qh[kt], kl[2], kl[3]);
                mma16816(s[2 * np],     ql[kt], kh[0], kh[1]);
                mma16816(s[2 * np + 1], ql[kt], kh[2], kh[3]);
            }
        }

        // ---- softmax numerators (no max subtraction needed) ----
        float ps0 = 0.f, ps1 = 0.f;
#pragma unroll
        for (int nt = 0; nt < 8; nt++) {
            s[nt][0] = fast_exp(s[nt][0]);
            s[nt][1] = fast_exp(s[nt][1]);
            s[nt][2] = fast_exp(s[nt][2]);
            s[nt][3] = fast_exp(s[nt][3]);
            ps0 += s[nt][0] + s[nt][1];
            ps1 += s[nt][2] + s[nt][3];
        }
        ps0 += __shfl_xor_sync(0xffffffffu, ps0, 1);
        ps0 += __shfl_xor_sync(0xffffffffu, ps0, 2);
        ps1 += __shfl_xor_sync(0xffffffffu, ps1, 1);
        ps1 += __shfl_xor_sync(0xffffffffu, ps1, 2);
        l0r += ps0;
        l1r += ps1;

        // ---- O += P V (3-pass hi/lo) ----
#pragma unroll
        for (int ct = 0; ct < 4; ct++) {
            unsigned ph[4], pl[4];
            split_pair(s[2 * ct][0],     s[2 * ct][1],     ph[0], pl[0]);
            split_pair(s[2 * ct][2],     s[2 * ct][3],     ph[1], pl[1]);
            split_pair(s[2 * ct + 1][0], s[2 * ct + 1][1], ph[2], pl[2]);
            split_pair(s[2 * ct + 1][2], s[2 * ct + 1][3], ph[3], pl[3]);
#pragma unroll
            for (int dp = 0; dp < 4; dp++) {
                int r = ct * 16 + (lane & 15);
                int ch = dp * 2 + (lane >> 4);
                unsigned vh[4], vl[4];
                ldsm4t(vh, stb + 16384 + swz(r, ch));
                ldsm4t(vl, stb + 24576 + swz(r, ch));
                mma16816(o[2 * dp],     ph, vh[0], vh[1]);
                mma16816(o[2 * dp + 1], ph, vh[2], vh[3]);
                mma16816(o[2 * dp],     ph, vl[0], vl[1]);
                mma16816(o[2 * dp + 1], ph, vl[2], vl[3]);
                mma16816(o[2 * dp],     pl, vh[0], vh[1]);
                mma16816(o[2 * dp + 1], pl, vh[2], vh[3]);
            }
        }
        __syncthreads();
    }

    // ---- epilogue: O/l -> hi/lo bf16 att in [B,N,C] layout ----
    const float inv0 = 1.0f / l0r, inv1 = 1.0f / l1r;
#pragma unroll
    for (int dt = 0; dt < 8; dt++) {
        int col = h * 64 + dt * 8 + (lane & 3) * 2;
        int r0 = qt * 128 + w * 16 + (lane >> 2);
        size_t i0 = ((size_t)b * NSEQ + r0) * CDIM + col;
        size_t i1 = ((size_t)b * NSEQ + r0 + 8) * CDIM + col;
        unsigned h0, l0, h1, l1;
        split_pair(o[dt][0] * inv0, o[dt][1] * inv0, h0, l0);
        split_pair(o[dt][2] * inv1, o[dt][3] * inv1, h1, l1);
        *reinterpret_cast<unsigned*>(&Ohi[i0]) = h0;
        *reinterpret_cast<unsigned*>(&Olo[i0]) = l0;
        *reinterpret_cast<unsigned*>(&Ohi[i1]) = h1;
        *reinterpret_cast<unsigned*>(&Olo[i1]) = l1;
    }
}

// ---------------------------------------------------------------------------
extern "C" void kernel_launch(void* const* d_in, const int* in_sizes, int n_in,
                              void* d_out, int out_size)
{
    const float* x      = (const float*)d_in[0];
    const float* cosb   = (const float*)d_in[1];
    const float* sinb   = (const float*)d_in[2];
    const float* w_qkv  = (const float*)d_in[3];
    const float* w_proj = (const float*)d_in[4];
    const float* b_proj = (const float*)d_in[5];
    const float* qw     = (const float*)d_in[6];
    const float* kw     = (const float*)d_in[7];
    float* out = (float*)d_out;

    __nv_bfloat16 *ahi, *alo, *wqh, *wql, *wph, *wpl;
    __nv_bfloat16 *qhi, *qlo, *khi, *klo, *vhi, *vlo;
    cudaGetSymbolAddress((void**)&ahi, g_ahi);
    cudaGetSymbolAddress((void**)&alo, g_alo);
    cudaGetSymbolAddress((void**)&wqh, g_wqkvhi);
    cudaGetSymbolAddress((void**)&wql, g_wqkvlo);
    cudaGetSymbolAddress((void**)&wph, g_wprojhi);
    cudaGetSymbolAddress((void**)&wpl, g_wprojlo);
    cudaGetSymbolAddress((void**)&qhi, g_qhi);
    cudaGetSymbolAddress((void**)&qlo, g_qlo);
    cudaGetSymbolAddress((void**)&khi, g_khi);
    cudaGetSymbolAddress((void**)&klo, g_klo);
    cudaGetSymbolAddress((void**)&vhi, g_vhi);
    cudaGetSymbolAddress((void**)&vlo, g_vlo);

    cudaFuncSetAttribute(gemm_hmma<0>,
                         cudaFuncAttributeMaxDynamicSharedMemorySize, GEMM_SMEM);
    cudaFuncSetAttribute(gemm_hmma<1>,
                         cudaFuncAttributeMaxDynamicSharedMemorySize, GEMM_SMEM);
    cudaFuncSetAttribute(flash_hmma,
                         cudaFuncAttributeMaxDynamicSharedMemorySize, FA_SMEM);

    // 0) hi/lo splits of x and both weights
    split_hi_lo<<<MROWS * CDIM / 4 / 256, 256>>>(x, ahi, alo, MROWS * CDIM / 4);
    split_hi_lo<<<QKVDIM * CDIM / 4 / 256, 256>>>(w_qkv, wqh, wql, QKVDIM * CDIM / 4);
    split_hi_lo<<<CDIM * CDIM / 4 / 256, 256>>>(w_proj, wph, wpl, CDIM * CDIM / 4);

    // 1) qkv = x @ w_qkv^T fused with rmsnorm+rope+split -> Q/K/V hi/lo
    gemm_hmma<1><<<dim3(QKVDIM / 128, MROWS / 128), 256, GEMM_SMEM>>>(
        ahi, alo, wqh, wql, nullptr, nullptr, QKVDIM,
        cosb, sinb, qw, kw, qhi, qlo, khi, klo, vhi, vlo);

    // 2) flash attention -> att hi/lo (into g_ahi/g_alo)
    flash_hmma<<<dim3(BHTOT, NSEQ / 128), 256, FA_SMEM>>>(
        qhi, qlo, khi, klo, vhi, vlo, ahi, alo);

    // 3) out = att @ w_proj^T + b
    gemm_hmma<0><<<dim3(CDIM / 128, MROWS / 128), 256, GEMM_SMEM>>>(
        ahi, alo, wph, wpl, b_proj, out, CDIM,
        nullptr, nullptr, nullptr, nullptr,
        nullptr, nullptr, nullptr, nullptr, nullptr, nullptr);
}

// round 7
// speedup vs baseline: 1.0203x; 1.0203x over previous
#include <cuda_runtime.h>
#include <cuda_bf16.h>
#include <math.h>

// Problem constants
#define B_SZ 4
#define NSEQ 2048
#define CDIM 1024
#define NHEAD 16
#define HD 64
#define MROWS 8192
#define QKVDIM 3072
#define BHTOT 64

// ---------------------------------------------------------------------------
// Static device scratch (allocation-free kernel_launch)
// ---------------------------------------------------------------------------
__device__ __nv_bfloat16 g_ahi[MROWS * CDIM];     // x splits, later att splits
__device__ __nv_bfloat16 g_alo[MROWS * CDIM];
__device__ __nv_bfloat16 g_wqkvhi[QKVDIM * CDIM];
__device__ __nv_bfloat16 g_wqkvlo[QKVDIM * CDIM];
__device__ __nv_bfloat16 g_wprojhi[CDIM * CDIM];
__device__ __nv_bfloat16 g_wprojlo[CDIM * CDIM];
__device__ __nv_bfloat16 g_qhi[BHTOT * NSEQ * HD];
__device__ __nv_bfloat16 g_qlo[BHTOT * NSEQ * HD];
__device__ __nv_bfloat16 g_khi[BHTOT * NSEQ * HD];
__device__ __nv_bfloat16 g_klo[BHTOT * NSEQ * HD];
__device__ __nv_bfloat16 g_vhi[BHTOT * NSEQ * HD];
__device__ __nv_bfloat16 g_vlo[BHTOT * NSEQ * HD];

// ---------------------------------------------------------------------------
// Helpers
// ---------------------------------------------------------------------------
__device__ __forceinline__ unsigned smem_u32(const void* p) {
    unsigned a;
    asm("{ .reg .u64 t; cvta.to.shared.u64 t, %1; cvt.u32.u64 %0, t; }"
        : "=r"(a) : "l"(p));
    return a;
}

__device__ __forceinline__ void ldsm4(unsigned* r, unsigned a) {
    asm volatile("ldmatrix.sync.aligned.m8n8.x4.shared.b16 {%0,%1,%2,%3}, [%4];"
        : "=r"(r[0]), "=r"(r[1]), "=r"(r[2]), "=r"(r[3]) : "r"(a));
}
__device__ __forceinline__ void ldsm4t(unsigned* r, unsigned a) {
    asm volatile("ldmatrix.sync.aligned.m8n8.x4.trans.shared.b16 {%0,%1,%2,%3}, [%4];"
        : "=r"(r[0]), "=r"(r[1]), "=r"(r[2]), "=r"(r[3]) : "r"(a));
}
__device__ __forceinline__ void mma16816(float* d, const unsigned* a,
                                         unsigned b0, unsigned b1) {
    asm volatile(
        "mma.sync.aligned.m16n8k16.row.col.f32.bf16.bf16.f32 "
        "{%0,%1,%2,%3}, {%4,%5,%6,%7}, {%8,%9}, {%0,%1,%2,%3};"
        : "+f"(d[0]), "+f"(d[1]), "+f"(d[2]), "+f"(d[3])
        : "r"(a[0]), "r"(a[1]), "r"(a[2]), "r"(a[3]), "r"(b0), "r"(b1));
}

#define CP16(sa, g) \
    asm volatile("cp.async.cg.shared.global [%0], [%1], 16;" :: "r"(sa), "l"(g))
#define CP_COMMIT() asm volatile("cp.async.commit_group;")
#define CP_WAIT1()  asm volatile("cp.async.wait_group 1;")
#define CP_WAIT0()  asm volatile("cp.async.wait_group 0;")

// chunk swizzle: 128B rows, 8 x 16B chunks
__device__ __forceinline__ unsigned swz(int row, int chunk) {
    return (unsigned)(row * 128 + ((chunk ^ (row & 7)) * 16));
}

// FMA-only exp (no MUFU, no CVT). Valid for |x| <= ~80 (clamped below).
__device__ __forceinline__ float fast_exp(float x) {
    x = fmaxf(x, -80.f);
    float t = fmaf(x, 1.442695041f, 12582912.f);
    int ebits = __float_as_int(t) << 23;
    float fi = t - 12582912.f;
    float f = fmaf(x, 1.442695041f, -fi);
    float p = 1.3333558e-3f;
    p = fmaf(p, f, 9.6181291e-3f);
    p = fmaf(p, f, 5.5504109e-2f);
    p = fmaf(p, f, 2.4022651e-1f);
    p = fmaf(p, f, 6.9314718e-1f);
    p = fmaf(p, f, 1.0f);
    return __int_as_float(__float_as_int(p) + ebits);
}

__device__ __forceinline__ void split_pair(float x, float y,
                                           unsigned& hi, unsigned& lo) {
    __nv_bfloat16 hx = __float2bfloat16(x), hy = __float2bfloat16(y);
    float rx = x - __bfloat162float(hx);
    float ry = y - __bfloat162float(hy);
    __nv_bfloat162 H(hx, hy);
    __nv_bfloat162 L(__float2bfloat16(rx), __float2bfloat16(ry));
    hi = *reinterpret_cast<unsigned*>(&H);
    lo = *reinterpret_cast<unsigned*>(&L);
}

// ---------------------------------------------------------------------------
// float -> (bf16 hi, bf16 lo) split
// ---------------------------------------------------------------------------
__global__ __launch_bounds__(256) void split_hi_lo(
    const float* __restrict__ src, __nv_bfloat16* __restrict__ hi,
    __nv_bfloat16* __restrict__ lo, int n4)
{
    int i = blockIdx.x * 256 + threadIdx.x;
    if (i >= n4) return;
    float4 v = reinterpret_cast<const float4*>(src)[i];
    unsigned h01, l01, h23, l23;
    split_pair(v.x, v.y, h01, l01);
    split_pair(v.z, v.w, h23, l23);
    reinterpret_cast<unsigned*>(hi)[2 * i]     = h01;
    reinterpret_cast<unsigned*>(hi)[2 * i + 1] = h23;
    reinterpret_cast<unsigned*>(lo)[2 * i]     = l01;
    reinterpret_cast<unsigned*>(lo)[2 * i + 1] = l23;
}

// ---------------------------------------------------------------------------
// HMMA GEMM (NT): C[m,n] = sum_k A[m,k]*B[n,k], hi/lo 3-pass fused.
// 128x128 tile, BK=64 stage holds {Ahi,Alo,Bhi,Blo}; 3 passes per stage.
// 3-stage cp.async pipeline (192KB smem, 1 CTA/SM), one sync per stage.
// MODE 0: proj epilogue (bias, fp32 C).  MODE 1: fused RMSNorm+RoPE+split.
// ---------------------------------------------------------------------------
#define GS_STAGE 65536
#define GEMM_SMEM (3 * GS_STAGE)     // 196608
#define NSTAGES 16                   // K=1024 / 64

template <int MODE>
__global__ __launch_bounds__(256, 1) void gemm_hmma(
    const __nv_bfloat16* __restrict__ Ahi, const __nv_bfloat16* __restrict__ Alo,
    const __nv_bfloat16* __restrict__ Bhi, const __nv_bfloat16* __restrict__ Blo,
    const float* __restrict__ bias, float* __restrict__ C, int N,
    const float* __restrict__ cosb, const float* __restrict__ sinb,
    const float* __restrict__ qw, const float* __restrict__ kw,
    __nv_bfloat16* __restrict__ Qh, __nv_bfloat16* __restrict__ Ql,
    __nv_bfloat16* __restrict__ Kh, __nv_bfloat16* __restrict__ Kl,
    __nv_bfloat16* __restrict__ Vh, __nv_bfloat16* __restrict__ Vl)
{
    extern __shared__ __align__(128) char smc[];
    const unsigned sb = smem_u32(smc);
    const int t = threadIdx.x, lane = t & 31, wid = t >> 5;
    const int wm = wid & 1, wn = wid >> 1;
    const int m0 = blockIdx.y * 128, n0 = blockIdx.x * 128;
    const int K = 1024;
    const int grp = lane >> 3, ri = lane & 7;

    float acc[4][4][4];
#pragma unroll
    for (int a = 0; a < 4; a++)
#pragma unroll
        for (int b = 0; b < 4; b++)
#pragma unroll
            for (int c = 0; c < 4; c++) acc[a][b][c] = 0.f;

    const __nv_bfloat16* srcs[4] = {
        Ahi + (size_t)m0 * K, Alo + (size_t)m0 * K,
        Bhi + (size_t)n0 * K, Blo + (size_t)n0 * K };

    // stage loader: 64KB = 4 mats x 128 rows x 8 chunks; 16 chunks/thread
    auto issue = [&](int s, int buf) {
        const int k0 = s * 64;
        const unsigned stb = sb + buf * GS_STAGE;
#pragma unroll
        for (int m = 0; m < 4; m++) {
            const unsigned mb = stb + m * 16384;
            const __nv_bfloat16* g = srcs[m] + k0;
#pragma unroll
            for (int i = 0; i < 4; i++) {
                int idx = i * 256 + t;
                int r = idx >> 3, ch = idx & 7;
                CP16(mb + swz(r, ch), g + (size_t)r * K + ch * 8);
            }
        }
    };

    issue(0, 0); CP_COMMIT();
    issue(1, 1); CP_COMMIT();

    for (int it = 0; it < NSTAGES; it++) {
        if (it == NSTAGES - 1) { CP_WAIT0(); } else { CP_WAIT1(); }
        __syncthreads();
        if (it + 2 < NSTAGES) {
            issue(it + 2, (it + 2) % 3);
            CP_COMMIT();
        }
        const unsigned stb = sb + (it % 3) * GS_STAGE;
        const unsigned abh = stb, abl = stb + 16384;
        const unsigned bbh = stb + 32768, bbl = stb + 49152;
#pragma unroll
        for (int k4 = 0; k4 < 4; k4++) {
            unsigned ah[4][4], al[4][4], bh[2][4], bl[2][4];
#pragma unroll
            for (int mt = 0; mt < 4; mt++) {
                int r = wm * 64 + mt * 16 + (grp & 1) * 8 + ri;
                int ch = k4 * 2 + (grp >> 1);
                ldsm4(ah[mt], abh + swz(r, ch));
                ldsm4(al[mt], abl + swz(r, ch));
            }
#pragma unroll
            for (int np = 0; np < 2; np++) {
                int r = wn * 32 + np * 16 + ((grp >> 1) & 1) * 8 + ri;
                int ch = k4 * 2 + (grp & 1);
                ldsm4(bh[np], bbh + swz(r, ch));
                ldsm4(bl[np], bbl + swz(r, ch));
            }
            // pass 1: Ahi * Bhi
#pragma unroll
            for (int mt = 0; mt < 4; mt++)
#pragma unroll
                for (int np = 0; np < 2; np++) {
                    mma16816(acc[mt][2 * np],     ah[mt], bh[np][0], bh[np][1]);
                    mma16816(acc[mt][2 * np + 1], ah[mt], bh[np][2], bh[np][3]);
                }
            // pass 2: Ahi * Blo
#pragma unroll
            for (int mt = 0; mt < 4; mt++)
#pragma unroll
                for (int np = 0; np < 2; np++) {
                    mma16816(acc[mt][2 * np],     ah[mt], bl[np][0], bl[np][1]);
                    mma16816(acc[mt][2 * np + 1], ah[mt], bl[np][2], bl[np][3]);
                }
            // pass 3: Alo * Bhi
#pragma unroll
            for (int mt = 0; mt < 4; mt++)
#pragma unroll
                for (int np = 0; np < 2; np++) {
                    mma16816(acc[mt][2 * np],     al[mt], bh[np][0], bh[np][1]);
                    mma16816(acc[mt][2 * np + 1], al[mt], bh[np][2], bh[np][3]);
                }
        }
    }

    if (MODE == 0) {
        // ---- proj epilogue: bias + fp32 store ----
#pragma unroll
        for (int mt = 0; mt < 4; mt++)
#pragma unroll
            for (int nt = 0; nt < 4; nt++) {
                int col = n0 + wn * 32 + nt * 8 + (lane & 3) * 2;
                int r0 = m0 + wm * 64 + mt * 16 + (lane >> 2);
                float bx = bias[col], by = bias[col + 1];
                float2 v0 = make_float2(acc[mt][nt][0] + bx, acc[mt][nt][1] + by);
                float2 v1 = make_float2(acc[mt][nt][2] + bx, acc[mt][nt][3] + by);
                *reinterpret_cast<float2*>(&C[(size_t)r0 * N + col]) = v0;
                *reinterpret_cast<float2*>(&C[(size_t)(r0 + 8) * N + col]) = v1;
            }
    } else {
        // ---- fused prep epilogue: accs -> smem tile -> norm/rope/split ----
        __syncthreads();                 // all MMAs done; smem reusable
        float* tile = reinterpret_cast<float*>(smc);
#pragma unroll
        for (int mt = 0; mt < 4; mt++)
#pragma unroll
            for (int nt = 0; nt < 4; nt++) {
                int col = wn * 32 + nt * 8 + (lane & 3) * 2;
                int r0 = wm * 64 + mt * 16 + (lane >> 2);
                tile[r0 * 129 + col]           = acc[mt][nt][0];
                tile[r0 * 129 + col + 1]       = acc[mt][nt][1];
                tile[(r0 + 8) * 129 + col]     = acc[mt][nt][2];
                tile[(r0 + 8) * 129 + col + 1] = acc[mt][nt][3];
            }
        __syncthreads();
        {
            const int row = t & 127;           // tile row
            const int hh = t >> 7;             // which head within the tile
            const int m = m0 + row;
            const int bidx = m >> 11, n = m & 2047;
            const int sec = n0 >> 10;          // 0=q, 1=k, 2=v
            const int h = ((n0 & 1023) >> 6) + hh;
            const float* v = tile + row * 129 + hh * 64;
            size_t dst = (((size_t)(bidx * NHEAD + h)) * NSEQ + n) * HD;
            float outv[64];
#pragma unroll
            for (int d = 0; d < 64; d++) outv[d] = v[d];
            if (sec != 2) {
                float ss = 0.f;
#pragma unroll
                for (int d = 0; d < 64; d++) ss = fmaf(outv[d], outv[d], ss);
                const float inv = rsqrtf(ss * (1.f / 64.f) + 1e-6f);
                const float* W = (sec == 0) ? qw : kw;
                const float scl = (sec == 0) ? 0.125f : 1.f;
#pragma unroll
                for (int d = 0; d < 32; d++) {
                    float a = outv[d] * inv * W[d];
                    float bq = outv[d + 32] * inv * W[d + 32];
                    float c1 = cosb[(n << 6) + d], s1 = sinb[(n << 6) + d];
                    float c2 = cosb[(n << 6) + d + 32], s2 = sinb[(n << 6) + d + 32];
                    outv[d]      = (a * c1 - bq * s1) * scl;
                    outv[d + 32] = (bq * c2 + a * s2) * scl;
                }
            }
            __nv_bfloat16 *H, *L;
            if (sec == 0)      { H = Qh; L = Ql; }
            else if (sec == 1) { H = Kh; L = Kl; }
            else               { H = Vh; L = Vl; }
#pragma unroll
            for (int d = 0; d < 64; d += 8) {
                unsigned h0, l0, h1, l1, h2, l2, h3, l3;
                split_pair(outv[d],     outv[d + 1], h0, l0);
                split_pair(outv[d + 2], outv[d + 3], h1, l1);
                split_pair(outv[d + 4], outv[d + 5], h2, l2);
                split_pair(outv[d + 6], outv[d + 7], h3, l3);
                uint4 Hv; Hv.x = h0; Hv.y = h1; Hv.z = h2; Hv.w = h3;
                uint4 Lv; Lv.x = l0; Lv.y = l1; Lv.z = l2; Lv.w = l3;
                *reinterpret_cast<uint4*>(&H[dst + d]) = Hv;
                *reinterpret_cast<uint4*>(&L[dst + d]) = Lv;
            }
        }
    }
}

// ---------------------------------------------------------------------------
// Flash attention on HMMA. 256 threads (8 warps, m16 each -> 128 q rows).
// KV tiles of 64, cp.async double-buffered. NO online max: RMS-normed q,k
// with RoPE give |s| <= 32, exp/sums stay well inside fp32 range.
// SMEM: Qhi 16K | Qlo 16K | stage{Khi,Klo,Vhi,Vlo}x2 = 32K + 64K = 96K
// ---------------------------------------------------------------------------
#define FA_SMEM 98304

__global__ __launch_bounds__(256, 2) void flash_hmma(
    const __nv_bfloat16* __restrict__ Qh, const __nv_bfloat16* __restrict__ Ql,
    const __nv_bfloat16* __restrict__ Kh, const __nv_bfloat16* __restrict__ Kl,
    const __nv_bfloat16* __restrict__ Vh, const __nv_bfloat16* __restrict__ Vl,
    __nv_bfloat16* __restrict__ Ohi, __nv_bfloat16* __restrict__ Olo)
{
    extern __shared__ __align__(128) char smc[];
    const unsigned sb = smem_u32(smc);
    const int t = threadIdx.x, lane = t & 31, w = t >> 5;
    const int bh = blockIdx.x, qt = blockIdx.y;
    const int b = bh >> 4, h = bh & 15;
    const int grp = lane >> 3, ri = lane & 7;

    const size_t qoff = ((size_t)bh * NSEQ + qt * 128) * HD;
    const size_t kvoff = (size_t)bh * NSEQ * HD;

    const __nv_bfloat16* mats[4] = {Kh, Kl, Vh, Vl};

    auto issue = [&](int j, int s) {
        const unsigned stb = sb + 32768 + s * 32768;
#pragma unroll
        for (int m = 0; m < 4; m++) {
            const __nv_bfloat16* g = mats[m] + kvoff + (size_t)(j * 64) * HD;
            const unsigned mb = stb + m * 8192;
#pragma unroll
            for (int i = 0; i < 2; i++) {
                int idx = i * 256 + t;
                int r = idx >> 3, ch = idx & 7;
                CP16(mb + swz(r, ch), g + (size_t)r * HD + ch * 8);
            }
        }
    };

    issue(0, 0);
    CP_COMMIT();

    // Q tiles -> smem (swizzled)
    {
#pragma unroll
        for (int i = 0; i < 4; i++) {
            int idx = i * 256 + t;
            int r = idx >> 3, ch = idx & 7;
            *reinterpret_cast<uint4*>(smc + swz(r, ch)) =
                *reinterpret_cast<const uint4*>(Qh + qoff + (size_t)r * HD + ch * 8);
            *reinterpret_cast<uint4*>(smc + 16384 + swz(r, ch)) =
                *reinterpret_cast<const uint4*>(Ql + qoff + (size_t)r * HD + ch * 8);
        }
    }
    __syncthreads();

    unsigned qh[4][4], ql[4][4];
#pragma unroll
    for (int kt = 0; kt < 4; kt++) {
        int r = w * 16 + (grp & 1) * 8 + ri;
        int ch = kt * 2 + (grp >> 1);
        ldsm4(qh[kt], sb + swz(r, ch));
        ldsm4(ql[kt], sb + 16384 + swz(r, ch));
    }

    float o[8][4];
#pragma unroll
    for (int d = 0; d < 8; d++)
#pragma unroll
        for (int c = 0; c < 4; c++) o[d][c] = 0.f;
    float l0r = 0.f, l1r = 0.f;

    for (int j = 0; j < NSEQ / 64; j++) {
        if (j + 1 < NSEQ / 64) {
            issue(j + 1, (j + 1) & 1);
            CP_COMMIT();
            CP_WAIT1();
        } else {
            CP_WAIT0();
        }
        __syncthreads();
        const unsigned stb = sb + 32768 + (j & 1) * 32768;

        // ---- S = Q K^T (3-pass hi/lo) ----
        float s[8][4];
#pragma unroll
        for (int nt = 0; nt < 8; nt++)
#pragma unroll
            for (int c = 0; c < 4; c++) s[nt][c] = 0.f;

#pragma unroll
        for (int kt = 0; kt < 4; kt++) {
#pragma unroll
            for (int np = 0; np < 4; np++) {
                int r = np * 16 + ((grp >> 1) & 1) * 8 + ri;
                int ch = kt * 2 + (grp & 1);
                unsigned kh[4], kl[4];
                ldsm4(kh, stb + swz(r, ch));
                ldsm4(kl, stb + 8192 + swz(r, ch));
                mma16816(s[2 * np],     qh[kt], kh[0], kh[1]);
                mma16816(s[2 * np + 1], qh[kt], kh[2], kh[3]);
                mma16816(s[2 * np],     qh[kt], kl[0], kl[1]);
                mma16816(s[2 * np + 1], qh[kt], kl[2], kl[3]);
                mma16816(s[2 * np],     ql[kt], kh[0], kh[1]);
                mma16816(s[2 * np + 1], ql[kt], kh[2], kh[3]);
            }
        }

        // ---- softmax numerators (no max subtraction needed) ----
        float ps0 = 0.f, ps1 = 0.f;
#pragma unroll
        for (int nt = 0; nt < 8; nt++) {
            s[nt][0] = fast_exp(s[nt][0]);
            s[nt][1] = fast_exp(s[nt][1]);
            s[nt][2] = fast_exp(s[nt][2]);
            s[nt][3] = fast_exp(s[nt][3]);
            ps0 += s[nt][0] + s[nt][1];
            ps1 += s[nt][2] + s[nt][3];
        }
        ps0 += __shfl_xor_sync(0xffffffffu, ps0, 1);
        ps0 += __shfl_xor_sync(0xffffffffu, ps0, 2);
        ps1 += __shfl_xor_sync(0xffffffffu, ps1, 1);
        ps1 += __shfl_xor_sync(0xffffffffu, ps1, 2);
        l0r += ps0;
        l1r += ps1;

        // ---- O += P V (3-pass hi/lo) ----
#pragma unroll
        for (int ct = 0; ct < 4; ct++) {
            unsigned ph[4], pl[4];
            split_pair(s[2 * ct][0],     s[2 * ct][1],     ph[0], pl[0]);
            split_pair(s[2 * ct][2],     s[2 * ct][3],     ph[1], pl[1]);
            split_pair(s[2 * ct + 1][0], s[2 * ct + 1][1], ph[2], pl[2]);
            split_pair(s[2 * ct + 1][2], s[2 * ct + 1][3], ph[3], pl[3]);
#pragma unroll
            for (int dp = 0; dp < 4; dp++) {
                int r = ct * 16 + (lane & 15);
                int ch = dp * 2 + (lane >> 4);
                unsigned vh[4], vl[4];
                ldsm4t(vh, stb + 16384 + swz(r, ch));
                ldsm4t(vl, stb + 24576 + swz(r, ch));
                mma16816(o[2 * dp],     ph, vh[0], vh[1]);
                mma16816(o[2 * dp + 1], ph, vh[2], vh[3]);
                mma16816(o[2 * dp],     ph, vl[0], vl[1]);
                mma16816(o[2 * dp + 1], ph, vl[2], vl[3]);
                mma16816(o[2 * dp],     pl, vh[0], vh[1]);
                mma16816(o[2 * dp + 1], pl, vh[2], vh[3]);
            }
        }
        __syncthreads();
    }

    // ---- epilogue: O/l -> hi/lo bf16 att in [B,N,C] layout ----
    const float inv0 = 1.0f / l0r, inv1 = 1.0f / l1r;
#pragma unroll
    for (int dt = 0; dt < 8; dt++) {
        int col = h * 64 + dt * 8 + (lane & 3) * 2;
        int r0 = qt * 128 + w * 16 + (lane >> 2);
        size_t i0 = ((size_t)b * NSEQ + r0) * CDIM + col;
        size_t i1 = ((size_t)b * NSEQ + r0 + 8) * CDIM + col;
        unsigned h0, l0, h1, l1;
        split_pair(o[dt][0] * inv0, o[dt][1] * inv0, h0, l0);
        split_pair(o[dt][2] * inv1, o[dt][3] * inv1, h1, l1);
        *reinterpret_cast<unsigned*>(&Ohi[i0]) = h0;
        *reinterpret_cast<unsigned*>(&Olo[i0]) = l0;
        *reinterpret_cast<unsigned*>(&Ohi[i1]) = h1;
        *reinterpret_cast<unsigned*>(&Olo[i1]) = l1;
    }
}

// ---------------------------------------------------------------------------
extern "C" void kernel_launch(void* const* d_in, const int* in_sizes, int n_in,
                              void* d_out, int out_size)
{
    const float* x      = (const float*)d_in[0];
    const float* cosb   = (const float*)d_in[1];
    const float* sinb   = (const float*)d_in[2];
    const float* w_qkv  = (const float*)d_in[3];
    const float* w_proj = (const float*)d_in[4];
    const float* b_proj = (const float*)d_in[5];
    const float* qw     = (const float*)d_in[6];
    const float* kw     = (const float*)d_in[7];
    float* out = (float*)d_out;

    __nv_bfloat16 *ahi, *alo, *wqh, *wql, *wph, *wpl;
    __nv_bfloat16 *qhi, *qlo, *khi, *klo, *vhi, *vlo;
    cudaGetSymbolAddress((void**)&ahi, g_ahi);
    cudaGetSymbolAddress((void**)&alo, g_alo);
    cudaGetSymbolAddress((void**)&wqh, g_wqkvhi);
    cudaGetSymbolAddress((void**)&wql, g_wqkvlo);
    cudaGetSymbolAddress((void**)&wph, g_wprojhi);
    cudaGetSymbolAddress((void**)&wpl, g_wprojlo);
    cudaGetSymbolAddress((void**)&qhi, g_qhi);
    cudaGetSymbolAddress((void**)&qlo, g_qlo);
    cudaGetSymbolAddress((void**)&khi, g_khi);
    cudaGetSymbolAddress((void**)&klo, g_klo);
    cudaGetSymbolAddress((void**)&vhi, g_vhi);
    cudaGetSymbolAddress((void**)&vlo, g_vlo);

    cudaFuncSetAttribute(gemm_hmma<0>,
                         cudaFuncAttributeMaxDynamicSharedMemorySize, GEMM_SMEM);
    cudaFuncSetAttribute(gemm_hmma<1>,
                         cudaFuncAttributeMaxDynamicSharedMemorySize, GEMM_SMEM);
    cudaFuncSetAttribute(flash_hmma,
                         cudaFuncAttributeMaxDynamicSharedMemorySize, FA_SMEM);

    // 0) hi/lo splits of x and both weights
    split_hi_lo<<<MROWS * CDIM / 4 / 256, 256>>>(x, ahi, alo, MROWS * CDIM / 4);
    split_hi_lo<<<QKVDIM * CDIM / 4 / 256, 256>>>(w_qkv, wqh, wql, QKVDIM * CDIM / 4);
    split_hi_lo<<<CDIM * CDIM / 4 / 256, 256>>>(w_proj, wph, wpl, CDIM * CDIM / 4);

    // 1) qkv = x @ w_qkv^T fused with rmsnorm+rope+split -> Q/K/V hi/lo
    gemm_hmma<1><<<dim3(QKVDIM / 128, MROWS / 128), 256, GEMM_SMEM>>>(
        ahi, alo, wqh, wql, nullptr, nullptr, QKVDIM,
        cosb, sinb, qw, kw, qhi, qlo, khi, klo, vhi, vlo);

    // 2) flash attention -> att hi/lo (into g_ahi/g_alo)
    flash_hmma<<<dim3(BHTOT, NSEQ / 128), 256, FA_SMEM>>>(
        qhi, qlo, khi, klo, vhi, vlo, ahi, alo);

    // 3) out = att @ w_proj^T + b
    gemm_hmma<0><<<dim3(CDIM / 128, MROWS / 128), 256, GEMM_SMEM>>>(
        ahi, alo, wph, wpl, b_proj, out, CDIM,
        nullptr, nullptr, nullptr, nullptr,
        nullptr, nullptr, nullptr, nullptr, nullptr, nullptr);
}

// round 8
// speedup vs baseline: 1.0212x; 1.0009x over previous
#include <cuda_runtime.h>
#include <cuda_bf16.h>
#include <math.h>

// Problem constants
#define B_SZ 4
#define NSEQ 2048
#define CDIM 1024
#define NHEAD 16
#define HD 64
#define MROWS 8192
#define QKVDIM 3072
#define BHTOT 64

// ---------------------------------------------------------------------------
// Static device scratch (allocation-free kernel_launch)
// ---------------------------------------------------------------------------
__device__ __nv_bfloat16 g_ahi[MROWS * CDIM];     // x splits, later att splits
__device__ __nv_bfloat16 g_alo[MROWS * CDIM];
__device__ __nv_bfloat16 g_wqkvhi[QKVDIM * CDIM];
__device__ __nv_bfloat16 g_wqkvlo[QKVDIM * CDIM];
__device__ __nv_bfloat16 g_wprojhi[CDIM * CDIM];
__device__ __nv_bfloat16 g_wprojlo[CDIM * CDIM];
__device__ __nv_bfloat16 g_qhi[BHTOT * NSEQ * HD];
__device__ __nv_bfloat16 g_qlo[BHTOT * NSEQ * HD];
__device__ __nv_bfloat16 g_khi[BHTOT * NSEQ * HD];
__device__ __nv_bfloat16 g_klo[BHTOT * NSEQ * HD];
__device__ __nv_bfloat16 g_vhi[BHTOT * NSEQ * HD];
__device__ __nv_bfloat16 g_vlo[BHTOT * NSEQ * HD];

// ---------------------------------------------------------------------------
// Helpers
// ---------------------------------------------------------------------------
__device__ __forceinline__ unsigned smem_u32(const void* p) {
    unsigned a;
    asm("{ .reg .u64 t; cvta.to.shared.u64 t, %1; cvt.u32.u64 %0, t; }"
        : "=r"(a) : "l"(p));
    return a;
}

__device__ __forceinline__ void ldsm4(unsigned* r, unsigned a) {
    asm volatile("ldmatrix.sync.aligned.m8n8.x4.shared.b16 {%0,%1,%2,%3}, [%4];"
        : "=r"(r[0]), "=r"(r[1]), "=r"(r[2]), "=r"(r[3]) : "r"(a));
}
__device__ __forceinline__ void ldsm4t(unsigned* r, unsigned a) {
    asm volatile("ldmatrix.sync.aligned.m8n8.x4.trans.shared.b16 {%0,%1,%2,%3}, [%4];"
        : "=r"(r[0]), "=r"(r[1]), "=r"(r[2]), "=r"(r[3]) : "r"(a));
}
__device__ __forceinline__ void mma16816(float* d, const unsigned* a,
                                         unsigned b0, unsigned b1) {
    asm volatile(
        "mma.sync.aligned.m16n8k16.row.col.f32.bf16.bf16.f32 "
        "{%0,%1,%2,%3}, {%4,%5,%6,%7}, {%8,%9}, {%0,%1,%2,%3};"
        : "+f"(d[0]), "+f"(d[1]), "+f"(d[2]), "+f"(d[3])
        : "r"(a[0]), "r"(a[1]), "r"(a[2]), "r"(a[3]), "r"(b0), "r"(b1));
}

#define CP16(sa, g) \
    asm volatile("cp.async.cg.shared.global [%0], [%1], 16;" :: "r"(sa), "l"(g))
#define CP_COMMIT() asm volatile("cp.async.commit_group;")
#define CP_WAIT1()  asm volatile("cp.async.wait_group 1;")
#define CP_WAIT0()  asm volatile("cp.async.wait_group 0;")

// chunk swizzle: 128B rows, 8 x 16B chunks
__device__ __forceinline__ unsigned swz(int row, int chunk) {
    return (unsigned)(row * 128 + ((chunk ^ (row & 7)) * 16));
}

// FMA-only exp (no MUFU, no CVT). Valid for |x| <= ~80 (clamped below).
__device__ __forceinline__ float fast_exp(float x) {
    x = fmaxf(x, -80.f);
    float t = fmaf(x, 1.442695041f, 12582912.f);
    int ebits = __float_as_int(t) << 23;
    float fi = t - 12582912.f;
    float f = fmaf(x, 1.442695041f, -fi);
    float p = 1.3333558e-3f;
    p = fmaf(p, f, 9.6181291e-3f);
    p = fmaf(p, f, 5.5504109e-2f);
    p = fmaf(p, f, 2.4022651e-1f);
    p = fmaf(p, f, 6.9314718e-1f);
    p = fmaf(p, f, 1.0f);
    return __int_as_float(__float_as_int(p) + ebits);
}

__device__ __forceinline__ void split_pair(float x, float y,
                                           unsigned& hi, unsigned& lo) {
    __nv_bfloat16 hx = __float2bfloat16(x), hy = __float2bfloat16(y);
    float rx = x - __bfloat162float(hx);
    float ry = y - __bfloat162float(hy);
    __nv_bfloat162 H(hx, hy);
    __nv_bfloat162 L(__float2bfloat16(rx), __float2bfloat16(ry));
    hi = *reinterpret_cast<unsigned*>(&H);
    lo = *reinterpret_cast<unsigned*>(&L);
}

// ---------------------------------------------------------------------------
// float -> (bf16 hi, bf16 lo) split
// ---------------------------------------------------------------------------
__global__ __launch_bounds__(256) void split_hi_lo(
    const float* __restrict__ src, __nv_bfloat16* __restrict__ hi,
    __nv_bfloat16* __restrict__ lo, int n4)
{
    int i = blockIdx.x * 256 + threadIdx.x;
    if (i >= n4) return;
    float4 v = reinterpret_cast<const float4*>(src)[i];
    unsigned h01, l01, h23, l23;
    split_pair(v.x, v.y, h01, l01);
    split_pair(v.z, v.w, h23, l23);
    reinterpret_cast<unsigned*>(hi)[2 * i]     = h01;
    reinterpret_cast<unsigned*>(hi)[2 * i + 1] = h23;
    reinterpret_cast<unsigned*>(lo)[2 * i]     = l01;
    reinterpret_cast<unsigned*>(lo)[2 * i + 1] = l23;
}

// ---------------------------------------------------------------------------
// HMMA GEMM (NT): C[m,n] = sum_k A[m,k]*B[n,k], hi/lo 3-pass fused.
// 128x128 tile, BK=64 stage holds {Ahi,Alo,Bhi,Blo}; 3 passes per stage.
// 3-stage cp.async pipeline (192KB smem, 1 CTA/SM), one sync per stage.
// MODE 0: proj epilogue (bias, fp32 C).
// MODE 1: fused RMSNorm+RoPE+split epilogue (register-lean, smem-streaming).
// ---------------------------------------------------------------------------
#define GS_STAGE 65536
#define GEMM_SMEM (3 * GS_STAGE)     // 196608
#define NSTAGES 16                   // K=1024 / 64

template <int MODE>
__global__ __launch_bounds__(256, 1) void gemm_hmma(
    const __nv_bfloat16* __restrict__ Ahi, const __nv_bfloat16* __restrict__ Alo,
    const __nv_bfloat16* __restrict__ Bhi, const __nv_bfloat16* __restrict__ Blo,
    const float* __restrict__ bias, float* __restrict__ C, int N,
    const float* __restrict__ cosb, const float* __restrict__ sinb,
    const float* __restrict__ qw, const float* __restrict__ kw,
    __nv_bfloat16* __restrict__ Qh, __nv_bfloat16* __restrict__ Ql,
    __nv_bfloat16* __restrict__ Kh, __nv_bfloat16* __restrict__ Kl,
    __nv_bfloat16* __restrict__ Vh, __nv_bfloat16* __restrict__ Vl)
{
    extern __shared__ __align__(128) char smc[];
    const unsigned sb = smem_u32(smc);
    const int t = threadIdx.x, lane = t & 31, wid = t >> 5;
    const int wm = wid & 1, wn = wid >> 1;
    const int m0 = blockIdx.y * 128, n0 = blockIdx.x * 128;
    const int K = 1024;
    const int grp = lane >> 3, ri = lane & 7;

    float acc[4][4][4];
#pragma unroll
    for (int a = 0; a < 4; a++)
#pragma unroll
        for (int b = 0; b < 4; b++)
#pragma unroll
            for (int c = 0; c < 4; c++) acc[a][b][c] = 0.f;

    const __nv_bfloat16* srcs[4] = {
        Ahi + (size_t)m0 * K, Alo + (size_t)m0 * K,
        Bhi + (size_t)n0 * K, Blo + (size_t)n0 * K };

    // stage loader: 64KB = 4 mats x 128 rows x 8 chunks; 16 chunks/thread
    auto issue = [&](int s, int buf) {
        const int k0 = s * 64;
        const unsigned stb = sb + buf * GS_STAGE;
#pragma unroll
        for (int m = 0; m < 4; m++) {
            const unsigned mb = stb + m * 16384;
            const __nv_bfloat16* g = srcs[m] + k0;
#pragma unroll
            for (int i = 0; i < 4; i++) {
                int idx = i * 256 + t;
                int r = idx >> 3, ch = idx & 7;
                CP16(mb + swz(r, ch), g + (size_t)r * K + ch * 8);
            }
        }
    };

    issue(0, 0); CP_COMMIT();
    issue(1, 1); CP_COMMIT();

    for (int it = 0; it < NSTAGES; it++) {
        if (it == NSTAGES - 1) { CP_WAIT0(); } else { CP_WAIT1(); }
        __syncthreads();
        if (it + 2 < NSTAGES) {
            issue(it + 2, (it + 2) % 3);
            CP_COMMIT();
        }
        const unsigned stb = sb + (it % 3) * GS_STAGE;
        const unsigned abh = stb, abl = stb + 16384;
        const unsigned bbh = stb + 32768, bbl = stb + 49152;
#pragma unroll
        for (int k4 = 0; k4 < 4; k4++) {
            unsigned ah[4][4], al[4][4], bh[2][4], bl[2][4];
#pragma unroll
            for (int mt = 0; mt < 4; mt++) {
                int r = wm * 64 + mt * 16 + (grp & 1) * 8 + ri;
                int ch = k4 * 2 + (grp >> 1);
                ldsm4(ah[mt], abh + swz(r, ch));
                ldsm4(al[mt], abl + swz(r, ch));
            }
#pragma unroll
            for (int np = 0; np < 2; np++) {
                int r = wn * 32 + np * 16 + ((grp >> 1) & 1) * 8 + ri;
                int ch = k4 * 2 + (grp & 1);
                ldsm4(bh[np], bbh + swz(r, ch));
                ldsm4(bl[np], bbl + swz(r, ch));
            }
            // pass 1: Ahi * Bhi
#pragma unroll
            for (int mt = 0; mt < 4; mt++)
#pragma unroll
                for (int np = 0; np < 2; np++) {
                    mma16816(acc[mt][2 * np],     ah[mt], bh[np][0], bh[np][1]);
                    mma16816(acc[mt][2 * np + 1], ah[mt], bh[np][2], bh[np][3]);
                }
            // pass 2: Ahi * Blo
#pragma unroll
            for (int mt = 0; mt < 4; mt++)
#pragma unroll
                for (int np = 0; np < 2; np++) {
                    mma16816(acc[mt][2 * np],     ah[mt], bl[np][0], bl[np][1]);
                    mma16816(acc[mt][2 * np + 1], ah[mt], bl[np][2], bl[np][3]);
                }
            // pass 3: Alo * Bhi
#pragma unroll
            for (int mt = 0; mt < 4; mt++)
#pragma unroll
                for (int np = 0; np < 2; np++) {
                    mma16816(acc[mt][2 * np],     al[mt], bh[np][0], bh[np][1]);
                    mma16816(acc[mt][2 * np + 1], al[mt], bh[np][2], bh[np][3]);
                }
        }
    }

    if (MODE == 0) {
        // ---- proj epilogue: bias + fp32 store ----
#pragma unroll
        for (int mt = 0; mt < 4; mt++)
#pragma unroll
            for (int nt = 0; nt < 4; nt++) {
                int col = n0 + wn * 32 + nt * 8 + (lane & 3) * 2;
                int r0 = m0 + wm * 64 + mt * 16 + (lane >> 2);
                float bx = bias[col], by = bias[col + 1];
                float2 v0 = make_float2(acc[mt][nt][0] + bx, acc[mt][nt][1] + by);
                float2 v1 = make_float2(acc[mt][nt][2] + bx, acc[mt][nt][3] + by);
                *reinterpret_cast<float2*>(&C[(size_t)r0 * N + col]) = v0;
                *reinterpret_cast<float2*>(&C[(size_t)(r0 + 8) * N + col]) = v1;
            }
    } else {
        // ---- fused prep epilogue (register-lean, streams from smem) ----
        __syncthreads();                 // all MMAs done; smem reusable
        float* tile = reinterpret_cast<float*>(smc);
#pragma unroll
        for (int mt = 0; mt < 4; mt++)
#pragma unroll
            for (int nt = 0; nt < 4; nt++) {
                int col = wn * 32 + nt * 8 + (lane & 3) * 2;
                int r0 = wm * 64 + mt * 16 + (lane >> 2);
                tile[r0 * 129 + col]           = acc[mt][nt][0];
                tile[r0 * 129 + col + 1]       = acc[mt][nt][1];
                tile[(r0 + 8) * 129 + col]     = acc[mt][nt][2];
                tile[(r0 + 8) * 129 + col + 1] = acc[mt][nt][3];
            }
        __syncthreads();
        {
            const int row = t & 127;           // tile row
            const int hh = t >> 7;             // head half within tile
            const int m = m0 + row;
            const int bidx = m >> 11, n = m & 2047;
            const int sec = n0 >> 10;          // 0=q, 1=k, 2=v
            const int h = ((n0 & 1023) >> 6) + hh;
            const float* v = tile + row * 129 + hh * 64;
            const size_t dst = (((size_t)(bidx * NHEAD + h)) * NSEQ + n) * HD;
            __nv_bfloat16 *H, *L;
            if (sec == 0)      { H = Qh; L = Ql; }
            else if (sec == 1) { H = Kh; L = Kl; }
            else               { H = Vh; L = Vl; }

            if (sec == 2) {
                // V: straight split
#pragma unroll
                for (int d0 = 0; d0 < 64; d0 += 8) {
                    unsigned hv[4], lv[4];
#pragma unroll
                    for (int i = 0; i < 4; i++)
                        split_pair(v[d0 + 2 * i], v[d0 + 2 * i + 1], hv[i], lv[i]);
                    uint4 Hv; Hv.x = hv[0]; Hv.y = hv[1]; Hv.z = hv[2]; Hv.w = hv[3];
                    uint4 Lv; Lv.x = lv[0]; Lv.y = lv[1]; Lv.z = lv[2]; Lv.w = lv[3];
                    *reinterpret_cast<uint4*>(&H[dst + d0]) = Hv;
                    *reinterpret_cast<uint4*>(&L[dst + d0]) = Lv;
                }
            } else {
                // pass 1: sum of squares (single live accumulator)
                float ss = 0.f;
                for (int d = 0; d < 64; d++) { float x = v[d]; ss = fmaf(x, x, ss); }
                float inv = rsqrtf(ss * (1.f / 64.f) + 1e-6f);
                if (sec == 0) inv *= 0.125f;   // fold q pre-scale (rope is linear)
                const float* W = (sec == 0) ? qw : kw;
                const float* cb = cosb + (n << 6);
                const float* sbp = sinb + (n << 6);
                // pass 2: rope pairs (d, d+32), 8-wide blocks, split + store
#pragma unroll
                for (int d0 = 0; d0 < 32; d0 += 8) {
                    unsigned hv0[4], lv0[4], hv1[4], lv1[4];
#pragma unroll
                    for (int i = 0; i < 8; i += 2) {
                        int d = d0 + i;
                        float a0 = v[d] * inv * W[d];
                        float a1 = v[d + 1] * inv * W[d + 1];
                        float b0 = v[d + 32] * inv * W[d + 32];
                        float b1 = v[d + 33] * inv * W[d + 33];
                        float o00 = a0 * cb[d]      - b0 * sbp[d];
                        float o01 = a1 * cb[d + 1]  - b1 * sbp[d + 1];
                        float o10 = b0 * cb[d + 32] + a0 * sbp[d + 32];
                        float o11 = b1 * cb[d + 33] + a1 * sbp[d + 33];
                        split_pair(o00, o01, hv0[i / 2], lv0[i / 2]);
                        split_pair(o10, o11, hv1[i / 2], lv1[i / 2]);
                    }
                    uint4 Hv, Lv;
                    Hv.x = hv0[0]; Hv.y = hv0[1]; Hv.z = hv0[2]; Hv.w = hv0[3];
                    Lv.x = lv0[0]; Lv.y = lv0[1]; Lv.z = lv0[2]; Lv.w = lv0[3];
                    *reinterpret_cast<uint4*>(&H[dst + d0]) = Hv;
                    *reinterpret_cast<uint4*>(&L[dst + d0]) = Lv;
                    Hv.x = hv1[0]; Hv.y = hv1[1]; Hv.z = hv1[2]; Hv.w = hv1[3];
                    Lv.x = lv1[0]; Lv.y = lv1[1]; Lv.z = lv1[2]; Lv.w = lv1[3];
                    *reinterpret_cast<uint4*>(&H[dst + d0 + 32]) = Hv;
                    *reinterpret_cast<uint4*>(&L[dst + d0 + 32]) = Lv;
                }
            }
        }
    }
}

// ---------------------------------------------------------------------------
// Flash attention on HMMA. 256 threads (8 warps, m16 each -> 128 q rows).
// KV tiles of 64, cp.async double-buffered. NO online max: RMS-normed q,k
// with RoPE give |s| <= 32, exp/sums stay well inside fp32 range.
// SMEM: Qhi 16K | Qlo 16K | stage{Khi,Klo,Vhi,Vlo}x2 = 32K + 64K = 96K
// ---------------------------------------------------------------------------
#define FA_SMEM 98304

__global__ __launch_bounds__(256, 2) void flash_hmma(
    const __nv_bfloat16* __restrict__ Qh, const __nv_bfloat16* __restrict__ Ql,
    const __nv_bfloat16* __restrict__ Kh, const __nv_bfloat16* __restrict__ Kl,
    const __nv_bfloat16* __restrict__ Vh, const __nv_bfloat16* __restrict__ Vl,
    __nv_bfloat16* __restrict__ Ohi, __nv_bfloat16* __restrict__ Olo)
{
    extern __shared__ __align__(128) char smc[];
    const unsigned sb = smem_u32(smc);
    const int t = threadIdx.x, lane = t & 31, w = t >> 5;
    const int bh = blockIdx.x, qt = blockIdx.y;
    const int b = bh >> 4, h = bh & 15;
    const int grp = lane >> 3, ri = lane & 7;

    const size_t qoff = ((size_t)bh * NSEQ + qt * 128) * HD;
    const size_t kvoff = (size_t)bh * NSEQ * HD;

    const __nv_bfloat16* mats[4] = {Kh, Kl, Vh, Vl};

    auto issue = [&](int j, int s) {
        const unsigned stb = sb + 32768 + s * 32768;
#pragma unroll
        for (int m = 0; m < 4; m++) {
            const __nv_bfloat16* g = mats[m] + kvoff + (size_t)(j * 64) * HD;
            const unsigned mb = stb + m * 8192;
#pragma unroll
            for (int i = 0; i < 2; i++) {
                int idx = i * 256 + t;
                int r = idx >> 3, ch = idx & 7;
                CP16(mb + swz(r, ch), g + (size_t)r * HD + ch * 8);
            }
        }
    };

    issue(0, 0);
    CP_COMMIT();

    // Q tiles -> smem (swizzled)
    {
#pragma unroll
        for (int i = 0; i < 4; i++) {
            int idx = i * 256 + t;
            int r = idx >> 3, ch = idx & 7;
            *reinterpret_cast<uint4*>(smc + swz(r, ch)) =
                *reinterpret_cast<const uint4*>(Qh + qoff + (size_t)r * HD + ch * 8);
            *reinterpret_cast<uint4*>(smc + 16384 + swz(r, ch)) =
                *reinterpret_cast<const uint4*>(Ql + qoff + (size_t)r * HD + ch * 8);
        }
    }
    __syncthreads();

    unsigned qh[4][4], ql[4][4];
#pragma unroll
    for (int kt = 0; kt < 4; kt++) {
        int r = w * 16 + (grp & 1) * 8 + ri;
        int ch = kt * 2 + (grp >> 1);
        ldsm4(qh[kt], sb + swz(r, ch));
        ldsm4(ql[kt], sb + 16384 + swz(r, ch));
    }

    float o[8][4];
#pragma unroll
    for (int d = 0; d < 8; d++)
#pragma unroll
        for (int c = 0; c < 4; c++) o[d][c] = 0.f;
    float l0r = 0.f, l1r = 0.f;

    for (int j = 0; j < NSEQ / 64; j++) {
        if (j + 1 < NSEQ / 64) {
            issue(j + 1, (j + 1) & 1);
            CP_COMMIT();
            CP_WAIT1();
        } else {
            CP_WAIT0();
        }
        __syncthreads();
        const unsigned stb = sb + 32768 + (j & 1) * 32768;

        // ---- S = Q K^T (3-pass hi/lo) ----
        float s[8][4];
#pragma unroll
        for (int nt = 0; nt < 8; nt++)
#pragma unroll
            for (int c = 0; c < 4; c++) s[nt][c] = 0.f;

#pragma unroll
        for (int kt = 0; kt < 4; kt++) {
#pragma unroll
            for (int np = 0; np < 4; np++) {
                int r = np * 16 + ((grp >> 1) & 1) * 8 + ri;
                int ch = kt * 2 + (grp & 1);
                unsigned kh[4], kl[4];
                ldsm4(kh, stb + swz(r, ch));
                ldsm4(kl, stb + 8192 + swz(r, ch));
                mma16816(s[2 * np],     qh[kt], kh[0], kh[1]);
                mma16816(s[2 * np + 1], qh[kt], kh[2], kh[3]);
                mma16816(s[2 * np],     qh[kt], kl[0], kl[1]);
                mma16816(s[2 * np + 1], qh[kt], kl[2], kl[3]);
                mma16816(s[2 * np],     ql[kt], kh[0], kh[1]);
                mma16816(s[2 * np + 1], ql[kt], kh[2], kh[3]);
            }
        }

        // ---- softmax numerators (no max subtraction needed) ----
        float ps0 = 0.f, ps1 = 0.f;
#pragma unroll
        for (int nt = 0; nt < 8; nt++) {
            s[nt][0] = fast_exp(s[nt][0]);
            s[nt][1] = fast_exp(s[nt][1]);
            s[nt][2] = fast_exp(s[nt][2]);
            s[nt][3] = fast_exp(s[nt][3]);
            ps0 += s[nt][0] + s[nt][1];
            ps1 += s[nt][2] + s[nt][3];
        }
        ps0 += __shfl_xor_sync(0xffffffffu, ps0, 1);
        ps0 += __shfl_xor_sync(0xffffffffu, ps0, 2);
        ps1 += __shfl_xor_sync(0xffffffffu, ps1, 1);
        ps1 += __shfl_xor_sync(0xffffffffu, ps1, 2);
        l0r += ps0;
        l1r += ps1;

        // ---- O += P V (3-pass hi/lo) ----
#pragma unroll
        for (int ct = 0; ct < 4; ct++) {
            unsigned ph[4], pl[4];
            split_pair(s[2 * ct][0],     s[2 * ct][1],     ph[0], pl[0]);
            split_pair(s[2 * ct][2],     s[2 * ct][3],     ph[1], pl[1]);
            split_pair(s[2 * ct + 1][0], s[2 * ct + 1][1], ph[2], pl[2]);
            split_pair(s[2 * ct + 1][2], s[2 * ct + 1][3], ph[3], pl[3]);
#pragma unroll
            for (int dp = 0; dp < 4; dp++) {
                int r = ct * 16 + (lane & 15);
                int ch = dp * 2 + (lane >> 4);
                unsigned vh[4], vl[4];
                ldsm4t(vh, stb + 16384 + swz(r, ch));
                ldsm4t(vl, stb + 24576 + swz(r, ch));
                mma16816(o[2 * dp],     ph, vh[0], vh[1]);
                mma16816(o[2 * dp + 1], ph, vh[2], vh[3]);
                mma16816(o[2 * dp],     ph, vl[0], vl[1]);
                mma16816(o[2 * dp + 1], ph, vl[2], vl[3]);
                mma16816(o[2 * dp],     pl, vh[0], vh[1]);
                mma16816(o[2 * dp + 1], pl, vh[2], vh[3]);
            }
        }
        __syncthreads();
    }

    // ---- epilogue: O/l -> hi/lo bf16 att in [B,N,C] layout ----
    const float inv0 = 1.0f / l0r, inv1 = 1.0f / l1r;
#pragma unroll
    for (int dt = 0; dt < 8; dt++) {
        int col = h * 64 + dt * 8 + (lane & 3) * 2;
        int r0 = qt * 128 + w * 16 + (lane >> 2);
        size_t i0 = ((size_t)b * NSEQ + r0) * CDIM + col;
        size_t i1 = ((size_t)b * NSEQ + r0 + 8) * CDIM + col;
        unsigned h0, l0, h1, l1;
        split_pair(o[dt][0] * inv0, o[dt][1] * inv0, h0, l0);
        split_pair(o[dt][2] * inv1, o[dt][3] * inv1, h1, l1);
        *reinterpret_cast<unsigned*>(&Ohi[i0]) = h0;
        *reinterpret_cast<unsigned*>(&Olo[i0]) = l0;
        *reinterpret_cast<unsigned*>(&Ohi[i1]) = h1;
        *reinterpret_cast<unsigned*>(&Olo[i1]) = l1;
    }
}

// ---------------------------------------------------------------------------
extern "C" void kernel_launch(void* const* d_in, const int* in_sizes, int n_in,
                              void* d_out, int out_size)
{
    const float* x      = (const float*)d_in[0];
    const float* cosb   = (const float*)d_in[1];
    const float* sinb   = (const float*)d_in[2];
    const float* w_qkv  = (const float*)d_in[3];
    const float* w_proj = (const float*)d_in[4];
    const float* b_proj = (const float*)d_in[5];
    const float* qw     = (const float*)d_in[6];
    const float* kw     = (const float*)d_in[7];
    float* out = (float*)d_out;

    __nv_bfloat16 *ahi, *alo, *wqh, *wql, *wph, *wpl;
    __nv_bfloat16 *qhi, *qlo, *khi, *klo, *vhi, *vlo;
    cudaGetSymbolAddress((void**)&ahi, g_ahi);
    cudaGetSymbolAddress((void**)&alo, g_alo);
    cudaGetSymbolAddress((void**)&wqh, g_wqkvhi);
    cudaGetSymbolAddress((void**)&wql, g_wqkvlo);
    cudaGetSymbolAddress((void**)&wph, g_wprojhi);
    cudaGetSymbolAddress((void**)&wpl, g_wprojlo);
    cudaGetSymbolAddress((void**)&qhi, g_qhi);
    cudaGetSymbolAddress((void**)&qlo, g_qlo);
    cudaGetSymbolAddress((void**)&khi, g_khi);
    cudaGetSymbolAddress((void**)&klo, g_klo);
    cudaGetSymbolAddress((void**)&vhi, g_vhi);
    cudaGetSymbolAddress((void**)&vlo, g_vlo);

    cudaFuncSetAttribute(gemm_hmma<0>,
                         cudaFuncAttributeMaxDynamicSharedMemorySize, GEMM_SMEM);
    cudaFuncSetAttribute(gemm_hmma<1>,
                         cudaFuncAttributeMaxDynamicSharedMemorySize, GEMM_SMEM);
    cudaFuncSetAttribute(flash_hmma,
                         cudaFuncAttributeMaxDynamicSharedMemorySize, FA_SMEM);

    // 0) hi/lo splits of x and both weights
    split_hi_lo<<<MROWS * CDIM / 4 / 256, 256>>>(x, ahi, alo, MROWS * CDIM / 4);
    split_hi_lo<<<QKVDIM * CDIM / 4 / 256, 256>>>(w_qkv, wqh, wql, QKVDIM * CDIM / 4);
    split_hi_lo<<<CDIM * CDIM / 4 / 256, 256>>>(w_proj, wph, wpl, CDIM * CDIM / 4);

    // 1) qkv = x @ w_qkv^T fused with rmsnorm+rope+split -> Q/K/V hi/lo
    gemm_hmma<1><<<dim3(QKVDIM / 128, MROWS / 128), 256, GEMM_SMEM>>>(
        ahi, alo, wqh, wql, nullptr, nullptr, QKVDIM,
        cosb, sinb, qw, kw, qhi, qlo, khi, klo, vhi, vlo);

    // 2) flash attention -> att hi/lo (into g_ahi/g_alo)
    flash_hmma<<<dim3(BHTOT, NSEQ / 128), 256, FA_SMEM>>>(
        qhi, qlo, khi, klo, vhi, vlo, ahi, alo);

    // 3) out = att @ w_proj^T + b
    gemm_hmma<0><<<dim3(CDIM / 128, MROWS / 128), 256, GEMM_SMEM>>>(
        ahi, alo, wph, wpl, b_proj, out, CDIM,
        nullptr, nullptr, nullptr, nullptr,
        nullptr, nullptr, nullptr, nullptr, nullptr, nullptr);
}

// round 9
// speedup vs baseline: 1.1323x; 1.1087x over previous
#include <cuda_runtime.h>
#include <cuda_bf16.h>
#include <math.h>

// Problem constants
#define B_SZ 4
#define NSEQ 2048
#define CDIM 1024
#define NHEAD 16
#define HD 64
#define MROWS 8192
#define QKVDIM 3072
#define BHTOT 64

// ---------------------------------------------------------------------------
// Static device scratch (allocation-free kernel_launch)
// ---------------------------------------------------------------------------
__device__ float g_qkv[MROWS * QKVDIM];
__device__ __nv_bfloat16 g_ahi[MROWS * CDIM];     // x splits, later att splits
__device__ __nv_bfloat16 g_alo[MROWS * CDIM];
__device__ __nv_bfloat16 g_wqkvhi[QKVDIM * CDIM];
__device__ __nv_bfloat16 g_wqkvlo[QKVDIM * CDIM];
__device__ __nv_bfloat16 g_wprojhi[CDIM * CDIM];
__device__ __nv_bfloat16 g_wprojlo[CDIM * CDIM];
__device__ __nv_bfloat16 g_qhi[BHTOT * NSEQ * HD];
__device__ __nv_bfloat16 g_qlo[BHTOT * NSEQ * HD];
__device__ __nv_bfloat16 g_khi[BHTOT * NSEQ * HD];
__device__ __nv_bfloat16 g_klo[BHTOT * NSEQ * HD];
__device__ __nv_bfloat16 g_vhi[BHTOT * NSEQ * HD];
__device__ __nv_bfloat16 g_vlo[BHTOT * NSEQ * HD];

// ---------------------------------------------------------------------------
// Helpers
// ---------------------------------------------------------------------------
__device__ __forceinline__ unsigned smem_u32(const void* p) {
    unsigned a;
    asm("{ .reg .u64 t; cvta.to.shared.u64 t, %1; cvt.u32.u64 %0, t; }"
        : "=r"(a) : "l"(p));
    return a;
}

__device__ __forceinline__ void ldsm4(unsigned* r, unsigned a) {
    asm volatile("ldmatrix.sync.aligned.m8n8.x4.shared.b16 {%0,%1,%2,%3}, [%4];"
        : "=r"(r[0]), "=r"(r[1]), "=r"(r[2]), "=r"(r[3]) : "r"(a));
}
__device__ __forceinline__ void ldsm4t(unsigned* r, unsigned a) {
    asm volatile("ldmatrix.sync.aligned.m8n8.x4.trans.shared.b16 {%0,%1,%2,%3}, [%4];"
        : "=r"(r[0]), "=r"(r[1]), "=r"(r[2]), "=r"(r[3]) : "r"(a));
}
__device__ __forceinline__ void mma16816(float* d, const unsigned* a,
                                         unsigned b0, unsigned b1) {
    asm volatile(
        "mma.sync.aligned.m16n8k16.row.col.f32.bf16.bf16.f32 "
        "{%0,%1,%2,%3}, {%4,%5,%6,%7}, {%8,%9}, {%0,%1,%2,%3};"
        : "+f"(d[0]), "+f"(d[1]), "+f"(d[2]), "+f"(d[3])
        : "r"(a[0]), "r"(a[1]), "r"(a[2]), "r"(a[3]), "r"(b0), "r"(b1));
}

#define CP16(sa, g) \
    asm volatile("cp.async.cg.shared.global [%0], [%1], 16;" :: "r"(sa), "l"(g))
#define CP_COMMIT() asm volatile("cp.async.commit_group;")
#define CP_WAIT1()  asm volatile("cp.async.wait_group 1;")
#define CP_WAIT0()  asm volatile("cp.async.wait_group 0;")

// chunk swizzle: 128B rows, 8 x 16B chunks
__device__ __forceinline__ unsigned swz(int row, int chunk) {
    return (unsigned)(row * 128 + ((chunk ^ (row & 7)) * 16));
}

// FMA-only exp (no MUFU, no CVT, no clamp — inputs bounded |x| <= 32).
__device__ __forceinline__ float fast_exp(float x) {
    float t = fmaf(x, 1.442695041f, 12582912.f);
    int ebits = __float_as_int(t) << 23;
    float fi = t - 12582912.f;
    float f = fmaf(x, 1.442695041f, -fi);
    float p = 1.3333558e-3f;
    p = fmaf(p, f, 9.6181291e-3f);
    p = fmaf(p, f, 5.5504109e-2f);
    p = fmaf(p, f, 2.4022651e-1f);
    p = fmaf(p, f, 6.9314718e-1f);
    p = fmaf(p, f, 1.0f);
    return __int_as_float(__float_as_int(p) + ebits);
}

__device__ __forceinline__ void split_pair(float x, float y,
                                           unsigned& hi, unsigned& lo) {
    __nv_bfloat16 hx = __float2bfloat16(x), hy = __float2bfloat16(y);
    float rx = x - __bfloat162float(hx);
    float ry = y - __bfloat162float(hy);
    __nv_bfloat162 H(hx, hy);
    __nv_bfloat162 L(__float2bfloat16(rx), __float2bfloat16(ry));
    hi = *reinterpret_cast<unsigned*>(&H);
    lo = *reinterpret_cast<unsigned*>(&L);
}

__device__ __forceinline__ void store_hl(__nv_bfloat16* H, __nv_bfloat16* L,
                                         size_t i, float v) {
    __nv_bfloat16 h = __float2bfloat16(v);
    H[i] = h;
    L[i] = __float2bfloat16(v - __bfloat162float(h));
}

// ---------------------------------------------------------------------------
// One merged split kernel: x, w_qkv, w_proj -> bf16 hi/lo
// ---------------------------------------------------------------------------
#define NX4 (MROWS * CDIM / 4)
#define NQ4 (QKVDIM * CDIM / 4)
#define NP4 (CDIM * CDIM / 4)

__global__ __launch_bounds__(256) void split_all(
    const float* __restrict__ x, const float* __restrict__ wq,
    const float* __restrict__ wp,
    __nv_bfloat16* __restrict__ xh, __nv_bfloat16* __restrict__ xl,
    __nv_bfloat16* __restrict__ wqh, __nv_bfloat16* __restrict__ wql,
    __nv_bfloat16* __restrict__ wph, __nv_bfloat16* __restrict__ wpl)
{
    int i = blockIdx.x * 256 + threadIdx.x;
    const float* src;
    __nv_bfloat16 *hi, *lo;
    if (i < NX4)            { src = x;  hi = xh;  lo = xl; }
    else if (i < NX4 + NQ4) { i -= NX4; src = wq; hi = wqh; lo = wql; }
    else                    { i -= NX4 + NQ4; src = wp; hi = wph; lo = wpl; }
    float4 v = reinterpret_cast<const float4*>(src)[i];
    unsigned h01, l01, h23, l23;
    split_pair(v.x, v.y, h01, l01);
    split_pair(v.z, v.w, h23, l23);
    reinterpret_cast<unsigned*>(hi)[2 * i]     = h01;
    reinterpret_cast<unsigned*>(hi)[2 * i + 1] = h23;
    reinterpret_cast<unsigned*>(lo)[2 * i]     = l01;
    reinterpret_cast<unsigned*>(lo)[2 * i + 1] = l23;
}

// ---------------------------------------------------------------------------
// HMMA GEMM (NT): C[m,n] = sum_k A[m,k]*B[n,k] (+bias), hi/lo 3-pass fused.
// 128x128 tile, BK=64 stage holds {Ahi,Alo,Bhi,Blo}; 3 passes per stage.
// 3-stage cp.async pipeline, one __syncthreads per stage. 256 threads.
// (Exact R4 configuration — measured 365us @ tensor 69.6%, regs 144.)
// ---------------------------------------------------------------------------
#define GS_STAGE 65536
#define GEMM_SMEM (3 * GS_STAGE)     // 196608
#define NSTAGES 16                   // K=1024 / 64

template <bool BIAS>
__global__ __launch_bounds__(256) void gemm_hmma(
    const __nv_bfloat16* __restrict__ Ahi, const __nv_bfloat16* __restrict__ Alo,
    const __nv_bfloat16* __restrict__ Bhi, const __nv_bfloat16* __restrict__ Blo,
    const float* __restrict__ bias, float* __restrict__ C, int N)
{
    extern __shared__ __align__(128) char smc[];
    const unsigned sb = smem_u32(smc);
    const int t = threadIdx.x, lane = t & 31, wid = t >> 5;
    const int wm = wid & 1, wn = wid >> 1;
    const int m0 = blockIdx.y * 128, n0 = blockIdx.x * 128;
    const int K = 1024;
    const int grp = lane >> 3, ri = lane & 7;

    float acc[4][4][4];
#pragma unroll
    for (int a = 0; a < 4; a++)
#pragma unroll
        for (int b = 0; b < 4; b++)
#pragma unroll
            for (int c = 0; c < 4; c++) acc[a][b][c] = 0.f;

    const __nv_bfloat16* srcs[4] = {
        Ahi + (size_t)m0 * K, Alo + (size_t)m0 * K,
        Bhi + (size_t)n0 * K, Blo + (size_t)n0 * K };

    // stage loader: 64KB = 4 mats x 128 rows x 8 chunks; 16 chunks/thread
    auto issue = [&](int s, int buf) {
        const int k0 = s * 64;
        const unsigned stb = sb + buf * GS_STAGE;
#pragma unroll
        for (int m = 0; m < 4; m++) {
            const unsigned mb = stb + m * 16384;
            const __nv_bfloat16* g = srcs[m] + k0;
#pragma unroll
            for (int i = 0; i < 4; i++) {
                int idx = i * 256 + t;
                int r = idx >> 3, ch = idx & 7;
                CP16(mb + swz(r, ch), g + (size_t)r * K + ch * 8);
            }
        }
    };

    issue(0, 0); CP_COMMIT();
    issue(1, 1); CP_COMMIT();

    for (int it = 0; it < NSTAGES; it++) {
        if (it == NSTAGES - 1) { CP_WAIT0(); } else { CP_WAIT1(); }
        __syncthreads();
        if (it + 2 < NSTAGES) {
            issue(it + 2, (it + 2) % 3);
            CP_COMMIT();
        }
        const unsigned stb = sb + (it % 3) * GS_STAGE;
        const unsigned abh = stb, abl = stb + 16384;
        const unsigned bbh = stb + 32768, bbl = stb + 49152;
#pragma unroll
        for (int k4 = 0; k4 < 4; k4++) {
            unsigned ah[4][4], al[4][4], bh[2][4], bl[2][4];
#pragma unroll
            for (int mt = 0; mt < 4; mt++) {
                int r = wm * 64 + mt * 16 + (grp & 1) * 8 + ri;
                int ch = k4 * 2 + (grp >> 1);
                ldsm4(ah[mt], abh + swz(r, ch));
                ldsm4(al[mt], abl + swz(r, ch));
            }
#pragma unroll
            for (int np = 0; np < 2; np++) {
                int r = wn * 32 + np * 16 + ((grp >> 1) & 1) * 8 + ri;
                int ch = k4 * 2 + (grp & 1);
                ldsm4(bh[np], bbh + swz(r, ch));
                ldsm4(bl[np], bbl + swz(r, ch));
            }
            // pass 1: Ahi * Bhi
#pragma unroll
            for (int mt = 0; mt < 4; mt++)
#pragma unroll
                for (int np = 0; np < 2; np++) {
                    mma16816(acc[mt][2 * np],     ah[mt], bh[np][0], bh[np][1]);
                    mma16816(acc[mt][2 * np + 1], ah[mt], bh[np][2], bh[np][3]);
                }
            // pass 2: Ahi * Blo
#pragma unroll
            for (int mt = 0; mt < 4; mt++)
#pragma unroll
                for (int np = 0; np < 2; np++) {
                    mma16816(acc[mt][2 * np],     ah[mt], bl[np][0], bl[np][1]);
                    mma16816(acc[mt][2 * np + 1], ah[mt], bl[np][2], bl[np][3]);
                }
            // pass 3: Alo * Bhi
#pragma unroll
            for (int mt = 0; mt < 4; mt++)
#pragma unroll
                for (int np = 0; np < 2; np++) {
                    mma16816(acc[mt][2 * np],     al[mt], bh[np][0], bh[np][1]);
                    mma16816(acc[mt][2 * np + 1], al[mt], bh[np][2], bh[np][3]);
                }
        }
    }

    // epilogue
#pragma unroll
    for (int mt = 0; mt < 4; mt++)
#pragma unroll
        for (int nt = 0; nt < 4; nt++) {
            int col = n0 + wn * 32 + nt * 8 + (lane & 3) * 2;
            int r0 = m0 + wm * 64 + mt * 16 + (lane >> 2);
            float bx = 0.f, by = 0.f;
            if (BIAS) { bx = bias[col]; by = bias[col + 1]; }
            float2 v0 = make_float2(acc[mt][nt][0] + bx, acc[mt][nt][1] + by);
            float2 v1 = make_float2(acc[mt][nt][2] + bx, acc[mt][nt][3] + by);
            *reinterpret_cast<float2*>(&C[(size_t)r0 * N + col]) = v0;
            *reinterpret_cast<float2*>(&C[(size_t)(r0 + 8) * N + col]) = v1;
        }
}

// ---------------------------------------------------------------------------
// Prep: split qkv, RMSNorm(q,k), RoPE(q,k); emit bf16 hi/lo Q (pre-scaled by
// 1/8), K, V in [b*H+h][n][64] layout. Warp per (b,n,h).
// ---------------------------------------------------------------------------
__global__ __launch_bounds__(256) void prep_kernel(
    const float* __restrict__ qkv,
    const float* __restrict__ cosb, const float* __restrict__ sinb,
    const float* __restrict__ qw, const float* __restrict__ kw,
    __nv_bfloat16* __restrict__ Qh, __nv_bfloat16* __restrict__ Ql,
    __nv_bfloat16* __restrict__ Kh, __nv_bfloat16* __restrict__ Kl,
    __nv_bfloat16* __restrict__ Vh, __nv_bfloat16* __restrict__ Vl)
{
    const int bn = blockIdx.x;
    const int h = (blockIdx.y << 3) | (threadIdx.x >> 5);
    const int l = threadIdx.x & 31;
    const int b = bn >> 11;
    const int n = bn & 2047;

    const float* base = qkv + (size_t)bn * QKVDIM + h * HD;
    float q1 = base[l],            q2 = base[l + 32];
    float k1 = base[CDIM + l],     k2 = base[CDIM + l + 32];
    float v1 = base[2 * CDIM + l], v2 = base[2 * CDIM + l + 32];

    float sq = q1 * q1 + q2 * q2;
    float sk = k1 * k1 + k2 * k2;
#pragma unroll
    for (int o = 16; o > 0; o >>= 1) {
        sq += __shfl_xor_sync(0xffffffffu, sq, o);
        sk += __shfl_xor_sync(0xffffffffu, sk, o);
    }
    float rq = rsqrtf(sq * (1.f / 64.f) + 1e-6f);
    float rk = rsqrtf(sk * (1.f / 64.f) + 1e-6f);
    q1 *= rq * qw[l]; q2 *= rq * qw[l + 32];
    k1 *= rk * kw[l]; k2 *= rk * kw[l + 32];

    float c1 = cosb[n * HD + l], c2 = cosb[n * HD + l + 32];
    float s1 = sinb[n * HD + l], s2 = sinb[n * HD + l + 32];

    size_t o = (((size_t)(b * NHEAD + h)) * NSEQ + n) * HD;
    store_hl(Qh, Ql, o + l,      (q1 * c1 - q2 * s1) * 0.125f);
    store_hl(Qh, Ql, o + l + 32, (q2 * c2 + q1 * s2) * 0.125f);
    store_hl(Kh, Kl, o + l,      k1 * c1 - k2 * s1);
    store_hl(Kh, Kl, o + l + 32, k2 * c2 + k1 * s2);
    store_hl(Vh, Vl, o + l,      v1);
    store_hl(Vh, Vl, o + l + 32, v2);
}

// ---------------------------------------------------------------------------
// Flash attention on HMMA. 256 threads (8 warps, m16 each -> 128 q rows).
// KV tiles of 64, cp.async double-buffered, ONE barrier per KV iteration
// (wait -> sync -> issue ordering makes the trailing barrier unnecessary).
// NO online max: RMS-normed q,k with RoPE give |s| <= 32.
// SMEM: Qhi 16K | Qlo 16K | stage{Khi,Klo,Vhi,Vlo}x2 = 32K + 64K = 96K
// ---------------------------------------------------------------------------
#define FA_SMEM 98304

__global__ __launch_bounds__(256, 2) void flash_hmma(
    const __nv_bfloat16* __restrict__ Qh, const __nv_bfloat16* __restrict__ Ql,
    const __nv_bfloat16* __restrict__ Kh, const __nv_bfloat16* __restrict__ Kl,
    const __nv_bfloat16* __restrict__ Vh, const __nv_bfloat16* __restrict__ Vl,
    __nv_bfloat16* __restrict__ Ohi, __nv_bfloat16* __restrict__ Olo)
{
    extern __shared__ __align__(128) char smc[];
    const unsigned sb = smem_u32(smc);
    const int t = threadIdx.x, lane = t & 31, w = t >> 5;
    const int bh = blockIdx.x, qt = blockIdx.y;
    const int b = bh >> 4, h = bh & 15;
    const int grp = lane >> 3, ri = lane & 7;

    const size_t qoff = ((size_t)bh * NSEQ + qt * 128) * HD;
    const size_t kvoff = (size_t)bh * NSEQ * HD;

    const __nv_bfloat16* mats[4] = {Kh, Kl, Vh, Vl};

    auto issue = [&](int j, int s) {
        const unsigned stb = sb + 32768 + s * 32768;
#pragma unroll
        for (int m = 0; m < 4; m++) {
            const __nv_bfloat16* g = mats[m] + kvoff + (size_t)(j * 64) * HD;
            const unsigned mb = stb + m * 8192;
#pragma unroll
            for (int i = 0; i < 2; i++) {
                int idx = i * 256 + t;
                int r = idx >> 3, ch = idx & 7;
                CP16(mb + swz(r, ch), g + (size_t)r * HD + ch * 8);
            }
        }
    };

    issue(0, 0);
    CP_COMMIT();

    // Q tiles -> smem (swizzled)
    {
#pragma unroll
        for (int i = 0; i < 4; i++) {
            int idx = i * 256 + t;
            int r = idx >> 3, ch = idx & 7;
            *reinterpret_cast<uint4*>(smc + swz(r, ch)) =
                *reinterpret_cast<const uint4*>(Qh + qoff + (size_t)r * HD + ch * 8);
            *reinterpret_cast<uint4*>(smc + 16384 + swz(r, ch)) =
                *reinterpret_cast<const uint4*>(Ql + qoff + (size_t)r * HD + ch * 8);
        }
    }
    __syncthreads();

    unsigned qh[4][4], ql[4][4];
#pragma unroll
    for (int kt = 0; kt < 4; kt++) {
        int r = w * 16 + (grp & 1) * 8 + ri;
        int ch = kt * 2 + (grp >> 1);
        ldsm4(qh[kt], sb + swz(r, ch));
        ldsm4(ql[kt], sb + 16384 + swz(r, ch));
    }

    float o[8][4];
#pragma unroll
    for (int d = 0; d < 8; d++)
#pragma unroll
        for (int c = 0; c < 4; c++) o[d][c] = 0.f;
    float l0r = 0.f, l1r = 0.f;

    for (int j = 0; j < NSEQ / 64; j++) {
        CP_WAIT0();
        __syncthreads();
        if (j + 1 < NSEQ / 64) {
            issue(j + 1, (j + 1) & 1);
            CP_COMMIT();
        }
        const unsigned stb = sb + 32768 + (j & 1) * 32768;

        // ---- S = Q K^T (3-pass hi/lo) ----
        float s[8][4];
#pragma unroll
        for (int nt = 0; nt < 8; nt++)
#pragma unroll
            for (int c = 0; c < 4; c++) s[nt][c] = 0.f;

#pragma unroll
        for (int kt = 0; kt < 4; kt++) {
#pragma unroll
            for (int np = 0; np < 4; np++) {
                int r = np * 16 + ((grp >> 1) & 1) * 8 + ri;
                int ch = kt * 2 + (grp & 1);
                unsigned kh[4], kl[4];
                ldsm4(kh, stb + swz(r, ch));
                ldsm4(kl, stb + 8192 + swz(r, ch));
                mma16816(s[2 * np],     qh[kt], kh[0], kh[1]);
                mma16816(s[2 * np + 1], qh[kt], kh[2], kh[3]);
                mma16816(s[2 * np],     qh[kt], kl[0], kl[1]);
                mma16816(s[2 * np + 1], qh[kt], kl[2], kl[3]);
                mma16816(s[2 * np],     ql[kt], kh[0], kh[1]);
                mma16816(s[2 * np + 1], ql[kt], kh[2], kh[3]);
            }
        }

        // ---- softmax numerators (no max subtraction needed) ----
        float ps0 = 0.f, ps1 = 0.f;
#pragma unroll
        for (int nt = 0; nt < 8; nt++) {
            s[nt][0] = fast_exp(s[nt][0]);
            s[nt][1] = fast_exp(s[nt][1]);
            s[nt][2] = fast_exp(s[nt][2]);
            s[nt][3] = fast_exp(s[nt][3]);
            ps0 += s[nt][0] + s[nt][1];
            ps1 += s[nt][2] + s[nt][3];
        }
        ps0 += __shfl_xor_sync(0xffffffffu, ps0, 1);
        ps0 += __shfl_xor_sync(0xffffffffu, ps0, 2);
        ps1 += __shfl_xor_sync(0xffffffffu, ps1, 1);
        ps1 += __shfl_xor_sync(0xffffffffu, ps1, 2);
        l0r += ps0;
        l1r += ps1;

        // ---- O += P V (3-pass hi/lo) ----
#pragma unroll
        for (int ct = 0; ct < 4; ct++) {
            unsigned ph[4], pl[4];
            split_pair(s[2 * ct][0],     s[2 * ct][1],     ph[0], pl[0]);
            split_pair(s[2 * ct][2],     s[2 * ct][3],     ph[1], pl[1]);
            split_pair(s[2 * ct + 1][0], s[2 * ct + 1][1], ph[2], pl[2]);
            split_pair(s[2 * ct + 1][2], s[2 * ct + 1][3], ph[3], pl[3]);
#pragma unroll
            for (int dp = 0; dp < 4; dp++) {
                int r = ct * 16 + (lane & 15);
                int ch = dp * 2 + (lane >> 4);
                unsigned vh[4], vl[4];
                ldsm4t(vh, stb + 16384 + swz(r, ch));
                ldsm4t(vl, stb + 24576 + swz(r, ch));
                mma16816(o[2 * dp],     ph, vh[0], vh[1]);
                mma16816(o[2 * dp + 1], ph, vh[2], vh[3]);
                mma16816(o[2 * dp],     ph, vl[0], vl[1]);
                mma16816(o[2 * dp + 1], ph, vl[2], vl[3]);
                mma16816(o[2 * dp],     pl, vh[0], vh[1]);
                mma16816(o[2 * dp + 1], pl, vh[2], vh[3]);
            }
        }
    }

    // ---- epilogue: O/l -> hi/lo bf16 att in [B,N,C] layout ----
    const float inv0 = 1.0f / l0r, inv1 = 1.0f / l1r;
#pragma unroll
    for (int dt = 0; dt < 8; dt++) {
        int col = h * 64 + dt * 8 + (lane & 3) * 2;
        int r0 = qt * 128 + w * 16 + (lane >> 2);
        size_t i0 = ((size_t)b * NSEQ + r0) * CDIM + col;
        size_t i1 = ((size_t)b * NSEQ + r0 + 8) * CDIM + col;
        unsigned h0, l0, h1, l1;
        split_pair(o[dt][0] * inv0, o[dt][1] * inv0, h0, l0);
        split_pair(o[dt][2] * inv1, o[dt][3] * inv1, h1, l1);
        *reinterpret_cast<unsigned*>(&Ohi[i0]) = h0;
        *reinterpret_cast<unsigned*>(&Olo[i0]) = l0;
        *reinterpret_cast<unsigned*>(&Ohi[i1]) = h1;
        *reinterpret_cast<unsigned*>(&Olo[i1]) = l1;
    }
}

// ---------------------------------------------------------------------------
extern "C" void kernel_launch(void* const* d_in, const int* in_sizes, int n_in,
                              void* d_out, int out_size)
{
    const float* x      = (const float*)d_in[0];
    const float* cosb   = (const float*)d_in[1];
    const float* sinb   = (const float*)d_in[2];
    const float* w_qkv  = (const float*)d_in[3];
    const float* w_proj = (const float*)d_in[4];
    const float* b_proj = (const float*)d_in[5];
    const float* qw     = (const float*)d_in[6];
    const float* kw     = (const float*)d_in[7];
    float* out = (float*)d_out;

    float* qkv;
    __nv_bfloat16 *ahi, *alo, *wqh, *wql, *wph, *wpl;
    __nv_bfloat16 *qhi, *qlo, *khi, *klo, *vhi, *vlo;
    cudaGetSymbolAddress((void**)&qkv, g_qkv);
    cudaGetSymbolAddress((void**)&ahi, g_ahi);
    cudaGetSymbolAddress((void**)&alo, g_alo);
    cudaGetSymbolAddress((void**)&wqh, g_wqkvhi);
    cudaGetSymbolAddress((void**)&wql, g_wqkvlo);
    cudaGetSymbolAddress((void**)&wph, g_wprojhi);
    cudaGetSymbolAddress((void**)&wpl, g_wprojlo);
    cudaGetSymbolAddress((void**)&qhi, g_qhi);
    cudaGetSymbolAddress((void**)&qlo, g_qlo);
    cudaGetSymbolAddress((void**)&khi, g_khi);
    cudaGetSymbolAddress((void**)&klo, g_klo);
    cudaGetSymbolAddress((void**)&vhi, g_vhi);
    cudaGetSymbolAddress((void**)&vlo, g_vlo);

    cudaFuncSetAttribute(gemm_hmma<false>,
                         cudaFuncAttributeMaxDynamicSharedMemorySize, GEMM_SMEM);
    cudaFuncSetAttribute(gemm_hmma<true>,
                         cudaFuncAttributeMaxDynamicSharedMemorySize, GEMM_SMEM);
    cudaFuncSetAttribute(flash_hmma,
                         cudaFuncAttributeMaxDynamicSharedMemorySize, FA_SMEM);

    // 0) hi/lo splits of x and both weights (one merged launch)
    split_all<<<(NX4 + NQ4 + NP4) / 256, 256>>>(
        x, w_qkv, w_proj, ahi, alo, wqh, wql, wph, wpl);

    // 1) qkv = x @ w_qkv^T
    gemm_hmma<false><<<dim3(QKVDIM / 128, MROWS / 128), 256, GEMM_SMEM>>>(
        ahi, alo, wqh, wql, nullptr, qkv, QKVDIM);

    // 2) rmsnorm + rope -> hi/lo Q(pre-scaled), K, V
    prep_kernel<<<dim3(MROWS, 2), 256>>>(qkv, cosb, sinb, qw, kw,
                                         qhi, qlo, khi, klo, vhi, vlo);

    // 3) flash attention -> att hi/lo (into g_ahi/g_alo)
    flash_hmma<<<dim3(BHTOT, NSEQ / 128), 256, FA_SMEM>>>(
        qhi, qlo, khi, klo, vhi, vlo, ahi, alo);

    // 4) out = att @ w_proj^T + b
    gemm_hmma<true><<<dim3(CDIM / 128, MROWS / 128), 256, GEMM_SMEM>>>(
        ahi, alo, wph, wpl, b_proj, out, CDIM);
}

// round 10
// speedup vs baseline: 1.3187x; 1.1646x over previous
#include <cuda_runtime.h>
#include <cuda_bf16.h>
#include <cuda_fp16.h>
#include <math.h>

// Problem constants
#define B_SZ 4
#define NSEQ 2048
#define CDIM 1024
#define NHEAD 16
#define HD 64
#define MROWS 8192
#define QKVDIM 3072
#define BHTOT 64

// ---------------------------------------------------------------------------
// Static device scratch (allocation-free kernel_launch)
// ---------------------------------------------------------------------------
__device__ float g_qkv[MROWS * QKVDIM];
__device__ __nv_bfloat16 g_ahi[MROWS * CDIM];     // x splits, later att splits
__device__ __nv_bfloat16 g_alo[MROWS * CDIM];
__device__ __nv_bfloat16 g_wqkvhi[QKVDIM * CDIM];
__device__ __nv_bfloat16 g_wqkvlo[QKVDIM * CDIM];
__device__ __nv_bfloat16 g_wprojhi[CDIM * CDIM];
__device__ __nv_bfloat16 g_wprojlo[CDIM * CDIM];
__device__ __half g_qh[BHTOT * NSEQ * HD];        // fp16 Q (pre-scaled 1/8)
__device__ __half g_kh[BHTOT * NSEQ * HD];        // fp16 K hi/lo
__device__ __half g_kl[BHTOT * NSEQ * HD];
__device__ __half g_vh[BHTOT * NSEQ * HD];        // fp16 V hi/lo
__device__ __half g_vl[BHTOT * NSEQ * HD];

// ---------------------------------------------------------------------------
// Helpers
// ---------------------------------------------------------------------------
__device__ __forceinline__ unsigned smem_u32(const void* p) {
    unsigned a;
    asm("{ .reg .u64 t; cvta.to.shared.u64 t, %1; cvt.u32.u64 %0, t; }"
        : "=r"(a) : "l"(p));
    return a;
}

__device__ __forceinline__ void ldsm4(unsigned* r, unsigned a) {
    asm volatile("ldmatrix.sync.aligned.m8n8.x4.shared.b16 {%0,%1,%2,%3}, [%4];"
        : "=r"(r[0]), "=r"(r[1]), "=r"(r[2]), "=r"(r[3]) : "r"(a));
}
__device__ __forceinline__ void ldsm4t(unsigned* r, unsigned a) {
    asm volatile("ldmatrix.sync.aligned.m8n8.x4.trans.shared.b16 {%0,%1,%2,%3}, [%4];"
        : "=r"(r[0]), "=r"(r[1]), "=r"(r[2]), "=r"(r[3]) : "r"(a));
}
// bf16 HMMA (GEMMs)
__device__ __forceinline__ void mma16816(float* d, const unsigned* a,
                                         unsigned b0, unsigned b1) {
    asm volatile(
        "mma.sync.aligned.m16n8k16.row.col.f32.bf16.bf16.f32 "
        "{%0,%1,%2,%3}, {%4,%5,%6,%7}, {%8,%9}, {%0,%1,%2,%3};"
        : "+f"(d[0]), "+f"(d[1]), "+f"(d[2]), "+f"(d[3])
        : "r"(a[0]), "r"(a[1]), "r"(a[2]), "r"(a[3]), "r"(b0), "r"(b1));
}
// fp16 HMMA (flash)
__device__ __forceinline__ void mma16816h(float* d, const unsigned* a,
                                          unsigned b0, unsigned b1) {
    asm volatile(
        "mma.sync.aligned.m16n8k16.row.col.f32.f16.f16.f32 "
        "{%0,%1,%2,%3}, {%4,%5,%6,%7}, {%8,%9}, {%0,%1,%2,%3};"
        : "+f"(d[0]), "+f"(d[1]), "+f"(d[2]), "+f"(d[3])
        : "r"(a[0]), "r"(a[1]), "r"(a[2]), "r"(a[3]), "r"(b0), "r"(b1));
}

#define CP16(sa, g) \
    asm volatile("cp.async.cg.shared.global [%0], [%1], 16;" :: "r"(sa), "l"(g))
#define CP_COMMIT() asm volatile("cp.async.commit_group;")
#define CP_WAIT1()  asm volatile("cp.async.wait_group 1;")
#define CP_WAIT0()  asm volatile("cp.async.wait_group 0;")

// chunk swizzle: 128B rows, 8 x 16B chunks
__device__ __forceinline__ unsigned swz(int row, int chunk) {
    return (unsigned)(row * 128 + ((chunk ^ (row & 7)) * 16));
}

// FMA-only exp (no MUFU, no CVT, no clamp — inputs bounded |x| <= 32).
__device__ __forceinline__ float fast_exp(float x) {
    float t = fmaf(x, 1.442695041f, 12582912.f);
    int ebits = __float_as_int(t) << 23;
    float fi = t - 12582912.f;
    float f = fmaf(x, 1.442695041f, -fi);
    float p = 1.3333558e-3f;
    p = fmaf(p, f, 9.6181291e-3f);
    p = fmaf(p, f, 5.5504109e-2f);
    p = fmaf(p, f, 2.4022651e-1f);
    p = fmaf(p, f, 6.9314718e-1f);
    p = fmaf(p, f, 1.0f);
    return __int_as_float(__float_as_int(p) + ebits);
}

__device__ __forceinline__ void split_pair(float x, float y,
                                           unsigned& hi, unsigned& lo) {
    __nv_bfloat16 hx = __float2bfloat16(x), hy = __float2bfloat16(y);
    float rx = x - __bfloat162float(hx);
    float ry = y - __bfloat162float(hy);
    __nv_bfloat162 H(hx, hy);
    __nv_bfloat162 L(__float2bfloat16(rx), __float2bfloat16(ry));
    hi = *reinterpret_cast<unsigned*>(&H);
    lo = *reinterpret_cast<unsigned*>(&L);
}

__device__ __forceinline__ unsigned pack_h2(float x, float y) {
    __half2 h = __floats2half2_rn(x, y);
    return *reinterpret_cast<unsigned*>(&h);
}

__device__ __forceinline__ void store_hl16(__half* H, __half* L,
                                           size_t i, float v) {
    __half h = __float2half_rn(v);
    H[i] = h;
    L[i] = __float2half_rn(v - __half2float(h));
}

// ---------------------------------------------------------------------------
// One merged split kernel: x, w_qkv, w_proj -> bf16 hi/lo
// ---------------------------------------------------------------------------
#define NX4 (MROWS * CDIM / 4)
#define NQ4 (QKVDIM * CDIM / 4)
#define NP4 (CDIM * CDIM / 4)

__global__ __launch_bounds__(256) void split_all(
    const float* __restrict__ x, const float* __restrict__ wq,
    const float* __restrict__ wp,
    __nv_bfloat16* __restrict__ xh, __nv_bfloat16* __restrict__ xl,
    __nv_bfloat16* __restrict__ wqh, __nv_bfloat16* __restrict__ wql,
    __nv_bfloat16* __restrict__ wph, __nv_bfloat16* __restrict__ wpl)
{
    int i = blockIdx.x * 256 + threadIdx.x;
    const float* src;
    __nv_bfloat16 *hi, *lo;
    if (i < NX4)            { src = x;  hi = xh;  lo = xl; }
    else if (i < NX4 + NQ4) { i -= NX4; src = wq; hi = wqh; lo = wql; }
    else                    { i -= NX4 + NQ4; src = wp; hi = wph; lo = wpl; }
    float4 v = reinterpret_cast<const float4*>(src)[i];
    unsigned h01, l01, h23, l23;
    split_pair(v.x, v.y, h01, l01);
    split_pair(v.z, v.w, h23, l23);
    reinterpret_cast<unsigned*>(hi)[2 * i]     = h01;
    reinterpret_cast<unsigned*>(hi)[2 * i + 1] = h23;
    reinterpret_cast<unsigned*>(lo)[2 * i]     = l01;
    reinterpret_cast<unsigned*>(lo)[2 * i + 1] = l23;
}

// ---------------------------------------------------------------------------
// HMMA GEMM (NT): C[m,n] = sum_k A[m,k]*B[n,k] (+bias), hi/lo 3-pass fused.
// 128x128 tile, BK=64 stage holds {Ahi,Alo,Bhi,Blo}; 3 passes per stage.
// 3-stage cp.async pipeline, one __syncthreads per stage. 256 threads.
// (Exact R4 configuration — measured 365us @ tensor 69.6%, regs 144.)
// ---------------------------------------------------------------------------
#define GS_STAGE 65536
#define GEMM_SMEM (3 * GS_STAGE)     // 196608
#define NSTAGES 16                   // K=1024 / 64

template <bool BIAS>
__global__ __launch_bounds__(256) void gemm_hmma(
    const __nv_bfloat16* __restrict__ Ahi, const __nv_bfloat16* __restrict__ Alo,
    const __nv_bfloat16* __restrict__ Bhi, const __nv_bfloat16* __restrict__ Blo,
    const float* __restrict__ bias, float* __restrict__ C, int N)
{
    extern __shared__ __align__(128) char smc[];
    const unsigned sb = smem_u32(smc);
    const int t = threadIdx.x, lane = t & 31, wid = t >> 5;
    const int wm = wid & 1, wn = wid >> 1;
    const int m0 = blockIdx.y * 128, n0 = blockIdx.x * 128;
    const int K = 1024;
    const int grp = lane >> 3, ri = lane & 7;

    float acc[4][4][4];
#pragma unroll
    for (int a = 0; a < 4; a++)
#pragma unroll
        for (int b = 0; b < 4; b++)
#pragma unroll
            for (int c = 0; c < 4; c++) acc[a][b][c] = 0.f;

    const __nv_bfloat16* srcs[4] = {
        Ahi + (size_t)m0 * K, Alo + (size_t)m0 * K,
        Bhi + (size_t)n0 * K, Blo + (size_t)n0 * K };

    // stage loader: 64KB = 4 mats x 128 rows x 8 chunks; 16 chunks/thread
    auto issue = [&](int s, int buf) {
        const int k0 = s * 64;
        const unsigned stb = sb + buf * GS_STAGE;
#pragma unroll
        for (int m = 0; m < 4; m++) {
            const unsigned mb = stb + m * 16384;
            const __nv_bfloat16* g = srcs[m] + k0;
#pragma unroll
            for (int i = 0; i < 4; i++) {
                int idx = i * 256 + t;
                int r = idx >> 3, ch = idx & 7;
                CP16(mb + swz(r, ch), g + (size_t)r * K + ch * 8);
            }
        }
    };

    issue(0, 0); CP_COMMIT();
    issue(1, 1); CP_COMMIT();

    for (int it = 0; it < NSTAGES; it++) {
        if (it == NSTAGES - 1) { CP_WAIT0(); } else { CP_WAIT1(); }
        __syncthreads();
        if (it + 2 < NSTAGES) {
            issue(it + 2, (it + 2) % 3);
            CP_COMMIT();
        }
        const unsigned stb = sb + (it % 3) * GS_STAGE;
        const unsigned abh = stb, abl = stb + 16384;
        const unsigned bbh = stb + 32768, bbl = stb + 49152;
#pragma unroll
        for (int k4 = 0; k4 < 4; k4++) {
            unsigned ah[4][4], al[4][4], bh[2][4], bl[2][4];
#pragma unroll
            for (int mt = 0; mt < 4; mt++) {
                int r = wm * 64 + mt * 16 + (grp & 1) * 8 + ri;
                int ch = k4 * 2 + (grp >> 1);
                ldsm4(ah[mt], abh + swz(r, ch));
                ldsm4(al[mt], abl + swz(r, ch));
            }
#pragma unroll
            for (int np = 0; np < 2; np++) {
                int r = wn * 32 + np * 16 + ((grp >> 1) & 1) * 8 + ri;
                int ch = k4 * 2 + (grp & 1);
                ldsm4(bh[np], bbh + swz(r, ch));
                ldsm4(bl[np], bbl + swz(r, ch));
            }
            // pass 1: Ahi * Bhi
#pragma unroll
            for (int mt = 0; mt < 4; mt++)
#pragma unroll
                for (int np = 0; np < 2; np++) {
                    mma16816(acc[mt][2 * np],     ah[mt], bh[np][0], bh[np][1]);
                    mma16816(acc[mt][2 * np + 1], ah[mt], bh[np][2], bh[np][3]);
                }
            // pass 2: Ahi * Blo
#pragma unroll
            for (int mt = 0; mt < 4; mt++)
#pragma unroll
                for (int np = 0; np < 2; np++) {
                    mma16816(acc[mt][2 * np],     ah[mt], bl[np][0], bl[np][1]);
                    mma16816(acc[mt][2 * np + 1], ah[mt], bl[np][2], bl[np][3]);
                }
            // pass 3: Alo * Bhi
#pragma unroll
            for (int mt = 0; mt < 4; mt++)
#pragma unroll
                for (int np = 0; np < 2; np++) {
                    mma16816(acc[mt][2 * np],     al[mt], bh[np][0], bh[np][1]);
                    mma16816(acc[mt][2 * np + 1], al[mt], bh[np][2], bh[np][3]);
                }
        }
    }

    // epilogue
#pragma unroll
    for (int mt = 0; mt < 4; mt++)
#pragma unroll
        for (int nt = 0; nt < 4; nt++) {
            int col = n0 + wn * 32 + nt * 8 + (lane & 3) * 2;
            int r0 = m0 + wm * 64 + mt * 16 + (lane >> 2);
            float bx = 0.f, by = 0.f;
            if (BIAS) { bx = bias[col]; by = bias[col + 1]; }
            float2 v0 = make_float2(acc[mt][nt][0] + bx, acc[mt][nt][1] + by);
            float2 v1 = make_float2(acc[mt][nt][2] + bx, acc[mt][nt][3] + by);
            *reinterpret_cast<float2*>(&C[(size_t)r0 * N + col]) = v0;
            *reinterpret_cast<float2*>(&C[(size_t)(r0 + 8) * N + col]) = v1;
        }
}

// ---------------------------------------------------------------------------
// Prep: split qkv, RMSNorm(q,k), RoPE(q,k); emit fp16 Q (pre-scaled 1/8),
// fp16 hi/lo K and V in [b*H+h][n][64] layout. Warp per (b,n,h).
// ---------------------------------------------------------------------------
__global__ __launch_bounds__(256) void prep_kernel(
    const float* __restrict__ qkv,
    const float* __restrict__ cosb, const float* __restrict__ sinb,
    const float* __restrict__ qw, const float* __restrict__ kw,
    __half* __restrict__ Qh,
    __half* __restrict__ Kh, __half* __restrict__ Kl,
    __half* __restrict__ Vh, __half* __restrict__ Vl)
{
    const int bn = blockIdx.x;
    const int h = (blockIdx.y << 3) | (threadIdx.x >> 5);
    const int l = threadIdx.x & 31;
    const int b = bn >> 11;
    const int n = bn & 2047;

    const float* base = qkv + (size_t)bn * QKVDIM + h * HD;
    float q1 = base[l],            q2 = base[l + 32];
    float k1 = base[CDIM + l],     k2 = base[CDIM + l + 32];
    float v1 = base[2 * CDIM + l], v2 = base[2 * CDIM + l + 32];

    float sq = q1 * q1 + q2 * q2;
    float sk = k1 * k1 + k2 * k2;
#pragma unroll
    for (int o = 16; o > 0; o >>= 1) {
        sq += __shfl_xor_sync(0xffffffffu, sq, o);
        sk += __shfl_xor_sync(0xffffffffu, sk, o);
    }
    float rq = rsqrtf(sq * (1.f / 64.f) + 1e-6f);
    float rk = rsqrtf(sk * (1.f / 64.f) + 1e-6f);
    q1 *= rq * qw[l]; q2 *= rq * qw[l + 32];
    k1 *= rk * kw[l]; k2 *= rk * kw[l + 32];

    float c1 = cosb[n * HD + l], c2 = cosb[n * HD + l + 32];
    float s1 = sinb[n * HD + l], s2 = sinb[n * HD + l + 32];

    size_t o = (((size_t)(b * NHEAD + h)) * NSEQ + n) * HD;
    Qh[o + l]      = __float2half_rn((q1 * c1 - q2 * s1) * 0.125f);
    Qh[o + l + 32] = __float2half_rn((q2 * c2 + q1 * s2) * 0.125f);
    store_hl16(Kh, Kl, o + l,      k1 * c1 - k2 * s1);
    store_hl16(Kh, Kl, o + l + 32, k2 * c2 + k1 * s2);
    store_hl16(Vh, Vl, o + l,      v1);
    store_hl16(Vh, Vl, o + l + 32, v2);
}

// ---------------------------------------------------------------------------
// Flash attention on fp16 HMMA, 2-pass correction. 256 threads, 128 q rows.
// S = qh*(kh+kl)  (Q single fp16; delta-pass dropped: ~2e-4 abs logit err)
// O = ph*(vh+vl)  (P single fp16 scaled by 2^-8 exact; ~1.6e-4 rel err)
// NO online max (|s| <= 16 bound); l accumulated in fp32, out = 256*o/l.
// SMEM: Q 16K | stage{Kh,Kl,Vh,Vl}x2 = 64K  -> 80K, 2 CTAs/SM.
// ---------------------------------------------------------------------------
#define FA_SMEM 81920
#define PSCALE 0.00390625f           // 2^-8

__global__ __launch_bounds__(256, 2) void flash_hmma(
    const __half* __restrict__ Qh,
    const __half* __restrict__ Kh, const __half* __restrict__ Kl,
    const __half* __restrict__ Vh, const __half* __restrict__ Vl,
    __nv_bfloat16* __restrict__ Ohi, __nv_bfloat16* __restrict__ Olo)
{
    extern __shared__ __align__(128) char smc[];
    const unsigned sb = smem_u32(smc);
    const int t = threadIdx.x, lane = t & 31, w = t >> 5;
    const int bh = blockIdx.x, qt = blockIdx.y;
    const int b = bh >> 4, h = bh & 15;
    const int grp = lane >> 3, ri = lane & 7;

    const size_t qoff = ((size_t)bh * NSEQ + qt * 128) * HD;
    const size_t kvoff = (size_t)bh * NSEQ * HD;

    const __half* mats[4] = {Kh, Kl, Vh, Vl};

    auto issue = [&](int j, int s) {
        const unsigned stb = sb + 16384 + s * 32768;
#pragma unroll
        for (int m = 0; m < 4; m++) {
            const __half* g = mats[m] + kvoff + (size_t)(j * 64) * HD;
            const unsigned mb = stb + m * 8192;
#pragma unroll
            for (int i = 0; i < 2; i++) {
                int idx = i * 256 + t;
                int r = idx >> 3, ch = idx & 7;
                CP16(mb + swz(r, ch), g + (size_t)r * HD + ch * 8);
            }
        }
    };

    issue(0, 0);
    CP_COMMIT();

    // Q tile -> smem (swizzled)
#pragma unroll
    for (int i = 0; i < 4; i++) {
        int idx = i * 256 + t;
        int r = idx >> 3, ch = idx & 7;
        *reinterpret_cast<uint4*>(smc + swz(r, ch)) =
            *reinterpret_cast<const uint4*>(Qh + qoff + (size_t)r * HD + ch * 8);
    }
    __syncthreads();

    unsigned qf[4][4];
#pragma unroll
    for (int kt = 0; kt < 4; kt++) {
        int r = w * 16 + (grp & 1) * 8 + ri;
        int ch = kt * 2 + (grp >> 1);
        ldsm4(qf[kt], sb + swz(r, ch));
    }

    float o[8][4];
#pragma unroll
    for (int d = 0; d < 8; d++)
#pragma unroll
        for (int c = 0; c < 4; c++) o[d][c] = 0.f;
    float l0r = 0.f, l1r = 0.f;

    for (int j = 0; j < NSEQ / 64; j++) {
        CP_WAIT0();
        __syncthreads();
        if (j + 1 < NSEQ / 64) {
            issue(j + 1, (j + 1) & 1);
            CP_COMMIT();
        }
        const unsigned stb = sb + 16384 + (j & 1) * 32768;

        // ---- S = Q K^T (2-pass: kh + kl) ----
        float s[8][4];
#pragma unroll
        for (int nt = 0; nt < 8; nt++)
#pragma unroll
            for (int c = 0; c < 4; c++) s[nt][c] = 0.f;

#pragma unroll
        for (int kt = 0; kt < 4; kt++) {
#pragma unroll
            for (int np = 0; np < 4; np++) {
                int r = np * 16 + ((grp >> 1) & 1) * 8 + ri;
                int ch = kt * 2 + (grp & 1);
                unsigned kh[4], kl[4];
                ldsm4(kh, stb + swz(r, ch));
                ldsm4(kl, stb + 8192 + swz(r, ch));
                mma16816h(s[2 * np],     qf[kt], kh[0], kh[1]);
                mma16816h(s[2 * np + 1], qf[kt], kh[2], kh[3]);
                mma16816h(s[2 * np],     qf[kt], kl[0], kl[1]);
                mma16816h(s[2 * np + 1], qf[kt], kl[2], kl[3]);
            }
        }

        // ---- softmax numerators ----
        float ps0 = 0.f, ps1 = 0.f;
#pragma unroll
        for (int nt = 0; nt < 8; nt++) {
            s[nt][0] = fast_exp(s[nt][0]);
            s[nt][1] = fast_exp(s[nt][1]);
            s[nt][2] = fast_exp(s[nt][2]);
            s[nt][3] = fast_exp(s[nt][3]);
            ps0 += s[nt][0] + s[nt][1];
            ps1 += s[nt][2] + s[nt][3];
        }
        ps0 += __shfl_xor_sync(0xffffffffu, ps0, 1);
        ps0 += __shfl_xor_sync(0xffffffffu, ps0, 2);
        ps1 += __shfl_xor_sync(0xffffffffu, ps1, 1);
        ps1 += __shfl_xor_sync(0xffffffffu, ps1, 2);
        l0r += ps0;
        l1r += ps1;

        // ---- O += P V (2-pass: vh + vl), P fp16 scaled by 2^-8 (exact) ----
#pragma unroll
        for (int ct = 0; ct < 4; ct++) {
            unsigned ph[4];
            ph[0] = pack_h2(s[2 * ct][0] * PSCALE,     s[2 * ct][1] * PSCALE);
            ph[1] = pack_h2(s[2 * ct][2] * PSCALE,     s[2 * ct][3] * PSCALE);
            ph[2] = pack_h2(s[2 * ct + 1][0] * PSCALE, s[2 * ct + 1][1] * PSCALE);
            ph[3] = pack_h2(s[2 * ct + 1][2] * PSCALE, s[2 * ct + 1][3] * PSCALE);
#pragma unroll
            for (int dp = 0; dp < 4; dp++) {
                int r = ct * 16 + (lane & 15);
                int ch = dp * 2 + (lane >> 4);
                unsigned vh[4], vl[4];
                ldsm4t(vh, stb + 16384 + swz(r, ch));
                ldsm4t(vl, stb + 24576 + swz(r, ch));
                mma16816h(o[2 * dp],     ph, vh[0], vh[1]);
                mma16816h(o[2 * dp + 1], ph, vh[2], vh[3]);
                mma16816h(o[2 * dp],     ph, vl[0], vl[1]);
                mma16816h(o[2 * dp + 1], ph, vl[2], vl[3]);
            }
        }
    }

    // ---- epilogue: 256*O/l -> hi/lo bf16 att in [B,N,C] layout ----
    const float inv0 = 256.0f / l0r, inv1 = 256.0f / l1r;
#pragma unroll
    for (int dt = 0; dt < 8; dt++) {
        int col = h * 64 + dt * 8 + (lane & 3) * 2;
        int r0 = qt * 128 + w * 16 + (lane >> 2);
        size_t i0 = ((size_t)b * NSEQ + r0) * CDIM + col;
        size_t i1 = ((size_t)b * NSEQ + r0 + 8) * CDIM + col;
        unsigned h0, l0, h1, l1;
        split_pair(o[dt][0] * inv0, o[dt][1] * inv0, h0, l0);
        split_pair(o[dt][2] * inv1, o[dt][3] * inv1, h1, l1);
        *reinterpret_cast<unsigned*>(&Ohi[i0]) = h0;
        *reinterpret_cast<unsigned*>(&Olo[i0]) = l0;
        *reinterpret_cast<unsigned*>(&Ohi[i1]) = h1;
        *reinterpret_cast<unsigned*>(&Olo[i1]) = l1;
    }
}

// ---------------------------------------------------------------------------
extern "C" void kernel_launch(void* const* d_in, const int* in_sizes, int n_in,
                              void* d_out, int out_size)
{
    const float* x      = (const float*)d_in[0];
    const float* cosb   = (const float*)d_in[1];
    const float* sinb   = (const float*)d_in[2];
    const float* w_qkv  = (const float*)d_in[3];
    const float* w_proj = (const float*)d_in[4];
    const float* b_proj = (const float*)d_in[5];
    const float* qw     = (const float*)d_in[6];
    const float* kw     = (const float*)d_in[7];
    float* out = (float*)d_out;

    float* qkv;
    __nv_bfloat16 *ahi, *alo, *wqh, *wql, *wph, *wpl;
    __half *qh, *kh, *kl, *vh, *vl;
    cudaGetSymbolAddress((void**)&qkv, g_qkv);
    cudaGetSymbolAddress((void**)&ahi, g_ahi);
    cudaGetSymbolAddress((void**)&alo, g_alo);
    cudaGetSymbolAddress((void**)&wqh, g_wqkvhi);
    cudaGetSymbolAddress((void**)&wql, g_wqkvlo);
    cudaGetSymbolAddress((void**)&wph, g_wprojhi);
    cudaGetSymbolAddress((void**)&wpl, g_wprojlo);
    cudaGetSymbolAddress((void**)&qh, g_qh);
    cudaGetSymbolAddress((void**)&kh, g_kh);
    cudaGetSymbolAddress((void**)&kl, g_kl);
    cudaGetSymbolAddress((void**)&vh, g_vh);
    cudaGetSymbolAddress((void**)&vl, g_vl);

    cudaFuncSetAttribute(gemm_hmma<false>,
                         cudaFuncAttributeMaxDynamicSharedMemorySize, GEMM_SMEM);
    cudaFuncSetAttribute(gemm_hmma<true>,
                         cudaFuncAttributeMaxDynamicSharedMemorySize, GEMM_SMEM);
    cudaFuncSetAttribute(flash_hmma,
                         cudaFuncAttributeMaxDynamicSharedMemorySize, FA_SMEM);

    // 0) hi/lo splits of x and both weights (one merged launch)
    split_all<<<(NX4 + NQ4 + NP4) / 256, 256>>>(
        x, w_qkv, w_proj, ahi, alo, wqh, wql, wph, wpl);

    // 1) qkv = x @ w_qkv^T
    gemm_hmma<false><<<dim3(QKVDIM / 128, MROWS / 128), 256, GEMM_SMEM>>>(
        ahi, alo, wqh, wql, nullptr, qkv, QKVDIM);

    // 2) rmsnorm + rope -> fp16 Q(pre-scaled), K/V hi/lo
    prep_kernel<<<dim3(MROWS, 2), 256>>>(qkv, cosb, sinb, qw, kw,
                                         qh, kh, kl, vh, vl);

    // 3) flash attention -> att hi/lo bf16 (into g_ahi/g_alo)
    flash_hmma<<<dim3(BHTOT, NSEQ / 128), 256, FA_SMEM>>>(
        qh, kh, kl, vh, vl, ahi, alo);

    // 4) out = att @ w_proj^T + b
    gemm_hmma<true><<<dim3(CDIM / 128, MROWS / 128), 256, GEMM_SMEM>>>(
        ahi, alo, wph, wpl, b_proj, out, CDIM);
}

// round 11
// speedup vs baseline: 1.6987x; 1.2882x over previous
#include <cuda_runtime.h>
#include <cuda_bf16.h>
#include <cuda_fp16.h>
#include <math.h>

// Problem constants
#define B_SZ 4
#define NSEQ 2048
#define CDIM 1024
#define NHEAD 16
#define HD 64
#define MROWS 8192
#define QKVDIM 3072
#define BHTOT 64

// ---------------------------------------------------------------------------
// Static device scratch (allocation-free kernel_launch)
// ---------------------------------------------------------------------------
__device__ float g_qkv[MROWS * QKVDIM];
__device__ __half g_x16[MROWS * CDIM];            // x single fp16
__device__ __half g_att16[MROWS * CDIM];          // att single fp16
__device__ __half g_wqkvhi[QKVDIM * CDIM];
__device__ __half g_wqkvlo[QKVDIM * CDIM];
__device__ __half g_wprojhi[CDIM * CDIM];
__device__ __half g_wprojlo[CDIM * CDIM];
__device__ __half g_qh[BHTOT * NSEQ * HD];        // fp16 Q (pre-scaled 1/8)
__device__ __half g_kh[BHTOT * NSEQ * HD];        // fp16 K (single)
__device__ __half g_vh[BHTOT * NSEQ * HD];        // fp16 V hi/lo
__device__ __half g_vl[BHTOT * NSEQ * HD];

// ---------------------------------------------------------------------------
// Helpers
// ---------------------------------------------------------------------------
__device__ __forceinline__ unsigned smem_u32(const void* p) {
    unsigned a;
    asm("{ .reg .u64 t; cvta.to.shared.u64 t, %1; cvt.u32.u64 %0, t; }"
        : "=r"(a) : "l"(p));
    return a;
}

__device__ __forceinline__ void ldsm4(unsigned* r, unsigned a) {
    asm volatile("ldmatrix.sync.aligned.m8n8.x4.shared.b16 {%0,%1,%2,%3}, [%4];"
        : "=r"(r[0]), "=r"(r[1]), "=r"(r[2]), "=r"(r[3]) : "r"(a));
}
__device__ __forceinline__ void ldsm4t(unsigned* r, unsigned a) {
    asm volatile("ldmatrix.sync.aligned.m8n8.x4.trans.shared.b16 {%0,%1,%2,%3}, [%4];"
        : "=r"(r[0]), "=r"(r[1]), "=r"(r[2]), "=r"(r[3]) : "r"(a));
}
// fp16 HMMA
__device__ __forceinline__ void mma16816h(float* d, const unsigned* a,
                                          unsigned b0, unsigned b1) {
    asm volatile(
        "mma.sync.aligned.m16n8k16.row.col.f32.f16.f16.f32 "
        "{%0,%1,%2,%3}, {%4,%5,%6,%7}, {%8,%9}, {%0,%1,%2,%3};"
        : "+f"(d[0]), "+f"(d[1]), "+f"(d[2]), "+f"(d[3])
        : "r"(a[0]), "r"(a[1]), "r"(a[2]), "r"(a[3]), "r"(b0), "r"(b1));
}

#define CP16(sa, g) \
    asm volatile("cp.async.cg.shared.global [%0], [%1], 16;" :: "r"(sa), "l"(g))
#define CP_COMMIT() asm volatile("cp.async.commit_group;")
#define CP_WAIT1()  asm volatile("cp.async.wait_group 1;")
#define CP_WAIT0()  asm volatile("cp.async.wait_group 0;")

// chunk swizzle: 128B rows, 8 x 16B chunks
__device__ __forceinline__ unsigned swz(int row, int chunk) {
    return (unsigned)(row * 128 + ((chunk ^ (row & 7)) * 16));
}

// FMA-only exp (no MUFU, no CVT, no clamp — inputs bounded |x| <= 32).
__device__ __forceinline__ float fast_exp(float x) {
    float t = fmaf(x, 1.442695041f, 12582912.f);
    int ebits = __float_as_int(t) << 23;
    float fi = t - 12582912.f;
    float f = fmaf(x, 1.442695041f, -fi);
    float p = 1.3333558e-3f;
    p = fmaf(p, f, 9.6181291e-3f);
    p = fmaf(p, f, 5.5504109e-2f);
    p = fmaf(p, f, 2.4022651e-1f);
    p = fmaf(p, f, 6.9314718e-1f);
    p = fmaf(p, f, 1.0f);
    return __int_as_float(__float_as_int(p) + ebits);
}

__device__ __forceinline__ unsigned pack_h2(float x, float y) {
    __half2 h = __floats2half2_rn(x, y);
    return *reinterpret_cast<unsigned*>(&h);
}

// fp16 hi/lo split of a pair
__device__ __forceinline__ void split_pair16(float x, float y,
                                             unsigned& hi, unsigned& lo) {
    __half hx = __float2half_rn(x), hy = __float2half_rn(y);
    float rx = x - __half2float(hx);
    float ry = y - __half2float(hy);
    __half2 H(hx, hy);
    __half2 L(__float2half_rn(rx), __float2half_rn(ry));
    hi = *reinterpret_cast<unsigned*>(&H);
    lo = *reinterpret_cast<unsigned*>(&L);
}

__device__ __forceinline__ void store_hl16(__half* H, __half* L,
                                           size_t i, float v) {
    __half h = __float2half_rn(v);
    H[i] = h;
    L[i] = __float2half_rn(v - __half2float(h));
}

// ---------------------------------------------------------------------------
// One merged split kernel: x -> f16 single; w_qkv, w_proj -> f16 hi/lo
// ---------------------------------------------------------------------------
#define NX4 (MROWS * CDIM / 4)
#define NQ4 (QKVDIM * CDIM / 4)
#define NP4 (CDIM * CDIM / 4)

__global__ __launch_bounds__(256) void split_all(
    const float* __restrict__ x, const float* __restrict__ wq,
    const float* __restrict__ wp,
    __half* __restrict__ x16,
    __half* __restrict__ wqh, __half* __restrict__ wql,
    __half* __restrict__ wph, __half* __restrict__ wpl)
{
    int i = blockIdx.x * 256 + threadIdx.x;
    if (i < NX4) {
        float4 v = reinterpret_cast<const float4*>(x)[i];
        reinterpret_cast<unsigned*>(x16)[2 * i]     = pack_h2(v.x, v.y);
        reinterpret_cast<unsigned*>(x16)[2 * i + 1] = pack_h2(v.z, v.w);
        return;
    }
    const float* src;
    __half *hi, *lo;
    if (i < NX4 + NQ4) { i -= NX4; src = wq; hi = wqh; lo = wql; }
    else               { i -= NX4 + NQ4; src = wp; hi = wph; lo = wpl; }
    float4 v = reinterpret_cast<const float4*>(src)[i];
    unsigned h01, l01, h23, l23;
    split_pair16(v.x, v.y, h01, l01);
    split_pair16(v.z, v.w, h23, l23);
    reinterpret_cast<unsigned*>(hi)[2 * i]     = h01;
    reinterpret_cast<unsigned*>(hi)[2 * i + 1] = h23;
    reinterpret_cast<unsigned*>(lo)[2 * i]     = l01;
    reinterpret_cast<unsigned*>(lo)[2 * i + 1] = l23;
}

// ---------------------------------------------------------------------------
// fp16 HMMA GEMM (NT): C[m,n] = sum_k A[m,k]*B[n,k] (+bias).
// A single fp16, B hi/lo fp16, 2 passes per stage.
// 128x128 tile, BK=64 stage {A 16K | Bh 16K | Bl 16K} = 48KB x 3 stages.
// ---------------------------------------------------------------------------
#define GS_STAGE 49152
#define GEMM_SMEM (3 * GS_STAGE)     // 147456
#define NSTAGES 16                   // K=1024 / 64

template <bool BIAS>
__global__ __launch_bounds__(256) void gemm_hmma(
    const __half* __restrict__ A,
    const __half* __restrict__ Bhi, const __half* __restrict__ Blo,
    const float* __restrict__ bias, float* __restrict__ C, int N)
{
    extern __shared__ __align__(128) char smc[];
    const unsigned sb = smem_u32(smc);
    const int t = threadIdx.x, lane = t & 31, wid = t >> 5;
    const int wm = wid & 1, wn = wid >> 1;
    const int m0 = blockIdx.y * 128, n0 = blockIdx.x * 128;
    const int K = 1024;
    const int grp = lane >> 3, ri = lane & 7;

    float acc[4][4][4];
#pragma unroll
    for (int a = 0; a < 4; a++)
#pragma unroll
        for (int b = 0; b < 4; b++)
#pragma unroll
            for (int c = 0; c < 4; c++) acc[a][b][c] = 0.f;

    const __half* srcs[3] = {
        A + (size_t)m0 * K, Bhi + (size_t)n0 * K, Blo + (size_t)n0 * K };

    // stage loader: 48KB = 3 mats x 128 rows x 8 chunks; 12 chunks/thread
    auto issue = [&](int s, int buf) {
        const int k0 = s * 64;
        const unsigned stb = sb + buf * GS_STAGE;
#pragma unroll
        for (int m = 0; m < 3; m++) {
            const unsigned mb = stb + m * 16384;
            const __half* g = srcs[m] + k0;
#pragma unroll
            for (int i = 0; i < 4; i++) {
                int idx = i * 256 + t;
                int r = idx >> 3, ch = idx & 7;
                CP16(mb + swz(r, ch), g + (size_t)r * K + ch * 8);
            }
        }
    };

    issue(0, 0); CP_COMMIT();
    issue(1, 1); CP_COMMIT();

    for (int it = 0; it < NSTAGES; it++) {
        if (it == NSTAGES - 1) { CP_WAIT0(); } else { CP_WAIT1(); }
        __syncthreads();
        if (it + 2 < NSTAGES) {
            issue(it + 2, (it + 2) % 3);
            CP_COMMIT();
        }
        const unsigned stb = sb + (it % 3) * GS_STAGE;
        const unsigned ab = stb;
        const unsigned bbh = stb + 16384, bbl = stb + 32768;
#pragma unroll
        for (int k4 = 0; k4 < 4; k4++) {
            unsigned af[4][4], bh[2][4], bl[2][4];
#pragma unroll
            for (int mt = 0; mt < 4; mt++) {
                int r = wm * 64 + mt * 16 + (grp & 1) * 8 + ri;
                int ch = k4 * 2 + (grp >> 1);
                ldsm4(af[mt], ab + swz(r, ch));
            }
#pragma unroll
            for (int np = 0; np < 2; np++) {
                int r = wn * 32 + np * 16 + ((grp >> 1) & 1) * 8 + ri;
                int ch = k4 * 2 + (grp & 1);
                ldsm4(bh[np], bbh + swz(r, ch));
                ldsm4(bl[np], bbl + swz(r, ch));
            }
            // pass 1: A * Bhi
#pragma unroll
            for (int mt = 0; mt < 4; mt++)
#pragma unroll
                for (int np = 0; np < 2; np++) {
                    mma16816h(acc[mt][2 * np],     af[mt], bh[np][0], bh[np][1]);
                    mma16816h(acc[mt][2 * np + 1], af[mt], bh[np][2], bh[np][3]);
                }
            // pass 2: A * Blo
#pragma unroll
            for (int mt = 0; mt < 4; mt++)
#pragma unroll
                for (int np = 0; np < 2; np++) {
                    mma16816h(acc[mt][2 * np],     af[mt], bl[np][0], bl[np][1]);
                    mma16816h(acc[mt][2 * np + 1], af[mt], bl[np][2], bl[np][3]);
                }
        }
    }

    // epilogue
#pragma unroll
    for (int mt = 0; mt < 4; mt++)
#pragma unroll
        for (int nt = 0; nt < 4; nt++) {
            int col = n0 + wn * 32 + nt * 8 + (lane & 3) * 2;
            int r0 = m0 + wm * 64 + mt * 16 + (lane >> 2);
            float bx = 0.f, by = 0.f;
            if (BIAS) { bx = bias[col]; by = bias[col + 1]; }
            float2 v0 = make_float2(acc[mt][nt][0] + bx, acc[mt][nt][1] + by);
            float2 v1 = make_float2(acc[mt][nt][2] + bx, acc[mt][nt][3] + by);
            *reinterpret_cast<float2*>(&C[(size_t)r0 * N + col]) = v0;
            *reinterpret_cast<float2*>(&C[(size_t)(r0 + 8) * N + col]) = v1;
        }
}

// ---------------------------------------------------------------------------
// Prep: split qkv, RMSNorm(q,k), RoPE(q,k); emit fp16 Q (pre-scaled 1/8),
// fp16 K (single), fp16 hi/lo V in [b*H+h][n][64] layout. Warp per (b,n,h).
// ---------------------------------------------------------------------------
__global__ __launch_bounds__(256) void prep_kernel(
    const float* __restrict__ qkv,
    const float* __restrict__ cosb, const float* __restrict__ sinb,
    const float* __restrict__ qw, const float* __restrict__ kw,
    __half* __restrict__ Qh, __half* __restrict__ Kh,
    __half* __restrict__ Vh, __half* __restrict__ Vl)
{
    const int bn = blockIdx.x;
    const int h = (blockIdx.y << 3) | (threadIdx.x >> 5);
    const int l = threadIdx.x & 31;
    const int b = bn >> 11;
    const int n = bn & 2047;

    const float* base = qkv + (size_t)bn * QKVDIM + h * HD;
    float q1 = base[l],            q2 = base[l + 32];
    float k1 = base[CDIM + l],     k2 = base[CDIM + l + 32];
    float v1 = base[2 * CDIM + l], v2 = base[2 * CDIM + l + 32];

    float sq = q1 * q1 + q2 * q2;
    float sk = k1 * k1 + k2 * k2;
#pragma unroll
    for (int o = 16; o > 0; o >>= 1) {
        sq += __shfl_xor_sync(0xffffffffu, sq, o);
        sk += __shfl_xor_sync(0xffffffffu, sk, o);
    }
    float rq = rsqrtf(sq * (1.f / 64.f) + 1e-6f);
    float rk = rsqrtf(sk * (1.f / 64.f) + 1e-6f);
    q1 *= rq * qw[l]; q2 *= rq * qw[l + 32];
    k1 *= rk * kw[l]; k2 *= rk * kw[l + 32];

    float c1 = cosb[n * HD + l], c2 = cosb[n * HD + l + 32];
    float s1 = sinb[n * HD + l], s2 = sinb[n * HD + l + 32];

    size_t o = (((size_t)(b * NHEAD + h)) * NSEQ + n) * HD;
    Qh[o + l]      = __float2half_rn((q1 * c1 - q2 * s1) * 0.125f);
    Qh[o + l + 32] = __float2half_rn((q2 * c2 + q1 * s2) * 0.125f);
    Kh[o + l]      = __float2half_rn(k1 * c1 - k2 * s1);
    Kh[o + l + 32] = __float2half_rn(k2 * c2 + k1 * s2);
    store_hl16(Vh, Vl, o + l,      v1);
    store_hl16(Vh, Vl, o + l + 32, v2);
}

// ---------------------------------------------------------------------------
// Flash attention on fp16 HMMA. 256 threads, 128 q rows.
// S = q*k single-pass; O = p*(vh+vl) 2-pass; P fp16 scaled 2^-8 (exact).
// NO online max (|s| <= 16 bound); out = 256*o/l, stored single fp16.
// SMEM: Q 16K | stage{Kh,Vh,Vl}x2 = 48K -> 64K total, 2 CTAs/SM.
// ---------------------------------------------------------------------------
#define FA_STAGE 24576
#define FA_SMEM (16384 + 2 * FA_STAGE)   // 65536
#define PSCALE 0.00390625f               // 2^-8

__global__ __launch_bounds__(256, 2) void flash_hmma(
    const __half* __restrict__ Qh, const __half* __restrict__ Kh,
    const __half* __restrict__ Vh, const __half* __restrict__ Vl,
    __half* __restrict__ Att)
{
    extern __shared__ __align__(128) char smc[];
    const unsigned sb = smem_u32(smc);
    const int t = threadIdx.x, lane = t & 31, w = t >> 5;
    const int bh = blockIdx.x, qt = blockIdx.y;
    const int b = bh >> 4, h = bh & 15;
    const int grp = lane >> 3, ri = lane & 7;

    const size_t qoff = ((size_t)bh * NSEQ + qt * 128) * HD;
    const size_t kvoff = (size_t)bh * NSEQ * HD;

    const __half* mats[3] = {Kh, Vh, Vl};

    auto issue = [&](int j, int s) {
        const unsigned stb = sb + 16384 + s * FA_STAGE;
#pragma unroll
        for (int m = 0; m < 3; m++) {
            const __half* g = mats[m] + kvoff + (size_t)(j * 64) * HD;
            const unsigned mb = stb + m * 8192;
#pragma unroll
            for (int i = 0; i < 2; i++) {
                int idx = i * 256 + t;
                int r = idx >> 3, ch = idx & 7;
                CP16(mb + swz(r, ch), g + (size_t)r * HD + ch * 8);
            }
        }
    };

    issue(0, 0);
    CP_COMMIT();

    // Q tile -> smem (swizzled)
#pragma unroll
    for (int i = 0; i < 4; i++) {
        int idx = i * 256 + t;
        int r = idx >> 3, ch = idx & 7;
        *reinterpret_cast<uint4*>(smc + swz(r, ch)) =
            *reinterpret_cast<const uint4*>(Qh + qoff + (size_t)r * HD + ch * 8);
    }
    __syncthreads();

    unsigned qf[4][4];
#pragma unroll
    for (int kt = 0; kt < 4; kt++) {
        int r = w * 16 + (grp & 1) * 8 + ri;
        int ch = kt * 2 + (grp >> 1);
        ldsm4(qf[kt], sb + swz(r, ch));
    }

    float o[8][4];
#pragma unroll
    for (int d = 0; d < 8; d++)
#pragma unroll
        for (int c = 0; c < 4; c++) o[d][c] = 0.f;
    float l0r = 0.f, l1r = 0.f;

    for (int j = 0; j < NSEQ / 64; j++) {
        CP_WAIT0();
        __syncthreads();
        if (j + 1 < NSEQ / 64) {
            issue(j + 1, (j + 1) & 1);
            CP_COMMIT();
        }
        const unsigned stb = sb + 16384 + (j & 1) * FA_STAGE;

        // ---- S = Q K^T (single pass) ----
        float s[8][4];
#pragma unroll
        for (int nt = 0; nt < 8; nt++)
#pragma unroll
            for (int c = 0; c < 4; c++) s[nt][c] = 0.f;

#pragma unroll
        for (int kt = 0; kt < 4; kt++) {
#pragma unroll
            for (int np = 0; np < 4; np++) {
                int r = np * 16 + ((grp >> 1) & 1) * 8 + ri;
                int ch = kt * 2 + (grp & 1);
                unsigned kf[4];
                ldsm4(kf, stb + swz(r, ch));
                mma16816h(s[2 * np],     qf[kt], kf[0], kf[1]);
                mma16816h(s[2 * np + 1], qf[kt], kf[2], kf[3]);
            }
        }

        // ---- softmax numerators ----
        float ps0 = 0.f, ps1 = 0.f;
#pragma unroll
        for (int nt = 0; nt < 8; nt++) {
            s[nt][0] = fast_exp(s[nt][0]);
            s[nt][1] = fast_exp(s[nt][1]);
            s[nt][2] = fast_exp(s[nt][2]);
            s[nt][3] = fast_exp(s[nt][3]);
            ps0 += s[nt][0] + s[nt][1];
            ps1 += s[nt][2] + s[nt][3];
        }
        ps0 += __shfl_xor_sync(0xffffffffu, ps0, 1);
        ps0 += __shfl_xor_sync(0xffffffffu, ps0, 2);
        ps1 += __shfl_xor_sync(0xffffffffu, ps1, 1);
        ps1 += __shfl_xor_sync(0xffffffffu, ps1, 2);
        l0r += ps0;
        l1r += ps1;

        // ---- O += P V (2-pass: vh + vl), P fp16 scaled by 2^-8 (exact) ----
#pragma unroll
        for (int ct = 0; ct < 4; ct++) {
            unsigned ph[4];
            ph[0] = pack_h2(s[2 * ct][0] * PSCALE,     s[2 * ct][1] * PSCALE);
            ph[1] = pack_h2(s[2 * ct][2] * PSCALE,     s[2 * ct][3] * PSCALE);
            ph[2] = pack_h2(s[2 * ct + 1][0] * PSCALE, s[2 * ct + 1][1] * PSCALE);
            ph[3] = pack_h2(s[2 * ct + 1][2] * PSCALE, s[2 * ct + 1][3] * PSCALE);
#pragma unroll
            for (int dp = 0; dp < 4; dp++) {
                int r = ct * 16 + (lane & 15);
                int ch = dp * 2 + (lane >> 4);
                unsigned vh[4], vl[4];
                ldsm4t(vh, stb + 8192 + swz(r, ch));
                ldsm4t(vl, stb + 16384 + swz(r, ch));
                mma16816h(o[2 * dp],     ph, vh[0], vh[1]);
                mma16816h(o[2 * dp + 1], ph, vh[2], vh[3]);
                mma16816h(o[2 * dp],     ph, vl[0], vl[1]);
                mma16816h(o[2 * dp + 1], ph, vl[2], vl[3]);
            }
        }
    }

    // ---- epilogue: 256*O/l -> single fp16 att in [B,N,C] layout ----
    const float inv0 = 256.0f / l0r, inv1 = 256.0f / l1r;
#pragma unroll
    for (int dt = 0; dt < 8; dt++) {
        int col = h * 64 + dt * 8 + (lane & 3) * 2;
        int r0 = qt * 128 + w * 16 + (lane >> 2);
        size_t i0 = ((size_t)b * NSEQ + r0) * CDIM + col;
        size_t i1 = ((size_t)b * NSEQ + r0 + 8) * CDIM + col;
        *reinterpret_cast<unsigned*>(&Att[i0]) =
            pack_h2(o[dt][0] * inv0, o[dt][1] * inv0);
        *reinterpret_cast<unsigned*>(&Att[i1]) =
            pack_h2(o[dt][2] * inv1, o[dt][3] * inv1);
    }
}

// ---------------------------------------------------------------------------
extern "C" void kernel_launch(void* const* d_in, const int* in_sizes, int n_in,
                              void* d_out, int out_size)
{
    const float* x      = (const float*)d_in[0];
    const float* cosb   = (const float*)d_in[1];
    const float* sinb   = (const float*)d_in[2];
    const float* w_qkv  = (const float*)d_in[3];
    const float* w_proj = (const float*)d_in[4];
    const float* b_proj = (const float*)d_in[5];
    const float* qw     = (const float*)d_in[6];
    const float* kw     = (const float*)d_in[7];
    float* out = (float*)d_out;

    float* qkv;
    __half *x16, *att16, *wqh, *wql, *wph, *wpl;
    __half *qh, *kh, *vh, *vl;
    cudaGetSymbolAddress((void**)&qkv, g_qkv);
    cudaGetSymbolAddress((void**)&x16, g_x16);
    cudaGetSymbolAddress((void**)&att16, g_att16);
    cudaGetSymbolAddress((void**)&wqh, g_wqkvhi);
    cudaGetSymbolAddress((void**)&wql, g_wqkvlo);
    cudaGetSymbolAddress((void**)&wph, g_wprojhi);
    cudaGetSymbolAddress((void**)&wpl, g_wprojlo);
    cudaGetSymbolAddress((void**)&qh, g_qh);
    cudaGetSymbolAddress((void**)&kh, g_kh);
    cudaGetSymbolAddress((void**)&vh, g_vh);
    cudaGetSymbolAddress((void**)&vl, g_vl);

    cudaFuncSetAttribute(gemm_hmma<false>,
                         cudaFuncAttributeMaxDynamicSharedMemorySize, GEMM_SMEM);
    cudaFuncSetAttribute(gemm_hmma<true>,
                         cudaFuncAttributeMaxDynamicSharedMemorySize, GEMM_SMEM);
    cudaFuncSetAttribute(flash_hmma,
                         cudaFuncAttributeMaxDynamicSharedMemorySize, FA_SMEM);

    // 0) splits: x -> f16 single; weights -> f16 hi/lo (one launch)
    split_all<<<(NX4 + NQ4 + NP4) / 256, 256>>>(
        x, w_qkv, w_proj, x16, wqh, wql, wph, wpl);

    // 1) qkv = x @ w_qkv^T (fp16 2-pass)
    gemm_hmma<false><<<dim3(QKVDIM / 128, MROWS / 128), 256, GEMM_SMEM>>>(
        x16, wqh, wql, nullptr, qkv, QKVDIM);

    // 2) rmsnorm + rope -> fp16 Q(pre-scaled), K single, V hi/lo
    prep_kernel<<<dim3(MROWS, 2), 256>>>(qkv, cosb, sinb, qw, kw,
                                         qh, kh, vh, vl);

    // 3) flash attention -> att single fp16
    flash_hmma<<<dim3(BHTOT, NSEQ / 128), 256, FA_SMEM>>>(
        qh, kh, vh, vl, att16);

    // 4) out = att @ w_proj^T + b (fp16 2-pass)
    gemm_hmma<true><<<dim3(CDIM / 128, MROWS / 128), 256, GEMM_SMEM>>>(
        att16, wph, wpl, b_proj, out, CDIM);
}

// round 12
// speedup vs baseline: 2.0111x; 1.1839x over previous
#include <cuda_runtime.h>
#include <cuda_fp16.h>
#include <math.h>

// Problem constants
#define B_SZ 4
#define NSEQ 2048
#define CDIM 1024
#define NHEAD 16
#define HD 64
#define MROWS 8192
#define QKVDIM 3072
#define BHTOT 64

// ---------------------------------------------------------------------------
// Static device scratch (allocation-free kernel_launch)
// ---------------------------------------------------------------------------
__device__ float g_qkv[MROWS * QKVDIM];
__device__ __half g_x16[MROWS * CDIM];            // x single fp16
__device__ __half g_att16[MROWS * CDIM];          // att single fp16
__device__ __half g_wqkvhi[QKVDIM * CDIM];
__device__ __half g_wqkvlo[QKVDIM * CDIM];
__device__ __half g_wproj16[CDIM * CDIM];         // w_proj single fp16
__device__ __half g_qh[BHTOT * NSEQ * HD];        // fp16 Q (pre-scaled 1/8)
__device__ __half g_kh[BHTOT * NSEQ * HD];        // fp16 K (single)
__device__ __half g_vh[BHTOT * NSEQ * HD];        // fp16 V (single)

// ---------------------------------------------------------------------------
// Helpers
// ---------------------------------------------------------------------------
__device__ __forceinline__ unsigned smem_u32(const void* p) {
    unsigned a;
    asm("{ .reg .u64 t; cvta.to.shared.u64 t, %1; cvt.u32.u64 %0, t; }"
        : "=r"(a) : "l"(p));
    return a;
}

__device__ __forceinline__ void ldsm4(unsigned* r, unsigned a) {
    asm volatile("ldmatrix.sync.aligned.m8n8.x4.shared.b16 {%0,%1,%2,%3}, [%4];"
        : "=r"(r[0]), "=r"(r[1]), "=r"(r[2]), "=r"(r[3]) : "r"(a));
}
__device__ __forceinline__ void ldsm4t(unsigned* r, unsigned a) {
    asm volatile("ldmatrix.sync.aligned.m8n8.x4.trans.shared.b16 {%0,%1,%2,%3}, [%4];"
        : "=r"(r[0]), "=r"(r[1]), "=r"(r[2]), "=r"(r[3]) : "r"(a));
}
// fp16 HMMA
__device__ __forceinline__ void mma16816h(float* d, const unsigned* a,
                                          unsigned b0, unsigned b1) {
    asm volatile(
        "mma.sync.aligned.m16n8k16.row.col.f32.f16.f16.f32 "
        "{%0,%1,%2,%3}, {%4,%5,%6,%7}, {%8,%9}, {%0,%1,%2,%3};"
        : "+f"(d[0]), "+f"(d[1]), "+f"(d[2]), "+f"(d[3])
        : "r"(a[0]), "r"(a[1]), "r"(a[2]), "r"(a[3]), "r"(b0), "r"(b1));
}

#define CP16(sa, g) \
    asm volatile("cp.async.cg.shared.global [%0], [%1], 16;" :: "r"(sa), "l"(g))
#define CP_COMMIT() asm volatile("cp.async.commit_group;")
#define CP_WAIT1()  asm volatile("cp.async.wait_group 1;")
#define CP_WAIT0()  asm volatile("cp.async.wait_group 0;")

// chunk swizzle: 128B rows, 8 x 16B chunks
__device__ __forceinline__ unsigned swz(int row, int chunk) {
    return (unsigned)(row * 128 + ((chunk ^ (row & 7)) * 16));
}

// FMA-only exp, result pre-scaled by 2^-8 (exponent-bit fold, exact).
// Inputs bounded |x| <= 32 -> no clamp needed.
__device__ __forceinline__ float fast_exp_p8(float x) {
    float t = fmaf(x, 1.442695041f, 12582912.f);
    int ebits = (__float_as_int(t) << 23) - (8 << 23);
    float fi = t - 12582912.f;
    float f = fmaf(x, 1.442695041f, -fi);
    float p = 1.3333558e-3f;
    p = fmaf(p, f, 9.6181291e-3f);
    p = fmaf(p, f, 5.5504109e-2f);
    p = fmaf(p, f, 2.4022651e-1f);
    p = fmaf(p, f, 6.9314718e-1f);
    p = fmaf(p, f, 1.0f);
    return __int_as_float(__float_as_int(p) + ebits);
}

__device__ __forceinline__ unsigned pack_h2(float x, float y) {
    __half2 h = __floats2half2_rn(x, y);
    return *reinterpret_cast<unsigned*>(&h);
}

// fp16 hi/lo split of a pair
__device__ __forceinline__ void split_pair16(float x, float y,
                                             unsigned& hi, unsigned& lo) {
    __half hx = __float2half_rn(x), hy = __float2half_rn(y);
    float rx = x - __half2float(hx);
    float ry = y - __half2float(hy);
    __half2 H(hx, hy);
    __half2 L(__float2half_rn(rx), __float2half_rn(ry));
    hi = *reinterpret_cast<unsigned*>(&H);
    lo = *reinterpret_cast<unsigned*>(&L);
}

// ---------------------------------------------------------------------------
// One merged split kernel: x, w_proj -> f16 single; w_qkv -> f16 hi/lo
// ---------------------------------------------------------------------------
#define NX4 (MROWS * CDIM / 4)
#define NQ4 (QKVDIM * CDIM / 4)
#define NP4 (CDIM * CDIM / 4)

__global__ __launch_bounds__(256) void split_all(
    const float* __restrict__ x, const float* __restrict__ wq,
    const float* __restrict__ wp,
    __half* __restrict__ x16,
    __half* __restrict__ wqh, __half* __restrict__ wql,
    __half* __restrict__ wp16)
{
    int i = blockIdx.x * 256 + threadIdx.x;
    if (i < NX4 + NP4) {
        const float* src;
        __half* dst;
        if (i < NX4) { src = x; dst = x16; }
        else         { i -= NX4; src = wp; dst = wp16; }
        float4 v = reinterpret_cast<const float4*>(src)[i];
        reinterpret_cast<unsigned*>(dst)[2 * i]     = pack_h2(v.x, v.y);
        reinterpret_cast<unsigned*>(dst)[2 * i + 1] = pack_h2(v.z, v.w);
        return;
    }
    i -= NX4 + NP4;
    float4 v = reinterpret_cast<const float4*>(wq)[i];
    unsigned h01, l01, h23, l23;
    split_pair16(v.x, v.y, h01, l01);
    split_pair16(v.z, v.w, h23, l23);
    reinterpret_cast<unsigned*>(wqh)[2 * i]     = h01;
    reinterpret_cast<unsigned*>(wqh)[2 * i + 1] = h23;
    reinterpret_cast<unsigned*>(wql)[2 * i]     = l01;
    reinterpret_cast<unsigned*>(wql)[2 * i + 1] = l23;
}

// ---------------------------------------------------------------------------
// fp16 HMMA GEMM (NT): C[m,n] = sum_k A[m,k]*B[n,k] (+bias).
// NMATS=3: A single + B hi/lo (2 passes).  NMATS=2: A single + B single.
// 128x128 tile, BK=64 stage of NMATS*16KB, 3-stage cp.async pipeline.
// ---------------------------------------------------------------------------
#define NSTAGES 16                   // K=1024 / 64

template <bool BIAS, int NMATS>
__global__ __launch_bounds__(256) void gemm_hmma(
    const __half* __restrict__ A,
    const __half* __restrict__ Bhi, const __half* __restrict__ Blo,
    const float* __restrict__ bias, float* __restrict__ C, int N)
{
    const int GS = NMATS * 16384;
    extern __shared__ __align__(128) char smc[];
    const unsigned sb = smem_u32(smc);
    const int t = threadIdx.x, lane = t & 31, wid = t >> 5;
    const int wm = wid & 1, wn = wid >> 1;
    const int m0 = blockIdx.y * 128, n0 = blockIdx.x * 128;
    const int K = 1024;
    const int grp = lane >> 3, ri = lane & 7;

    float acc[4][4][4];
#pragma unroll
    for (int a = 0; a < 4; a++)
#pragma unroll
        for (int b = 0; b < 4; b++)
#pragma unroll
            for (int c = 0; c < 4; c++) acc[a][b][c] = 0.f;

    const __half* srcs[3] = {
        A + (size_t)m0 * K, Bhi + (size_t)n0 * K,
        (NMATS == 3) ? Blo + (size_t)n0 * K : Bhi };

    auto issue = [&](int s, int buf) {
        const int k0 = s * 64;
        const unsigned stb = sb + buf * GS;
#pragma unroll
        for (int m = 0; m < NMATS; m++) {
            const unsigned mb = stb + m * 16384;
            const __half* g = srcs[m] + k0;
#pragma unroll
            for (int i = 0; i < 4; i++) {
                int idx = i * 256 + t;
                int r = idx >> 3, ch = idx & 7;
                CP16(mb + swz(r, ch), g + (size_t)r * K + ch * 8);
            }
        }
    };

    issue(0, 0); CP_COMMIT();
    issue(1, 1); CP_COMMIT();

    for (int it = 0; it < NSTAGES; it++) {
        if (it == NSTAGES - 1) { CP_WAIT0(); } else { CP_WAIT1(); }
        __syncthreads();
        if (it + 2 < NSTAGES) {
            issue(it + 2, (it + 2) % 3);
            CP_COMMIT();
        }
        const unsigned stb = sb + (it % 3) * GS;
        const unsigned ab = stb;
        const unsigned bbh = stb + 16384, bbl = stb + 32768;
#pragma unroll
        for (int k4 = 0; k4 < 4; k4++) {
            unsigned af[4][4], bh[2][4], bl[2][4];
#pragma unroll
            for (int mt = 0; mt < 4; mt++) {
                int r = wm * 64 + mt * 16 + (grp & 1) * 8 + ri;
                int ch = k4 * 2 + (grp >> 1);
                ldsm4(af[mt], ab + swz(r, ch));
            }
#pragma unroll
            for (int np = 0; np < 2; np++) {
                int r = wn * 32 + np * 16 + ((grp >> 1) & 1) * 8 + ri;
                int ch = k4 * 2 + (grp & 1);
                ldsm4(bh[np], bbh + swz(r, ch));
                if (NMATS == 3) ldsm4(bl[np], bbl + swz(r, ch));
            }
            // pass 1: A * Bhi
#pragma unroll
            for (int mt = 0; mt < 4; mt++)
#pragma unroll
                for (int np = 0; np < 2; np++) {
                    mma16816h(acc[mt][2 * np],     af[mt], bh[np][0], bh[np][1]);
                    mma16816h(acc[mt][2 * np + 1], af[mt], bh[np][2], bh[np][3]);
                }
            // pass 2: A * Blo
            if (NMATS == 3) {
#pragma unroll
                for (int mt = 0; mt < 4; mt++)
#pragma unroll
                    for (int np = 0; np < 2; np++) {
                        mma16816h(acc[mt][2 * np],     af[mt], bl[np][0], bl[np][1]);
                        mma16816h(acc[mt][2 * np + 1], af[mt], bl[np][2], bl[np][3]);
                    }
            }
        }
    }

    // epilogue
#pragma unroll
    for (int mt = 0; mt < 4; mt++)
#pragma unroll
        for (int nt = 0; nt < 4; nt++) {
            int col = n0 + wn * 32 + nt * 8 + (lane & 3) * 2;
            int r0 = m0 + wm * 64 + mt * 16 + (lane >> 2);
            float bx = 0.f, by = 0.f;
            if (BIAS) { bx = bias[col]; by = bias[col + 1]; }
            float2 v0 = make_float2(acc[mt][nt][0] + bx, acc[mt][nt][1] + by);
            float2 v1 = make_float2(acc[mt][nt][2] + bx, acc[mt][nt][3] + by);
            *reinterpret_cast<float2*>(&C[(size_t)r0 * N + col]) = v0;
            *reinterpret_cast<float2*>(&C[(size_t)(r0 + 8) * N + col]) = v1;
        }
}

// ---------------------------------------------------------------------------
// Prep: split qkv, RMSNorm(q,k), RoPE(q,k); emit fp16 Q (pre-scaled 1/8),
// fp16 K, fp16 V (all single) in [b*H+h][n][64] layout. Warp per (b,n,h).
// ---------------------------------------------------------------------------
__global__ __launch_bounds__(256) void prep_kernel(
    const float* __restrict__ qkv,
    const float* __restrict__ cosb, const float* __restrict__ sinb,
    const float* __restrict__ qw, const float* __restrict__ kw,
    __half* __restrict__ Qh, __half* __restrict__ Kh,
    __half* __restrict__ Vh)
{
    const int bn = blockIdx.x;
    const int h = (blockIdx.y << 3) | (threadIdx.x >> 5);
    const int l = threadIdx.x & 31;
    const int b = bn >> 11;
    const int n = bn & 2047;

    const float* base = qkv + (size_t)bn * QKVDIM + h * HD;
    float q1 = base[l],            q2 = base[l + 32];
    float k1 = base[CDIM + l],     k2 = base[CDIM + l + 32];
    float v1 = base[2 * CDIM + l], v2 = base[2 * CDIM + l + 32];

    float sq = q1 * q1 + q2 * q2;
    float sk = k1 * k1 + k2 * k2;
#pragma unroll
    for (int o = 16; o > 0; o >>= 1) {
        sq += __shfl_xor_sync(0xffffffffu, sq, o);
        sk += __shfl_xor_sync(0xffffffffu, sk, o);
    }
    float rq = rsqrtf(sq * (1.f / 64.f) + 1e-6f);
    float rk = rsqrtf(sk * (1.f / 64.f) + 1e-6f);
    q1 *= rq * qw[l]; q2 *= rq * qw[l + 32];
    k1 *= rk * kw[l]; k2 *= rk * kw[l + 32];

    float c1 = cosb[n * HD + l], c2 = cosb[n * HD + l + 32];
    float s1 = sinb[n * HD + l], s2 = sinb[n * HD + l + 32];

    size_t o = (((size_t)(b * NHEAD + h)) * NSEQ + n) * HD;
    Qh[o + l]      = __float2half_rn((q1 * c1 - q2 * s1) * 0.125f);
    Qh[o + l + 32] = __float2half_rn((q2 * c2 + q1 * s2) * 0.125f);
    Kh[o + l]      = __float2half_rn(k1 * c1 - k2 * s1);
    Kh[o + l + 32] = __float2half_rn(k2 * c2 + k1 * s2);
    Vh[o + l]      = __float2half_rn(v1);
    Vh[o + l + 32] = __float2half_rn(v2);
}

// ---------------------------------------------------------------------------
// Flash attention on fp16 HMMA. 256 threads, 128 q rows.
// S = q*k single-pass; O = p*v single-pass; P = exp(s)*2^-8 (exp-bit fold).
// NO online max (|s| <= 16 bound); out = o/l (2^-8 cancels), single fp16.
// SMEM: Q 16K | stage{Kh,Vh}x2 = 32K -> 48K total, 2 CTAs/SM.
// ---------------------------------------------------------------------------
#define FA_STAGE 16384
#define FA_SMEM (16384 + 2 * FA_STAGE)   // 49152

__global__ __launch_bounds__(256, 2) void flash_hmma(
    const __half* __restrict__ Qh, const __half* __restrict__ Kh,
    const __half* __restrict__ Vh, __half* __restrict__ Att)
{
    extern __shared__ __align__(128) char smc[];
    const unsigned sb = smem_u32(smc);
    const int t = threadIdx.x, lane = t & 31, w = t >> 5;
    const int bh = blockIdx.x, qt = blockIdx.y;
    const int b = bh >> 4, h = bh & 15;
    const int grp = lane >> 3, ri = lane & 7;

    const size_t qoff = ((size_t)bh * NSEQ + qt * 128) * HD;
    const size_t kvoff = (size_t)bh * NSEQ * HD;

    const __half* mats[2] = {Kh, Vh};

    auto issue = [&](int j, int s) {
        const unsigned stb = sb + 16384 + s * FA_STAGE;
#pragma unroll
        for (int m = 0; m < 2; m++) {
            const __half* g = mats[m] + kvoff + (size_t)(j * 64) * HD;
            const unsigned mb = stb + m * 8192;
#pragma unroll
            for (int i = 0; i < 2; i++) {
                int idx = i * 256 + t;
                int r = idx >> 3, ch = idx & 7;
                CP16(mb + swz(r, ch), g + (size_t)r * HD + ch * 8);
            }
        }
    };

    issue(0, 0);
    CP_COMMIT();

    // Q tile -> smem (swizzled)
#pragma unroll
    for (int i = 0; i < 4; i++) {
        int idx = i * 256 + t;
        int r = idx >> 3, ch = idx & 7;
        *reinterpret_cast<uint4*>(smc + swz(r, ch)) =
            *reinterpret_cast<const uint4*>(Qh + qoff + (size_t)r * HD + ch * 8);
    }
    __syncthreads();

    unsigned qf[4][4];
#pragma unroll
    for (int kt = 0; kt < 4; kt++) {
        int r = w * 16 + (grp & 1) * 8 + ri;
        int ch = kt * 2 + (grp >> 1);
        ldsm4(qf[kt], sb + swz(r, ch));
    }

    float o[8][4];
#pragma unroll
    for (int d = 0; d < 8; d++)
#pragma unroll
        for (int c = 0; c < 4; c++) o[d][c] = 0.f;
    float l0r = 0.f, l1r = 0.f;

    for (int j = 0; j < NSEQ / 64; j++) {
        CP_WAIT0();
        __syncthreads();
        if (j + 1 < NSEQ / 64) {
            issue(j + 1, (j + 1) & 1);
            CP_COMMIT();
        }
        const unsigned stb = sb + 16384 + (j & 1) * FA_STAGE;

        // ---- S = Q K^T (single pass) ----
        float s[8][4];
#pragma unroll
        for (int nt = 0; nt < 8; nt++)
#pragma unroll
            for (int c = 0; c < 4; c++) s[nt][c] = 0.f;

#pragma unroll
        for (int kt = 0; kt < 4; kt++) {
#pragma unroll
            for (int np = 0; np < 4; np++) {
                int r = np * 16 + ((grp >> 1) & 1) * 8 + ri;
                int ch = kt * 2 + (grp & 1);
                unsigned kf[4];
                ldsm4(kf, stb + swz(r, ch));
                mma16816h(s[2 * np],     qf[kt], kf[0], kf[1]);
                mma16816h(s[2 * np + 1], qf[kt], kf[2], kf[3]);
            }
        }

        // ---- softmax numerators, pre-scaled 2^-8 via exponent fold ----
        float ps0 = 0.f, ps1 = 0.f;
#pragma unroll
        for (int nt = 0; nt < 8; nt++) {
            s[nt][0] = fast_exp_p8(s[nt][0]);
            s[nt][1] = fast_exp_p8(s[nt][1]);
            s[nt][2] = fast_exp_p8(s[nt][2]);
            s[nt][3] = fast_exp_p8(s[nt][3]);
            ps0 += s[nt][0] + s[nt][1];
            ps1 += s[nt][2] + s[nt][3];
        }
        ps0 += __shfl_xor_sync(0xffffffffu, ps0, 1);
        ps0 += __shfl_xor_sync(0xffffffffu, ps0, 2);
        ps1 += __shfl_xor_sync(0xffffffffu, ps1, 1);
        ps1 += __shfl_xor_sync(0xffffffffu, ps1, 2);
        l0r += ps0;
        l1r += ps1;

        // ---- O += P V (single pass) ----
#pragma unroll
        for (int ct = 0; ct < 4; ct++) {
            unsigned ph[4];
            ph[0] = pack_h2(s[2 * ct][0],     s[2 * ct][1]);
            ph[1] = pack_h2(s[2 * ct][2],     s[2 * ct][3]);
            ph[2] = pack_h2(s[2 * ct + 1][0], s[2 * ct + 1][1]);
            ph[3] = pack_h2(s[2 * ct + 1][2], s[2 * ct + 1][3]);
#pragma unroll
            for (int dp = 0; dp < 4; dp++) {
                int r = ct * 16 + (lane & 15);
                int ch = dp * 2 + (lane >> 4);
                unsigned vf[4];
                ldsm4t(vf, stb + 8192 + swz(r, ch));
                mma16816h(o[2 * dp],     ph, vf[0], vf[1]);
                mma16816h(o[2 * dp + 1], ph, vf[2], vf[3]);
            }
        }
    }

    // ---- epilogue: o/l (2^-8 cancels) -> single fp16 att [B,N,C] ----
    const float inv0 = 1.0f / l0r, inv1 = 1.0f / l1r;
#pragma unroll
    for (int dt = 0; dt < 8; dt++) {
        int col = h * 64 + dt * 8 + (lane & 3) * 2;
        int r0 = qt * 128 + w * 16 + (lane >> 2);
        size_t i0 = ((size_t)b * NSEQ + r0) * CDIM + col;
        size_t i1 = ((size_t)b * NSEQ + r0 + 8) * CDIM + col;
        *reinterpret_cast<unsigned*>(&Att[i0]) =
            pack_h2(o[dt][0] * inv0, o[dt][1] * inv0);
        *reinterpret_cast<unsigned*>(&Att[i1]) =
            pack_h2(o[dt][2] * inv1, o[dt][3] * inv1);
    }
}

// ---------------------------------------------------------------------------
extern "C" void kernel_launch(void* const* d_in, const int* in_sizes, int n_in,
                              void* d_out, int out_size)
{
    const float* x      = (const float*)d_in[0];
    const float* cosb   = (const float*)d_in[1];
    const float* sinb   = (const float*)d_in[2];
    const float* w_qkv  = (const float*)d_in[3];
    const float* w_proj = (const float*)d_in[4];
    const float* b_proj = (const float*)d_in[5];
    const float* qw     = (const float*)d_in[6];
    const float* kw     = (const float*)d_in[7];
    float* out = (float*)d_out;

    float* qkv;
    __half *x16, *att16, *wqh, *wql, *wp16;
    __half *qh, *kh, *vh;
    cudaGetSymbolAddress((void**)&qkv, g_qkv);
    cudaGetSymbolAddress((void**)&x16, g_x16);
    cudaGetSymbolAddress((void**)&att16, g_att16);
    cudaGetSymbolAddress((void**)&wqh, g_wqkvhi);
    cudaGetSymbolAddress((void**)&wql, g_wqkvlo);
    cudaGetSymbolAddress((void**)&wp16, g_wproj16);
    cudaGetSymbolAddress((void**)&qh, g_qh);
    cudaGetSymbolAddress((void**)&kh, g_kh);
    cudaGetSymbolAddress((void**)&vh, g_vh);

    cudaFuncSetAttribute(gemm_hmma<false, 3>,
                         cudaFuncAttributeMaxDynamicSharedMemorySize, 3 * 49152);
    cudaFuncSetAttribute(gemm_hmma<true, 2>,
                         cudaFuncAttributeMaxDynamicSharedMemorySize, 3 * 32768);
    cudaFuncSetAttribute(flash_hmma,
                         cudaFuncAttributeMaxDynamicSharedMemorySize, FA_SMEM);

    // 0) splits: x, w_proj -> f16 single; w_qkv -> f16 hi/lo (one launch)
    split_all<<<(NX4 + NQ4 + NP4) / 256, 256>>>(
        x, w_qkv, w_proj, x16, wqh, wql, wp16);

    // 1) qkv = x @ w_qkv^T (fp16, 2-pass weights)
    gemm_hmma<false, 3><<<dim3(QKVDIM / 128, MROWS / 128), 256, 3 * 49152>>>(
        x16, wqh, wql, nullptr, qkv, QKVDIM);

    // 2) rmsnorm + rope -> fp16 Q(pre-scaled), K, V
    prep_kernel<<<dim3(MROWS, 2), 256>>>(qkv, cosb, sinb, qw, kw, qh, kh, vh);

    // 3) flash attention -> att single fp16
    flash_hmma<<<dim3(BHTOT, NSEQ / 128), 256, FA_SMEM>>>(qh, kh, vh, att16);

    // 4) out = att @ w_proj^T + b (fp16, single-pass weights)
    gemm_hmma<true, 2><<<dim3(CDIM / 128, MROWS / 128), 256, 3 * 32768>>>(
        att16, wp16, nullptr, b_proj, out, CDIM);
}

// round 13
// speedup vs baseline: 2.6046x; 1.2951x over previous
#include <cuda_runtime.h>
#include <cuda_fp16.h>
#include <math.h>

// Problem constants
#define B_SZ 4
#define NSEQ 2048
#define CDIM 1024
#define NHEAD 16
#define HD 64
#define MROWS 8192
#define QKVDIM 3072
#define BHTOT 64

// ---------------------------------------------------------------------------
// Static device scratch (allocation-free kernel_launch)
// ---------------------------------------------------------------------------
__device__ float g_qkv[MROWS * QKVDIM];
__device__ __half g_x16[MROWS * CDIM];            // x single fp16
__device__ __half g_att16[MROWS * CDIM];          // att single fp16
__device__ __half g_wqkv16[QKVDIM * CDIM];        // w_qkv single fp16
__device__ __half g_wproj16[CDIM * CDIM];         // w_proj single fp16
__device__ __half g_qh[BHTOT * NSEQ * HD];        // fp16 Q (pre-scaled 1/8)
__device__ __half g_kh[BHTOT * NSEQ * HD];        // fp16 K
__device__ __half g_vh[BHTOT * NSEQ * HD];        // fp16 V

// ---------------------------------------------------------------------------
// Helpers
// ---------------------------------------------------------------------------
__device__ __forceinline__ unsigned smem_u32(const void* p) {
    unsigned a;
    asm("{ .reg .u64 t; cvta.to.shared.u64 t, %1; cvt.u32.u64 %0, t; }"
        : "=r"(a) : "l"(p));
    return a;
}

__device__ __forceinline__ void ldsm4(unsigned* r, unsigned a) {
    asm volatile("ldmatrix.sync.aligned.m8n8.x4.shared.b16 {%0,%1,%2,%3}, [%4];"
        : "=r"(r[0]), "=r"(r[1]), "=r"(r[2]), "=r"(r[3]) : "r"(a));
}
__device__ __forceinline__ void ldsm4t(unsigned* r, unsigned a) {
    asm volatile("ldmatrix.sync.aligned.m8n8.x4.trans.shared.b16 {%0,%1,%2,%3}, [%4];"
        : "=r"(r[0]), "=r"(r[1]), "=r"(r[2]), "=r"(r[3]) : "r"(a));
}
// fp16 HMMA
__device__ __forceinline__ void mma16816h(float* d, const unsigned* a,
                                          unsigned b0, unsigned b1) {
    asm volatile(
        "mma.sync.aligned.m16n8k16.row.col.f32.f16.f16.f32 "
        "{%0,%1,%2,%3}, {%4,%5,%6,%7}, {%8,%9}, {%0,%1,%2,%3};"
        : "+f"(d[0]), "+f"(d[1]), "+f"(d[2]), "+f"(d[3])
        : "r"(a[0]), "r"(a[1]), "r"(a[2]), "r"(a[3]), "r"(b0), "r"(b1));
}

#define CP16(sa, g) \
    asm volatile("cp.async.cg.shared.global [%0], [%1], 16;" :: "r"(sa), "l"(g))
#define CP_COMMIT() asm volatile("cp.async.commit_group;")
#define CP_WAIT1()  asm volatile("cp.async.wait_group 1;")
#define CP_WAIT0()  asm volatile("cp.async.wait_group 0;")

// chunk swizzle: 128B rows, 8 x 16B chunks
__device__ __forceinline__ unsigned swz(int row, int chunk) {
    return (unsigned)(row * 128 + ((chunk ^ (row & 7)) * 16));
}

// FMA-only exp, result pre-scaled by 2^-8 (exponent-bit fold, exact).
// Inputs bounded |x| <= ~16.1 -> no clamp needed.
__device__ __forceinline__ float fast_exp_p8(float x) {
    float t = fmaf(x, 1.442695041f, 12582912.f);
    int ebits = (__float_as_int(t) << 23) - (8 << 23);
    float fi = t - 12582912.f;
    float f = fmaf(x, 1.442695041f, -fi);
    float p = 1.3333558e-3f;
    p = fmaf(p, f, 9.6181291e-3f);
    p = fmaf(p, f, 5.5504109e-2f);
    p = fmaf(p, f, 2.4022651e-1f);
    p = fmaf(p, f, 6.9314718e-1f);
    p = fmaf(p, f, 1.0f);
    return __int_as_float(__float_as_int(p) + ebits);
}

__device__ __forceinline__ unsigned pack_h2(float x, float y) {
    __half2 h = __floats2half2_rn(x, y);
    return *reinterpret_cast<unsigned*>(&h);
}

// ---------------------------------------------------------------------------
// One merged split kernel: x, w_qkv, w_proj -> single fp16
// ---------------------------------------------------------------------------
#define NX4 (MROWS * CDIM / 4)
#define NQ4 (QKVDIM * CDIM / 4)
#define NP4 (CDIM * CDIM / 4)

__global__ __launch_bounds__(256) void split_all(
    const float* __restrict__ x, const float* __restrict__ wq,
    const float* __restrict__ wp,
    __half* __restrict__ x16, __half* __restrict__ wq16,
    __half* __restrict__ wp16)
{
    int i = blockIdx.x * 256 + threadIdx.x;
    const float* src;
    __half* dst;
    if (i < NX4)            { src = x;  dst = x16; }
    else if (i < NX4 + NQ4) { i -= NX4; src = wq; dst = wq16; }
    else                    { i -= NX4 + NQ4; src = wp; dst = wp16; }
    float4 v = reinterpret_cast<const float4*>(src)[i];
    reinterpret_cast<unsigned*>(dst)[2 * i]     = pack_h2(v.x, v.y);
    reinterpret_cast<unsigned*>(dst)[2 * i + 1] = pack_h2(v.z, v.w);
}

// ---------------------------------------------------------------------------
// fp16 HMMA GEMM (NT): C[m,n] = sum_k A[m,k]*B[n,k] (+bias). Single-pass.
// 128x128 tile, BK=64 stage {A 16K | B 16K} = 32KB x 3 stages -> 2 CTAs/SM.
// ---------------------------------------------------------------------------
#define GS_STAGE 32768
#define GEMM_SMEM (3 * GS_STAGE)     // 98304
#define NSTAGES 16                   // K=1024 / 64

template <bool BIAS>
__global__ __launch_bounds__(256) void gemm_hmma(
    const __half* __restrict__ A, const __half* __restrict__ B,
    const float* __restrict__ bias, float* __restrict__ C, int N)
{
    extern __shared__ __align__(128) char smc[];
    const unsigned sb = smem_u32(smc);
    const int t = threadIdx.x, lane = t & 31, wid = t >> 5;
    const int wm = wid & 1, wn = wid >> 1;
    const int m0 = blockIdx.y * 128, n0 = blockIdx.x * 128;
    const int K = 1024;
    const int grp = lane >> 3, ri = lane & 7;

    float acc[4][4][4];
#pragma unroll
    for (int a = 0; a < 4; a++)
#pragma unroll
        for (int b = 0; b < 4; b++)
#pragma unroll
            for (int c = 0; c < 4; c++) acc[a][b][c] = 0.f;

    const __half* srcs[2] = { A + (size_t)m0 * K, B + (size_t)n0 * K };

    auto issue = [&](int s, int buf) {
        const int k0 = s * 64;
        const unsigned stb = sb + buf * GS_STAGE;
#pragma unroll
        for (int m = 0; m < 2; m++) {
            const unsigned mb = stb + m * 16384;
            const __half* g = srcs[m] + k0;
#pragma unroll
            for (int i = 0; i < 4; i++) {
                int idx = i * 256 + t;
                int r = idx >> 3, ch = idx & 7;
                CP16(mb + swz(r, ch), g + (size_t)r * K + ch * 8);
            }
        }
    };

    issue(0, 0); CP_COMMIT();
    issue(1, 1); CP_COMMIT();

    for (int it = 0; it < NSTAGES; it++) {
        if (it == NSTAGES - 1) { CP_WAIT0(); } else { CP_WAIT1(); }
        __syncthreads();
        if (it + 2 < NSTAGES) {
            issue(it + 2, (it + 2) % 3);
            CP_COMMIT();
        }
        const unsigned ab = sb + (it % 3) * GS_STAGE;
        const unsigned bb = ab + 16384;
#pragma unroll
        for (int k4 = 0; k4 < 4; k4++) {
            unsigned af[4][4], bf[2][4];
#pragma unroll
            for (int mt = 0; mt < 4; mt++) {
                int r = wm * 64 + mt * 16 + (grp & 1) * 8 + ri;
                int ch = k4 * 2 + (grp >> 1);
                ldsm4(af[mt], ab + swz(r, ch));
            }
#pragma unroll
            for (int np = 0; np < 2; np++) {
                int r = wn * 32 + np * 16 + ((grp >> 1) & 1) * 8 + ri;
                int ch = k4 * 2 + (grp & 1);
                ldsm4(bf[np], bb + swz(r, ch));
            }
#pragma unroll
            for (int mt = 0; mt < 4; mt++)
#pragma unroll
                for (int np = 0; np < 2; np++) {
                    mma16816h(acc[mt][2 * np],     af[mt], bf[np][0], bf[np][1]);
                    mma16816h(acc[mt][2 * np + 1], af[mt], bf[np][2], bf[np][3]);
                }
        }
    }

    // epilogue
#pragma unroll
    for (int mt = 0; mt < 4; mt++)
#pragma unroll
        for (int nt = 0; nt < 4; nt++) {
            int col = n0 + wn * 32 + nt * 8 + (lane & 3) * 2;
            int r0 = m0 + wm * 64 + mt * 16 + (lane >> 2);
            float bx = 0.f, by = 0.f;
            if (BIAS) { bx = bias[col]; by = bias[col + 1]; }
            float2 v0 = make_float2(acc[mt][nt][0] + bx, acc[mt][nt][1] + by);
            float2 v1 = make_float2(acc[mt][nt][2] + bx, acc[mt][nt][3] + by);
            *reinterpret_cast<float2*>(&C[(size_t)r0 * N + col]) = v0;
            *reinterpret_cast<float2*>(&C[(size_t)(r0 + 8) * N + col]) = v1;
        }
}

// ---------------------------------------------------------------------------
// Prep: split qkv, RMSNorm(q,k), RoPE(q,k); emit fp16 Q (pre-scaled 1/8),
// fp16 K, fp16 V in [b*H+h][n][64] layout. Warp per (b,n,h).
// ---------------------------------------------------------------------------
__global__ __launch_bounds__(256) void prep_kernel(
    const float* __restrict__ qkv,
    const float* __restrict__ cosb, const float* __restrict__ sinb,
    const float* __restrict__ qw, const float* __restrict__ kw,
    __half* __restrict__ Qh, __half* __restrict__ Kh,
    __half* __restrict__ Vh)
{
    const int bn = blockIdx.x;
    const int h = (blockIdx.y << 3) | (threadIdx.x >> 5);
    const int l = threadIdx.x & 31;
    const int b = bn >> 11;
    const int n = bn & 2047;

    const float* base = qkv + (size_t)bn * QKVDIM + h * HD;
    float q1 = base[l],            q2 = base[l + 32];
    float k1 = base[CDIM + l],     k2 = base[CDIM + l + 32];
    float v1 = base[2 * CDIM + l], v2 = base[2 * CDIM + l + 32];

    float sq = q1 * q1 + q2 * q2;
    float sk = k1 * k1 + k2 * k2;
#pragma unroll
    for (int o = 16; o > 0; o >>= 1) {
        sq += __shfl_xor_sync(0xffffffffu, sq, o);
        sk += __shfl_xor_sync(0xffffffffu, sk, o);
    }
    float rq = rsqrtf(sq * (1.f / 64.f) + 1e-6f);
    float rk = rsqrtf(sk * (1.f / 64.f) + 1e-6f);
    q1 *= rq * qw[l]; q2 *= rq * qw[l + 32];
    k1 *= rk * kw[l]; k2 *= rk * kw[l + 32];

    float c1 = cosb[n * HD + l], c2 = cosb[n * HD + l + 32];
    float s1 = sinb[n * HD + l], s2 = sinb[n * HD + l + 32];

    size_t o = (((size_t)(b * NHEAD + h)) * NSEQ + n) * HD;
    Qh[o + l]      = __float2half_rn((q1 * c1 - q2 * s1) * 0.125f);
    Qh[o + l + 32] = __float2half_rn((q2 * c2 + q1 * s2) * 0.125f);
    Kh[o + l]      = __float2half_rn(k1 * c1 - k2 * s1);
    Kh[o + l + 32] = __float2half_rn(k2 * c2 + k1 * s2);
    Vh[o + l]      = __float2half_rn(v1);
    Vh[o + l + 32] = __float2half_rn(v2);
}

// ---------------------------------------------------------------------------
// Flash attention on fp16 HMMA. 256 threads, 128 q rows.
// S = q*k; P = exp(s)*2^-8 (exp-bit fold); O = p*v; l = P @ ones via MMA
// (row sums on the tensor pipe — no shuffle/FADD reduction).
// NO online max (|s| <= 16 bound); out = o/l (2^-8 cancels), single fp16.
// SMEM: Q 16K | stage{Kh,Vh}x2 = 32K | ones 512B, 2 CTAs/SM.
// ---------------------------------------------------------------------------
#define FA_STAGE 16384
#define FA_SMEM (16384 + 2 * FA_STAGE + 512)   // 49664

__global__ __launch_bounds__(256, 2) void flash_hmma(
    const __half* __restrict__ Qh, const __half* __restrict__ Kh,
    const __half* __restrict__ Vh, __half* __restrict__ Att)
{
    extern __shared__ __align__(128) char smc[];
    const unsigned sb = smem_u32(smc);
    const unsigned ob = sb + 16384 + 2 * FA_STAGE;   // ones tile (512B)
    const int t = threadIdx.x, lane = t & 31, w = t >> 5;
    const int bh = blockIdx.x, qt = blockIdx.y;
    const int b = bh >> 4, h = bh & 15;
    const int grp = lane >> 3, ri = lane & 7;

    const size_t qoff = ((size_t)bh * NSEQ + qt * 128) * HD;
    const size_t kvoff = (size_t)bh * NSEQ * HD;

    const __half* mats[2] = {Kh, Vh};

    auto issue = [&](int j, int s) {
        const unsigned stb = sb + 16384 + s * FA_STAGE;
#pragma unroll
        for (int m = 0; m < 2; m++) {
            const __half* g = mats[m] + kvoff + (size_t)(j * 64) * HD;
            const unsigned mb = stb + m * 8192;
#pragma unroll
            for (int i = 0; i < 2; i++) {
                int idx = i * 256 + t;
                int r = idx >> 3, ch = idx & 7;
                CP16(mb + swz(r, ch), g + (size_t)r * HD + ch * 8);
            }
        }
    };

    issue(0, 0);
    CP_COMMIT();

    // Q tile -> smem (swizzled); ones tile init
#pragma unroll
    for (int i = 0; i < 4; i++) {
        int idx = i * 256 + t;
        int r = idx >> 3, ch = idx & 7;
        *reinterpret_cast<uint4*>(smc + swz(r, ch)) =
            *reinterpret_cast<const uint4*>(Qh + qoff + (size_t)r * HD + ch * 8);
    }
    if (t < 128)
        *reinterpret_cast<unsigned*>(smc + (16384 + 2 * FA_STAGE) + t * 4)
            = 0x3C003C00u;   // half2(1, 1)
    __syncthreads();

    unsigned qf[4][4];
#pragma unroll
    for (int kt = 0; kt < 4; kt++) {
        int r = w * 16 + (grp & 1) * 8 + ri;
        int ch = kt * 2 + (grp >> 1);
        ldsm4(qf[kt], sb + swz(r, ch));
    }
    // ones B-frag (k16 x n8, all 1.0) — loaded once
    unsigned of[4];
    ldsm4t(of, ob + (lane & 15) * 32);

    float o[8][4], o9[4];
#pragma unroll
    for (int d = 0; d < 8; d++)
#pragma unroll
        for (int c = 0; c < 4; c++) o[d][c] = 0.f;
#pragma unroll
    for (int c = 0; c < 4; c++) o9[c] = 0.f;

    for (int j = 0; j < NSEQ / 64; j++) {
        CP_WAIT0();
        __syncthreads();
        if (j + 1 < NSEQ / 64) {
            issue(j + 1, (j + 1) & 1);
            CP_COMMIT();
        }
        const unsigned stb = sb + 16384 + (j & 1) * FA_STAGE;

        // ---- S = Q K^T ----
        float s[8][4];
#pragma unroll
        for (int nt = 0; nt < 8; nt++)
#pragma unroll
            for (int c = 0; c < 4; c++) s[nt][c] = 0.f;

#pragma unroll
        for (int kt = 0; kt < 4; kt++) {
#pragma unroll
            for (int np = 0; np < 4; np++) {
                int r = np * 16 + ((grp >> 1) & 1) * 8 + ri;
                int ch = kt * 2 + (grp & 1);
                unsigned kf[4];
                ldsm4(kf, stb + swz(r, ch));
                mma16816h(s[2 * np],     qf[kt], kf[0], kf[1]);
                mma16816h(s[2 * np + 1], qf[kt], kf[2], kf[3]);
            }
        }

        // ---- P = exp(s) * 2^-8; O += P V; l += P @ ones ----
#pragma unroll
        for (int ct = 0; ct < 4; ct++) {
            unsigned ph[4];
            ph[0] = pack_h2(fast_exp_p8(s[2 * ct][0]),
                            fast_exp_p8(s[2 * ct][1]));
            ph[1] = pack_h2(fast_exp_p8(s[2 * ct][2]),
                            fast_exp_p8(s[2 * ct][3]));
            ph[2] = pack_h2(fast_exp_p8(s[2 * ct + 1][0]),
                            fast_exp_p8(s[2 * ct + 1][1]));
            ph[3] = pack_h2(fast_exp_p8(s[2 * ct + 1][2]),
                            fast_exp_p8(s[2 * ct + 1][3]));
            mma16816h(o9, ph, of[0], of[1]);   // row sums -> l
#pragma unroll
            for (int dp = 0; dp < 4; dp++) {
                int r = ct * 16 + (lane & 15);
                int ch = dp * 2 + (lane >> 4);
                unsigned vf[4];
                ldsm4t(vf, stb + 8192 + swz(r, ch));
                mma16816h(o[2 * dp],     ph, vf[0], vf[1]);
                mma16816h(o[2 * dp + 1], ph, vf[2], vf[3]);
            }
        }
    }

    // ---- epilogue: o/l (2^-8 cancels) -> single fp16 att [B,N,C] ----
    const float inv0 = 1.0f / o9[0], inv1 = 1.0f / o9[2];
#pragma unroll
    for (int dt = 0; dt < 8; dt++) {
        int col = h * 64 + dt * 8 + (lane & 3) * 2;
        int r0 = qt * 128 + w * 16 + (lane >> 2);
        size_t i0 = ((size_t)b * NSEQ + r0) * CDIM + col;
        size_t i1 = ((size_t)b * NSEQ + r0 + 8) * CDIM + col;
        *reinterpret_cast<unsigned*>(&Att[i0]) =
            pack_h2(o[dt][0] * inv0, o[dt][1] * inv0);
        *reinterpret_cast<unsigned*>(&Att[i1]) =
            pack_h2(o[dt][2] * inv1, o[dt][3] * inv1);
    }
}

// ---------------------------------------------------------------------------
extern "C" void kernel_launch(void* const* d_in, const int* in_sizes, int n_in,
                              void* d_out, int out_size)
{
    const float* x      = (const float*)d_in[0];
    const float* cosb   = (const float*)d_in[1];
    const float* sinb   = (const float*)d_in[2];
    const float* w_qkv  = (const float*)d_in[3];
    const float* w_proj = (const float*)d_in[4];
    const float* b_proj = (const float*)d_in[5];
    const float* qw     = (const float*)d_in[6];
    const float* kw     = (const float*)d_in[7];
    float* out = (float*)d_out;

    float* qkv;
    __half *x16, *att16, *wq16, *wp16;
    __half *qh, *kh, *vh;
    cudaGetSymbolAddress((void**)&qkv, g_qkv);
    cudaGetSymbolAddress((void**)&x16, g_x16);
    cudaGetSymbolAddress((void**)&att16, g_att16);
    cudaGetSymbolAddress((void**)&wq16, g_wqkv16);
    cudaGetSymbolAddress((void**)&wp16, g_wproj16);
    cudaGetSymbolAddress((void**)&qh, g_qh);
    cudaGetSymbolAddress((void**)&kh, g_kh);
    cudaGetSymbolAddress((void**)&vh, g_vh);

    cudaFuncSetAttribute(gemm_hmma<false>,
                         cudaFuncAttributeMaxDynamicSharedMemorySize, GEMM_SMEM);
    cudaFuncSetAttribute(gemm_hmma<true>,
                         cudaFuncAttributeMaxDynamicSharedMemorySize, GEMM_SMEM);
    cudaFuncSetAttribute(flash_hmma,
                         cudaFuncAttributeMaxDynamicSharedMemorySize, FA_SMEM);

    // 0) splits: x, w_qkv, w_proj -> single fp16 (one launch)
    split_all<<<(NX4 + NQ4 + NP4) / 256, 256>>>(
        x, w_qkv, w_proj, x16, wq16, wp16);

    // 1) qkv = x @ w_qkv^T (fp16 single-pass)
    gemm_hmma<false><<<dim3(QKVDIM / 128, MROWS / 128), 256, GEMM_SMEM>>>(
        x16, wq16, nullptr, qkv, QKVDIM);

    // 2) rmsnorm + rope -> fp16 Q(pre-scaled), K, V
    prep_kernel<<<dim3(MROWS, 2), 256>>>(qkv, cosb, sinb, qw, kw, qh, kh, vh);

    // 3) flash attention -> att single fp16
    flash_hmma<<<dim3(BHTOT, NSEQ / 128), 256, FA_SMEM>>>(qh, kh, vh, att16);

    // 4) out = att @ w_proj^T + b (fp16 single-pass)
    gemm_hmma<true><<<dim3(CDIM / 128, MROWS / 128), 256, GEMM_SMEM>>>(
        att16, wp16, b_proj, out, CDIM);
}

// round 14
// speedup vs baseline: 2.6505x; 1.0177x over previous
#include <cuda_runtime.h>
#include <cuda_fp16.h>
#include <math.h>

// Problem constants
#define B_SZ 4
#define NSEQ 2048
#define CDIM 1024
#define NHEAD 16
#define HD 64
#define MROWS 8192
#define QKVDIM 3072
#define BHTOT 64

// ---------------------------------------------------------------------------
// Static device scratch (allocation-free kernel_launch)
// ---------------------------------------------------------------------------
__device__ __half g_qkv16[MROWS * QKVDIM];        // fp16 qkv intermediate
__device__ __half g_x16[MROWS * CDIM];            // x single fp16
__device__ __half g_att16[MROWS * CDIM];          // att single fp16
__device__ __half g_wqkv16[QKVDIM * CDIM];        // w_qkv single fp16
__device__ __half g_wproj16[CDIM * CDIM];         // w_proj single fp16
__device__ __half g_qh[BHTOT * NSEQ * HD];        // fp16 Q (pre-scaled 1/8)
__device__ __half g_kh[BHTOT * NSEQ * HD];        // fp16 K
__device__ __half g_vh[BHTOT * NSEQ * HD];        // fp16 V

// ---------------------------------------------------------------------------
// Helpers
// ---------------------------------------------------------------------------
__device__ __forceinline__ unsigned smem_u32(const void* p) {
    unsigned a;
    asm("{ .reg .u64 t; cvta.to.shared.u64 t, %1; cvt.u32.u64 %0, t; }"
        : "=r"(a) : "l"(p));
    return a;
}

__device__ __forceinline__ void ldsm4(unsigned* r, unsigned a) {
    asm volatile("ldmatrix.sync.aligned.m8n8.x4.shared.b16 {%0,%1,%2,%3}, [%4];"
        : "=r"(r[0]), "=r"(r[1]), "=r"(r[2]), "=r"(r[3]) : "r"(a));
}
__device__ __forceinline__ void ldsm4t(unsigned* r, unsigned a) {
    asm volatile("ldmatrix.sync.aligned.m8n8.x4.trans.shared.b16 {%0,%1,%2,%3}, [%4];"
        : "=r"(r[0]), "=r"(r[1]), "=r"(r[2]), "=r"(r[3]) : "r"(a));
}
// fp16 HMMA
__device__ __forceinline__ void mma16816h(float* d, const unsigned* a,
                                          unsigned b0, unsigned b1) {
    asm volatile(
        "mma.sync.aligned.m16n8k16.row.col.f32.f16.f16.f32 "
        "{%0,%1,%2,%3}, {%4,%5,%6,%7}, {%8,%9}, {%0,%1,%2,%3};"
        : "+f"(d[0]), "+f"(d[1]), "+f"(d[2]), "+f"(d[3])
        : "r"(a[0]), "r"(a[1]), "r"(a[2]), "r"(a[3]), "r"(b0), "r"(b1));
}

#define CP16(sa, g) \
    asm volatile("cp.async.cg.shared.global [%0], [%1], 16;" :: "r"(sa), "l"(g))
#define CP_COMMIT() asm volatile("cp.async.commit_group;")
#define CP_WAIT1()  asm volatile("cp.async.wait_group 1;")
#define CP_WAIT0()  asm volatile("cp.async.wait_group 0;")

// chunk swizzle: 128B rows, 8 x 16B chunks
__device__ __forceinline__ unsigned swz(int row, int chunk) {
    return (unsigned)(row * 128 + ((chunk ^ (row & 7)) * 16));
}

// FMA-only exp, result pre-scaled by 2^-8 (exponent-bit fold, exact).
// Inputs bounded |x| <= ~16.1 -> no clamp needed.
__device__ __forceinline__ float fast_exp_p8(float x) {
    float t = fmaf(x, 1.442695041f, 12582912.f);
    int ebits = (__float_as_int(t) << 23) - (8 << 23);
    float fi = t - 12582912.f;
    float f = fmaf(x, 1.442695041f, -fi);
    float p = 1.3333558e-3f;
    p = fmaf(p, f, 9.6181291e-3f);
    p = fmaf(p, f, 5.5504109e-2f);
    p = fmaf(p, f, 2.4022651e-1f);
    p = fmaf(p, f, 6.9314718e-1f);
    p = fmaf(p, f, 1.0f);
    return __int_as_float(__float_as_int(p) + ebits);
}

__device__ __forceinline__ unsigned pack_h2(float x, float y) {
    __half2 h = __floats2half2_rn(x, y);
    return *reinterpret_cast<unsigned*>(&h);
}

// ---------------------------------------------------------------------------
// One merged split kernel: x, w_qkv, w_proj -> single fp16
// ---------------------------------------------------------------------------
#define NX4 (MROWS * CDIM / 4)
#define NQ4 (QKVDIM * CDIM / 4)
#define NP4 (CDIM * CDIM / 4)

__global__ __launch_bounds__(256) void split_all(
    const float* __restrict__ x, const float* __restrict__ wq,
    const float* __restrict__ wp,
    __half* __restrict__ x16, __half* __restrict__ wq16,
    __half* __restrict__ wp16)
{
    int i = blockIdx.x * 256 + threadIdx.x;
    const float* src;
    __half* dst;
    if (i < NX4)            { src = x;  dst = x16; }
    else if (i < NX4 + NQ4) { i -= NX4; src = wq; dst = wq16; }
    else                    { i -= NX4 + NQ4; src = wp; dst = wp16; }
    float4 v = reinterpret_cast<const float4*>(src)[i];
    reinterpret_cast<unsigned*>(dst)[2 * i]     = pack_h2(v.x, v.y);
    reinterpret_cast<unsigned*>(dst)[2 * i + 1] = pack_h2(v.z, v.w);
}

// ---------------------------------------------------------------------------
// fp16 HMMA GEMM (NT): C[m,n] = sum_k A[m,k]*B[n,k] (+bias). Single-pass.
// 128x128 tile, BK=64 stage {A 16K | B 16K} = 32KB x 3 stages -> 2 CTAs/SM.
// HALFOUT: store fp16 (half2 packs); else fp32.
// ---------------------------------------------------------------------------
#define GS_STAGE 32768
#define GEMM_SMEM (3 * GS_STAGE)     // 98304
#define NSTAGES 16                   // K=1024 / 64

template <bool BIAS, bool HALFOUT>
__global__ __launch_bounds__(256) void gemm_hmma(
    const __half* __restrict__ A, const __half* __restrict__ B,
    const float* __restrict__ bias, void* __restrict__ Cv, int N)
{
    extern __shared__ __align__(128) char smc[];
    const unsigned sb = smem_u32(smc);
    const int t = threadIdx.x, lane = t & 31, wid = t >> 5;
    const int wm = wid & 1, wn = wid >> 1;
    const int m0 = blockIdx.y * 128, n0 = blockIdx.x * 128;
    const int K = 1024;
    const int grp = lane >> 3, ri = lane & 7;

    float acc[4][4][4];
#pragma unroll
    for (int a = 0; a < 4; a++)
#pragma unroll
        for (int b = 0; b < 4; b++)
#pragma unroll
            for (int c = 0; c < 4; c++) acc[a][b][c] = 0.f;

    const __half* srcs[2] = { A + (size_t)m0 * K, B + (size_t)n0 * K };

    auto issue = [&](int s, int buf) {
        const int k0 = s * 64;
        const unsigned stb = sb + buf * GS_STAGE;
#pragma unroll
        for (int m = 0; m < 2; m++) {
            const unsigned mb = stb + m * 16384;
            const __half* g = srcs[m] + k0;
#pragma unroll
            for (int i = 0; i < 4; i++) {
                int idx = i * 256 + t;
                int r = idx >> 3, ch = idx & 7;
                CP16(mb + swz(r, ch), g + (size_t)r * K + ch * 8);
            }
        }
    };

    issue(0, 0); CP_COMMIT();
    issue(1, 1); CP_COMMIT();

    for (int it = 0; it < NSTAGES; it++) {
        if (it == NSTAGES - 1) { CP_WAIT0(); } else { CP_WAIT1(); }
        __syncthreads();
        if (it + 2 < NSTAGES) {
            issue(it + 2, (it + 2) % 3);
            CP_COMMIT();
        }
        const unsigned ab = sb + (it % 3) * GS_STAGE;
        const unsigned bb = ab + 16384;
#pragma unroll
        for (int k4 = 0; k4 < 4; k4++) {
            unsigned af[4][4], bf[2][4];
#pragma unroll
            for (int mt = 0; mt < 4; mt++) {
                int r = wm * 64 + mt * 16 + (grp & 1) * 8 + ri;
                int ch = k4 * 2 + (grp >> 1);
                ldsm4(af[mt], ab + swz(r, ch));
            }
#pragma unroll
            for (int np = 0; np < 2; np++) {
                int r = wn * 32 + np * 16 + ((grp >> 1) & 1) * 8 + ri;
                int ch = k4 * 2 + (grp & 1);
                ldsm4(bf[np], bb + swz(r, ch));
            }
#pragma unroll
            for (int mt = 0; mt < 4; mt++)
#pragma unroll
                for (int np = 0; np < 2; np++) {
                    mma16816h(acc[mt][2 * np],     af[mt], bf[np][0], bf[np][1]);
                    mma16816h(acc[mt][2 * np + 1], af[mt], bf[np][2], bf[np][3]);
                }
        }
    }

    // epilogue
#pragma unroll
    for (int mt = 0; mt < 4; mt++)
#pragma unroll
        for (int nt = 0; nt < 4; nt++) {
            int col = n0 + wn * 32 + nt * 8 + (lane & 3) * 2;
            int r0 = m0 + wm * 64 + mt * 16 + (lane >> 2);
            float bx = 0.f, by = 0.f;
            if (BIAS) { bx = bias[col]; by = bias[col + 1]; }
            float a0 = acc[mt][nt][0] + bx, a1 = acc[mt][nt][1] + by;
            float a2 = acc[mt][nt][2] + bx, a3 = acc[mt][nt][3] + by;
            if (HALFOUT) {
                __half* C = (__half*)Cv;
                *reinterpret_cast<unsigned*>(&C[(size_t)r0 * N + col]) =
                    pack_h2(a0, a1);
                *reinterpret_cast<unsigned*>(&C[(size_t)(r0 + 8) * N + col]) =
                    pack_h2(a2, a3);
            } else {
                float* C = (float*)Cv;
                *reinterpret_cast<float2*>(&C[(size_t)r0 * N + col]) =
                    make_float2(a0, a1);
                *reinterpret_cast<float2*>(&C[(size_t)(r0 + 8) * N + col]) =
                    make_float2(a2, a3);
            }
        }
}

// ---------------------------------------------------------------------------
// Prep: read fp16 qkv, RMSNorm(q,k), RoPE(q,k); emit fp16 Q (pre-scaled 1/8),
// fp16 K, fp16 V in [b*H+h][n][64] layout. Warp per (b,n,h).
// ---------------------------------------------------------------------------
__global__ __launch_bounds__(256) void prep_kernel(
    const __half* __restrict__ qkv,
    const float* __restrict__ cosb, const float* __restrict__ sinb,
    const float* __restrict__ qw, const float* __restrict__ kw,
    __half* __restrict__ Qh, __half* __restrict__ Kh,
    __half* __restrict__ Vh)
{
    const int bn = blockIdx.x;
    const int h = (blockIdx.y << 3) | (threadIdx.x >> 5);
    const int l = threadIdx.x & 31;
    const int b = bn >> 11;
    const int n = bn & 2047;

    const __half* base = qkv + (size_t)bn * QKVDIM + h * HD;
    float q1 = __half2float(base[l]);
    float q2 = __half2float(base[l + 32]);
    float k1 = __half2float(base[CDIM + l]);
    float k2 = __half2float(base[CDIM + l + 32]);
    float v1 = __half2float(base[2 * CDIM + l]);
    float v2 = __half2float(base[2 * CDIM + l + 32]);

    float sq = q1 * q1 + q2 * q2;
    float sk = k1 * k1 + k2 * k2;
#pragma unroll
    for (int o = 16; o > 0; o >>= 1) {
        sq += __shfl_xor_sync(0xffffffffu, sq, o);
        sk += __shfl_xor_sync(0xffffffffu, sk, o);
    }
    float rq = rsqrtf(sq * (1.f / 64.f) + 1e-6f);
    float rk = rsqrtf(sk * (1.f / 64.f) + 1e-6f);
    q1 *= rq * qw[l]; q2 *= rq * qw[l + 32];
    k1 *= rk * kw[l]; k2 *= rk * kw[l + 32];

    float c1 = cosb[n * HD + l], c2 = cosb[n * HD + l + 32];
    float s1 = sinb[n * HD + l], s2 = sinb[n * HD + l + 32];

    size_t o = (((size_t)(b * NHEAD + h)) * NSEQ + n) * HD;
    Qh[o + l]      = __float2half_rn((q1 * c1 - q2 * s1) * 0.125f);
    Qh[o + l + 32] = __float2half_rn((q2 * c2 + q1 * s2) * 0.125f);
    Kh[o + l]      = __float2half_rn(k1 * c1 - k2 * s1);
    Kh[o + l + 32] = __float2half_rn(k2 * c2 + k1 * s2);
    Vh[o + l]      = __float2half_rn(v1);
    Vh[o + l + 32] = __float2half_rn(v2);
}

// ---------------------------------------------------------------------------
// Flash attention on fp16 HMMA. 256 threads, 128 q rows, KV tiles of 128.
// Fused per-ct pipeline: S MMAs (16 kv rows) -> exp -> l-MMA -> PV MMAs.
// NO online max (|s| <= 16 bound); P = exp(s)*2^-8 (exp-bit fold);
// out = o/l (2^-8 cancels), single fp16.
// SMEM: Q 16K | stage{Kh 16K,Vh 16K}x2 = 64K | ones 512B -> 2 CTAs/SM.
// ---------------------------------------------------------------------------
#define FA_STAGE 32768
#define FA_SMEM (16384 + 2 * FA_STAGE + 512)   // 82432

__global__ __launch_bounds__(256, 2) void flash_hmma(
    const __half* __restrict__ Qh, const __half* __restrict__ Kh,
    const __half* __restrict__ Vh, __half* __restrict__ Att)
{
    extern __shared__ __align__(128) char smc[];
    const unsigned sb = smem_u32(smc);
    const unsigned ob = sb + 16384 + 2 * FA_STAGE;   // ones tile (512B)
    const int t = threadIdx.x, lane = t & 31, w = t >> 5;
    const int bh = blockIdx.x, qt = blockIdx.y;
    const int b = bh >> 4, h = bh & 15;
    const int grp = lane >> 3, ri = lane & 7;

    const size_t qoff = ((size_t)bh * NSEQ + qt * 128) * HD;
    const size_t kvoff = (size_t)bh * NSEQ * HD;

    const __half* mats[2] = {Kh, Vh};

    auto issue = [&](int j, int s) {
        const unsigned stb = sb + 16384 + s * FA_STAGE;
#pragma unroll
        for (int m = 0; m < 2; m++) {
            const __half* g = mats[m] + kvoff + (size_t)(j * 128) * HD;
            const unsigned mb = stb + m * 16384;
#pragma unroll
            for (int i = 0; i < 4; i++) {
                int idx = i * 256 + t;
                int r = idx >> 3, ch = idx & 7;
                CP16(mb + swz(r, ch), g + (size_t)r * HD + ch * 8);
            }
        }
    };

    issue(0, 0);
    CP_COMMIT();

    // Q tile -> smem (swizzled); ones tile init
#pragma unroll
    for (int i = 0; i < 4; i++) {
        int idx = i * 256 + t;
        int r = idx >> 3, ch = idx & 7;
        *reinterpret_cast<uint4*>(smc + swz(r, ch)) =
            *reinterpret_cast<const uint4*>(Qh + qoff + (size_t)r * HD + ch * 8);
    }
    if (t < 128)
        *reinterpret_cast<unsigned*>(smc + (16384 + 2 * FA_STAGE) + t * 4)
            = 0x3C003C00u;   // half2(1, 1)
    __syncthreads();

    unsigned qf[4][4];
#pragma unroll
    for (int kt = 0; kt < 4; kt++) {
        int r = w * 16 + (grp & 1) * 8 + ri;
        int ch = kt * 2 + (grp >> 1);
        ldsm4(qf[kt], sb + swz(r, ch));
    }
    // ones B-frag (k16 x n8, all 1.0) — loaded once
    unsigned of[4];
    ldsm4t(of, ob + (lane & 15) * 32);

    float o[8][4], o9[4];
#pragma unroll
    for (int d = 0; d < 8; d++)
#pragma unroll
        for (int c = 0; c < 4; c++) o[d][c] = 0.f;
#pragma unroll
    for (int c = 0; c < 4; c++) o9[c] = 0.f;

    for (int j = 0; j < NSEQ / 128; j++) {
        CP_WAIT0();
        __syncthreads();
        if (j + 1 < NSEQ / 128) {
            issue(j + 1, (j + 1) & 1);
            CP_COMMIT();
        }
        const unsigned stb = sb + 16384 + (j & 1) * FA_STAGE;

        // fused per-ct: S (16 kv rows) -> exp -> l-MMA -> PV
#pragma unroll
        for (int ct = 0; ct < 8; ct++) {
            float s2[2][4];
#pragma unroll
            for (int c = 0; c < 4; c++) { s2[0][c] = 0.f; s2[1][c] = 0.f; }
#pragma unroll
            for (int kt = 0; kt < 4; kt++) {
                int r = ct * 16 + ((grp >> 1) & 1) * 8 + ri;
                int ch = kt * 2 + (grp & 1);
                unsigned kf[4];
                ldsm4(kf, stb + swz(r, ch));
                mma16816h(s2[0], qf[kt], kf[0], kf[1]);
                mma16816h(s2[1], qf[kt], kf[2], kf[3]);
            }
            unsigned ph[4];
            ph[0] = pack_h2(fast_exp_p8(s2[0][0]), fast_exp_p8(s2[0][1]));
            ph[1] = pack_h2(fast_exp_p8(s2[0][2]), fast_exp_p8(s2[0][3]));
            ph[2] = pack_h2(fast_exp_p8(s2[1][0]), fast_exp_p8(s2[1][1]));
            ph[3] = pack_h2(fast_exp_p8(s2[1][2]), fast_exp_p8(s2[1][3]));
            mma16816h(o9, ph, of[0], of[1]);   // row sums -> l
#pragma unroll
            for (int dp = 0; dp < 4; dp++) {
                int r = ct * 16 + (lane & 15);
                int ch = dp * 2 + (lane >> 4);
                unsigned vf[4];
                ldsm4t(vf, stb + 16384 + swz(r, ch));
                mma16816h(o[2 * dp],     ph, vf[0], vf[1]);
                mma16816h(o[2 * dp + 1], ph, vf[2], vf[3]);
            }
        }
    }

    // ---- epilogue: o/l (2^-8 cancels) -> single fp16 att [B,N,C] ----
    const float inv0 = 1.0f / o9[0], inv1 = 1.0f / o9[2];
#pragma unroll
    for (int dt = 0; dt < 8; dt++) {
        int col = h * 64 + dt * 8 + (lane & 3) * 2;
        int r0 = qt * 128 + w * 16 + (lane >> 2);
        size_t i0 = ((size_t)b * NSEQ + r0) * CDIM + col;
        size_t i1 = ((size_t)b * NSEQ + r0 + 8) * CDIM + col;
        *reinterpret_cast<unsigned*>(&Att[i0]) =
            pack_h2(o[dt][0] * inv0, o[dt][1] * inv0);
        *reinterpret_cast<unsigned*>(&Att[i1]) =
            pack_h2(o[dt][2] * inv1, o[dt][3] * inv1);
    }
}

// ---------------------------------------------------------------------------
extern "C" void kernel_launch(void* const* d_in, const int* in_sizes, int n_in,
                              void* d_out, int out_size)
{
    const float* x      = (const float*)d_in[0];
    const float* cosb   = (const float*)d_in[1];
    const float* sinb   = (const float*)d_in[2];
    const float* w_qkv  = (const float*)d_in[3];
    const float* w_proj = (const float*)d_in[4];
    const float* b_proj = (const float*)d_in[5];
    const float* qw     = (const float*)d_in[6];
    const float* kw     = (const float*)d_in[7];
    float* out = (float*)d_out;

    __half *qkv16, *x16, *att16, *wq16, *wp16;
    __half *qh, *kh, *vh;
    cudaGetSymbolAddress((void**)&qkv16, g_qkv16);
    cudaGetSymbolAddress((void**)&x16, g_x16);
    cudaGetSymbolAddress((void**)&att16, g_att16);
    cudaGetSymbolAddress((void**)&wq16, g_wqkv16);
    cudaGetSymbolAddress((void**)&wp16, g_wproj16);
    cudaGetSymbolAddress((void**)&qh, g_qh);
    cudaGetSymbolAddress((void**)&kh, g_kh);
    cudaGetSymbolAddress((void**)&vh, g_vh);

    cudaFuncSetAttribute((const void*)gemm_hmma<false, true>,
                         cudaFuncAttributeMaxDynamicSharedMemorySize, GEMM_SMEM);
    cudaFuncSetAttribute((const void*)gemm_hmma<true, false>,
                         cudaFuncAttributeMaxDynamicSharedMemorySize, GEMM_SMEM);
    cudaFuncSetAttribute(flash_hmma,
                         cudaFuncAttributeMaxDynamicSharedMemorySize, FA_SMEM);

    // 0) splits: x, w_qkv, w_proj -> single fp16 (one launch)
    split_all<<<(NX4 + NQ4 + NP4) / 256, 256>>>(
        x, w_qkv, w_proj, x16, wq16, wp16);

    // 1) qkv = x @ w_qkv^T (fp16 in, fp16 out)
    gemm_hmma<false, true><<<dim3(QKVDIM / 128, MROWS / 128), 256, GEMM_SMEM>>>(
        x16, wq16, nullptr, qkv16, QKVDIM);

    // 2) rmsnorm + rope -> fp16 Q(pre-scaled), K, V
    prep_kernel<<<dim3(MROWS, 2), 256>>>(qkv16, cosb, sinb, qw, kw, qh, kh, vh);

    // 3) flash attention -> att single fp16
    flash_hmma<<<dim3(BHTOT, NSEQ / 128), 256, FA_SMEM>>>(qh, kh, vh, att16);

    // 4) out = att @ w_proj^T + b (fp16 in, fp32 out)
    gemm_hmma<true, false><<<dim3(CDIM / 128, MROWS / 128), 256, GEMM_SMEM>>>(
        att16, wp16, b_proj, out, CDIM);
}

// round 15
// speedup vs baseline: 2.9891x; 1.1277x over previous
#include <cuda_runtime.h>
#include <cuda_fp16.h>
#include <math.h>

// Problem constants
#define B_SZ 4
#define NSEQ 2048
#define CDIM 1024
#define NHEAD 16
#define HD 64
#define MROWS 8192
#define QKVDIM 3072
#define BHTOT 64

// ---------------------------------------------------------------------------
// Static device scratch (allocation-free kernel_launch)
// ---------------------------------------------------------------------------
__device__ __half g_qkv16[MROWS * QKVDIM];        // fp16 qkv intermediate
__device__ __half g_x16[MROWS * CDIM];            // x single fp16
__device__ __half g_att16[MROWS * CDIM];          // att single fp16
__device__ __half g_wqkv16[QKVDIM * CDIM];        // w_qkv single fp16
__device__ __half g_wproj16[CDIM * CDIM];         // w_proj single fp16
__device__ __half g_qh[BHTOT * NSEQ * HD];        // fp16 Q (pre-scaled 1/8)
__device__ __half g_kh[BHTOT * NSEQ * HD];        // fp16 K
__device__ __half g_vh[BHTOT * NSEQ * HD];        // fp16 V

// ---------------------------------------------------------------------------
// Helpers
// ---------------------------------------------------------------------------
__device__ __forceinline__ unsigned smem_u32(const void* p) {
    unsigned a;
    asm("{ .reg .u64 t; cvta.to.shared.u64 t, %1; cvt.u32.u64 %0, t; }"
        : "=r"(a) : "l"(p));
    return a;
}

__device__ __forceinline__ void ldsm4(unsigned* r, unsigned a) {
    asm volatile("ldmatrix.sync.aligned.m8n8.x4.shared.b16 {%0,%1,%2,%3}, [%4];"
        : "=r"(r[0]), "=r"(r[1]), "=r"(r[2]), "=r"(r[3]) : "r"(a));
}
__device__ __forceinline__ void ldsm4t(unsigned* r, unsigned a) {
    asm volatile("ldmatrix.sync.aligned.m8n8.x4.trans.shared.b16 {%0,%1,%2,%3}, [%4];"
        : "=r"(r[0]), "=r"(r[1]), "=r"(r[2]), "=r"(r[3]) : "r"(a));
}
// fp16 HMMA
__device__ __forceinline__ void mma16816h(float* d, const unsigned* a,
                                          unsigned b0, unsigned b1) {
    asm volatile(
        "mma.sync.aligned.m16n8k16.row.col.f32.f16.f16.f32 "
        "{%0,%1,%2,%3}, {%4,%5,%6,%7}, {%8,%9}, {%0,%1,%2,%3};"
        : "+f"(d[0]), "+f"(d[1]), "+f"(d[2]), "+f"(d[3])
        : "r"(a[0]), "r"(a[1]), "r"(a[2]), "r"(a[3]), "r"(b0), "r"(b1));
}

#define CP16(sa, g) \
    asm volatile("cp.async.cg.shared.global [%0], [%1], 16;" :: "r"(sa), "l"(g))
#define CP_COMMIT() asm volatile("cp.async.commit_group;")
#define CP_WAIT1()  asm volatile("cp.async.wait_group 1;")
#define CP_WAIT0()  asm volatile("cp.async.wait_group 0;")

// chunk swizzle: 128B rows, 8 x 16B chunks
__device__ __forceinline__ unsigned swz(int row, int chunk) {
    return (unsigned)(row * 128 + ((chunk ^ (row & 7)) * 16));
}

// exp(x) * 2^-8 via MUFU: 1 FFMA + 1 MUFU.EX2 (separate pipe from FMA).
// ex2.approx rel err ~2^-21. Inputs bounded |x| <= ~16.1.
__device__ __forceinline__ float exp_p8(float x) {
    float e;
    float a = fmaf(x, 1.442695041f, -8.0f);
    asm("ex2.approx.f32 %0, %1;" : "=f"(e) : "f"(a));
    return e;
}

__device__ __forceinline__ unsigned pack_h2(float x, float y) {
    __half2 h = __floats2half2_rn(x, y);
    return *reinterpret_cast<unsigned*>(&h);
}

// ---------------------------------------------------------------------------
// One merged split kernel: x, w_qkv, w_proj -> single fp16
// ---------------------------------------------------------------------------
#define NX4 (MROWS * CDIM / 4)
#define NQ4 (QKVDIM * CDIM / 4)
#define NP4 (CDIM * CDIM / 4)

__global__ __launch_bounds__(256) void split_all(
    const float* __restrict__ x, const float* __restrict__ wq,
    const float* __restrict__ wp,
    __half* __restrict__ x16, __half* __restrict__ wq16,
    __half* __restrict__ wp16)
{
    int i = blockIdx.x * 256 + threadIdx.x;
    const float* src;
    __half* dst;
    if (i < NX4)            { src = x;  dst = x16; }
    else if (i < NX4 + NQ4) { i -= NX4; src = wq; dst = wq16; }
    else                    { i -= NX4 + NQ4; src = wp; dst = wp16; }
    float4 v = reinterpret_cast<const float4*>(src)[i];
    reinterpret_cast<unsigned*>(dst)[2 * i]     = pack_h2(v.x, v.y);
    reinterpret_cast<unsigned*>(dst)[2 * i + 1] = pack_h2(v.z, v.w);
}

// ---------------------------------------------------------------------------
// fp16 HMMA GEMM (NT): C[m,n] = sum_k A[m,k]*B[n,k] (+bias). Single-pass.
// 128x128 tile, BK=64 stage {A 16K | B 16K} = 32KB x 3 stages -> 2 CTAs/SM.
// HALFOUT: store fp16 (half2 packs); else fp32.
// ---------------------------------------------------------------------------
#define GS_STAGE 32768
#define GEMM_SMEM (3 * GS_STAGE)     // 98304
#define NSTAGES 16                   // K=1024 / 64

template <bool BIAS, bool HALFOUT>
__global__ __launch_bounds__(256) void gemm_hmma(
    const __half* __restrict__ A, const __half* __restrict__ B,
    const float* __restrict__ bias, void* __restrict__ Cv, int N)
{
    extern __shared__ __align__(128) char smc[];
    const unsigned sb = smem_u32(smc);
    const int t = threadIdx.x, lane = t & 31, wid = t >> 5;
    const int wm = wid & 1, wn = wid >> 1;
    const int m0 = blockIdx.y * 128, n0 = blockIdx.x * 128;
    const int K = 1024;
    const int grp = lane >> 3, ri = lane & 7;

    float acc[4][4][4];
#pragma unroll
    for (int a = 0; a < 4; a++)
#pragma unroll
        for (int b = 0; b < 4; b++)
#pragma unroll
            for (int c = 0; c < 4; c++) acc[a][b][c] = 0.f;

    const __half* srcs[2] = { A + (size_t)m0 * K, B + (size_t)n0 * K };

    auto issue = [&](int s, int buf) {
        const int k0 = s * 64;
        const unsigned stb = sb + buf * GS_STAGE;
#pragma unroll
        for (int m = 0; m < 2; m++) {
            const unsigned mb = stb + m * 16384;
            const __half* g = srcs[m] + k0;
#pragma unroll
            for (int i = 0; i < 4; i++) {
                int idx = i * 256 + t;
                int r = idx >> 3, ch = idx & 7;
                CP16(mb + swz(r, ch), g + (size_t)r * K + ch * 8);
            }
        }
    };

    issue(0, 0); CP_COMMIT();
    issue(1, 1); CP_COMMIT();

    for (int it = 0; it < NSTAGES; it++) {
        if (it == NSTAGES - 1) { CP_WAIT0(); } else { CP_WAIT1(); }
        __syncthreads();
        if (it + 2 < NSTAGES) {
            issue(it + 2, (it + 2) % 3);
            CP_COMMIT();
        }
        const unsigned ab = sb + (it % 3) * GS_STAGE;
        const unsigned bb = ab + 16384;
#pragma unroll
        for (int k4 = 0; k4 < 4; k4++) {
            unsigned af[4][4], bf[2][4];
#pragma unroll
            for (int mt = 0; mt < 4; mt++) {
                int r = wm * 64 + mt * 16 + (grp & 1) * 8 + ri;
                int ch = k4 * 2 + (grp >> 1);
                ldsm4(af[mt], ab + swz(r, ch));
            }
#pragma unroll
            for (int np = 0; np < 2; np++) {
                int r = wn * 32 + np * 16 + ((grp >> 1) & 1) * 8 + ri;
                int ch = k4 * 2 + (grp & 1);
                ldsm4(bf[np], bb + swz(r, ch));
            }
#pragma unroll
            for (int mt = 0; mt < 4; mt++)
#pragma unroll
                for (int np = 0; np < 2; np++) {
                    mma16816h(acc[mt][2 * np],     af[mt], bf[np][0], bf[np][1]);
                    mma16816h(acc[mt][2 * np + 1], af[mt], bf[np][2], bf[np][3]);
                }
        }
    }

    // epilogue
#pragma unroll
    for (int mt = 0; mt < 4; mt++)
#pragma unroll
        for (int nt = 0; nt < 4; nt++) {
            int col = n0 + wn * 32 + nt * 8 + (lane & 3) * 2;
            int r0 = m0 + wm * 64 + mt * 16 + (lane >> 2);
            float bx = 0.f, by = 0.f;
            if (BIAS) { bx = bias[col]; by = bias[col + 1]; }
            float a0 = acc[mt][nt][0] + bx, a1 = acc[mt][nt][1] + by;
            float a2 = acc[mt][nt][2] + bx, a3 = acc[mt][nt][3] + by;
            if (HALFOUT) {
                __half* C = (__half*)Cv;
                *reinterpret_cast<unsigned*>(&C[(size_t)r0 * N + col]) =
                    pack_h2(a0, a1);
                *reinterpret_cast<unsigned*>(&C[(size_t)(r0 + 8) * N + col]) =
                    pack_h2(a2, a3);
            } else {
                float* C = (float*)Cv;
                *reinterpret_cast<float2*>(&C[(size_t)r0 * N + col]) =
                    make_float2(a0, a1);
                *reinterpret_cast<float2*>(&C[(size_t)(r0 + 8) * N + col]) =
                    make_float2(a2, a3);
            }
        }
}

// ---------------------------------------------------------------------------
// Prep: read fp16 qkv, RMSNorm(q,k), RoPE(q,k); emit fp16 Q (pre-scaled 1/8),
// fp16 K, fp16 V in [b*H+h][n][64] layout. Warp per (b,n,h).
// ---------------------------------------------------------------------------
__global__ __launch_bounds__(256) void prep_kernel(
    const __half* __restrict__ qkv,
    const float* __restrict__ cosb, const float* __restrict__ sinb,
    const float* __restrict__ qw, const float* __restrict__ kw,
    __half* __restrict__ Qh, __half* __restrict__ Kh,
    __half* __restrict__ Vh)
{
    const int bn = blockIdx.x;
    const int h = (blockIdx.y << 3) | (threadIdx.x >> 5);
    const int l = threadIdx.x & 31;
    const int b = bn >> 11;
    const int n = bn & 2047;

    const __half* base = qkv + (size_t)bn * QKVDIM + h * HD;
    float q1 = __half2float(base[l]);
    float q2 = __half2float(base[l + 32]);
    float k1 = __half2float(base[CDIM + l]);
    float k2 = __half2float(base[CDIM + l + 32]);
    float v1 = __half2float(base[2 * CDIM + l]);
    float v2 = __half2float(base[2 * CDIM + l + 32]);

    float sq = q1 * q1 + q2 * q2;
    float sk = k1 * k1 + k2 * k2;
#pragma unroll
    for (int o = 16; o > 0; o >>= 1) {
        sq += __shfl_xor_sync(0xffffffffu, sq, o);
        sk += __shfl_xor_sync(0xffffffffu, sk, o);
    }
    float rq = rsqrtf(sq * (1.f / 64.f) + 1e-6f);
    float rk = rsqrtf(sk * (1.f / 64.f) + 1e-6f);
    q1 *= rq * qw[l]; q2 *= rq * qw[l + 32];
    k1 *= rk * kw[l]; k2 *= rk * kw[l + 32];

    float c1 = cosb[n * HD + l], c2 = cosb[n * HD + l + 32];
    float s1 = sinb[n * HD + l], s2 = sinb[n * HD + l + 32];

    size_t o = (((size_t)(b * NHEAD + h)) * NSEQ + n) * HD;
    Qh[o + l]      = __float2half_rn((q1 * c1 - q2 * s1) * 0.125f);
    Qh[o + l + 32] = __float2half_rn((q2 * c2 + q1 * s2) * 0.125f);
    Kh[o + l]      = __float2half_rn(k1 * c1 - k2 * s1);
    Kh[o + l + 32] = __float2half_rn(k2 * c2 + k1 * s2);
    Vh[o + l]      = __float2half_rn(v1);
    Vh[o + l + 32] = __float2half_rn(v2);
}

// ---------------------------------------------------------------------------
// Flash attention on fp16 HMMA. 256 threads, 128 q rows, KV tiles of 128.
// Fused per-ct pipeline: S MMAs (16 kv rows) -> exp (MUFU) -> l-MMA -> PV.
// NO online max (|s| <= 16 bound); P = exp(s)*2^-8 via ex2.approx with
// folded bias; out = o/l (2^-8 cancels), single fp16.
// SMEM: Q 16K | stage{Kh 16K,Vh 16K}x2 = 64K | ones 512B -> 2 CTAs/SM.
// ---------------------------------------------------------------------------
#define FA_STAGE 32768
#define FA_SMEM (16384 + 2 * FA_STAGE + 512)   // 82432

__global__ __launch_bounds__(256, 2) void flash_hmma(
    const __half* __restrict__ Qh, const __half* __restrict__ Kh,
    const __half* __restrict__ Vh, __half* __restrict__ Att)
{
    extern __shared__ __align__(128) char smc[];
    const unsigned sb = smem_u32(smc);
    const unsigned ob = sb + 16384 + 2 * FA_STAGE;   // ones tile (512B)
    const int t = threadIdx.x, lane = t & 31, w = t >> 5;
    const int bh = blockIdx.x, qt = blockIdx.y;
    const int b = bh >> 4, h = bh & 15;
    const int grp = lane >> 3, ri = lane & 7;

    const size_t qoff = ((size_t)bh * NSEQ + qt * 128) * HD;
    const size_t kvoff = (size_t)bh * NSEQ * HD;

    const __half* mats[2] = {Kh, Vh};

    auto issue = [&](int j, int s) {
        const unsigned stb = sb + 16384 + s * FA_STAGE;
#pragma unroll
        for (int m = 0; m < 2; m++) {
            const __half* g = mats[m] + kvoff + (size_t)(j * 128) * HD;
            const unsigned mb = stb + m * 16384;
#pragma unroll
            for (int i = 0; i < 4; i++) {
                int idx = i * 256 + t;
                int r = idx >> 3, ch = idx & 7;
                CP16(mb + swz(r, ch), g + (size_t)r * HD + ch * 8);
            }
        }
    };

    issue(0, 0);
    CP_COMMIT();

    // Q tile -> smem (swizzled); ones tile init
#pragma unroll
    for (int i = 0; i < 4; i++) {
        int idx = i * 256 + t;
        int r = idx >> 3, ch = idx & 7;
        *reinterpret_cast<uint4*>(smc + swz(r, ch)) =
            *reinterpret_cast<const uint4*>(Qh + qoff + (size_t)r * HD + ch * 8);
    }
    if (t < 128)
        *reinterpret_cast<unsigned*>(smc + (16384 + 2 * FA_STAGE) + t * 4)
            = 0x3C003C00u;   // half2(1, 1)
    __syncthreads();

    unsigned qf[4][4];
#pragma unroll
    for (int kt = 0; kt < 4; kt++) {
        int r = w * 16 + (grp & 1) * 8 + ri;
        int ch = kt * 2 + (grp >> 1);
        ldsm4(qf[kt], sb + swz(r, ch));
    }
    // ones B-frag (k16 x n8, all 1.0) — loaded once
    unsigned of[4];
    ldsm4t(of, ob + (lane & 15) * 32);

    float o[8][4], o9[4];
#pragma unroll
    for (int d = 0; d < 8; d++)
#pragma unroll
        for (int c = 0; c < 4; c++) o[d][c] = 0.f;
#pragma unroll
    for (int c = 0; c < 4; c++) o9[c] = 0.f;

    for (int j = 0; j < NSEQ / 128; j++) {
        CP_WAIT0();
        __syncthreads();
        if (j + 1 < NSEQ / 128) {
            issue(j + 1, (j + 1) & 1);
            CP_COMMIT();
        }
        const unsigned stb = sb + 16384 + (j & 1) * FA_STAGE;

        // fused per-ct: S (16 kv rows) -> exp (MUFU) -> l-MMA -> PV
#pragma unroll
        for (int ct = 0; ct < 8; ct++) {
            float s2[2][4];
#pragma unroll
            for (int c = 0; c < 4; c++) { s2[0][c] = 0.f; s2[1][c] = 0.f; }
#pragma unroll
            for (int kt = 0; kt < 4; kt++) {
                int r = ct * 16 + ((grp >> 1) & 1) * 8 + ri;
                int ch = kt * 2 + (grp & 1);
                unsigned kf[4];
                ldsm4(kf, stb + swz(r, ch));
                mma16816h(s2[0], qf[kt], kf[0], kf[1]);
                mma16816h(s2[1], qf[kt], kf[2], kf[3]);
            }
            unsigned ph[4];
            ph[0] = pack_h2(exp_p8(s2[0][0]), exp_p8(s2[0][1]));
            ph[1] = pack_h2(exp_p8(s2[0][2]), exp_p8(s2[0][3]));
            ph[2] = pack_h2(exp_p8(s2[1][0]), exp_p8(s2[1][1]));
            ph[3] = pack_h2(exp_p8(s2[1][2]), exp_p8(s2[1][3]));
            mma16816h(o9, ph, of[0], of[1]);   // row sums -> l
#pragma unroll
            for (int dp = 0; dp < 4; dp++) {
                int r = ct * 16 + (lane & 15);
                int ch = dp * 2 + (lane >> 4);
                unsigned vf[4];
                ldsm4t(vf, stb + 16384 + swz(r, ch));
                mma16816h(o[2 * dp],     ph, vf[0], vf[1]);
                mma16816h(o[2 * dp + 1], ph, vf[2], vf[3]);
            }
        }
    }

    // ---- epilogue: o/l (2^-8 cancels) -> single fp16 att [B,N,C] ----
    const float inv0 = 1.0f / o9[0], inv1 = 1.0f / o9[2];
#pragma unroll
    for (int dt = 0; dt < 8; dt++) {
        int col = h * 64 + dt * 8 + (lane & 3) * 2;
        int r0 = qt * 128 + w * 16 + (lane >> 2);
        size_t i0 = ((size_t)b * NSEQ + r0) * CDIM + col;
        size_t i1 = ((size_t)b * NSEQ + r0 + 8) * CDIM + col;
        *reinterpret_cast<unsigned*>(&Att[i0]) =
            pack_h2(o[dt][0] * inv0, o[dt][1] * inv0);
        *reinterpret_cast<unsigned*>(&Att[i1]) =
            pack_h2(o[dt][2] * inv1, o[dt][3] * inv1);
    }
}

// ---------------------------------------------------------------------------
extern "C" void kernel_launch(void* const* d_in, const int* in_sizes, int n_in,
                              void* d_out, int out_size)
{
    const float* x      = (const float*)d_in[0];
    const float* cosb   = (const float*)d_in[1];
    const float* sinb   = (const float*)d_in[2];
    const float* w_qkv  = (const float*)d_in[3];
    const float* w_proj = (const float*)d_in[4];
    const float* b_proj = (const float*)d_in[5];
    const float* qw     = (const float*)d_in[6];
    const float* kw     = (const float*)d_in[7];
    float* out = (float*)d_out;

    __half *qkv16, *x16, *att16, *wq16, *wp16;
    __half *qh, *kh, *vh;
    cudaGetSymbolAddress((void**)&qkv16, g_qkv16);
    cudaGetSymbolAddress((void**)&x16, g_x16);
    cudaGetSymbolAddress((void**)&att16, g_att16);
    cudaGetSymbolAddress((void**)&wq16, g_wqkv16);
    cudaGetSymbolAddress((void**)&wp16, g_wproj16);
    cudaGetSymbolAddress((void**)&qh, g_qh);
    cudaGetSymbolAddress((void**)&kh, g_kh);
    cudaGetSymbolAddress((void**)&vh, g_vh);

    cudaFuncSetAttribute((const void*)gemm_hmma<false, true>,
                         cudaFuncAttributeMaxDynamicSharedMemorySize, GEMM_SMEM);
    cudaFuncSetAttribute((const void*)gemm_hmma<true, false>,
                         cudaFuncAttributeMaxDynamicSharedMemorySize, GEMM_SMEM);
    cudaFuncSetAttribute(flash_hmma,
                         cudaFuncAttributeMaxDynamicSharedMemorySize, FA_SMEM);

    // 0) splits: x, w_qkv, w_proj -> single fp16 (one launch)
    split_all<<<(NX4 + NQ4 + NP4) / 256, 256>>>(
        x, w_qkv, w_proj, x16, wq16, wp16);

    // 1) qkv = x @ w_qkv^T (fp16 in, fp16 out)
    gemm_hmma<false, true><<<dim3(QKVDIM / 128, MROWS / 128), 256, GEMM_SMEM>>>(
        x16, wq16, nullptr, qkv16, QKVDIM);

    // 2) rmsnorm + rope -> fp16 Q(pre-scaled), K, V
    prep_kernel<<<dim3(MROWS, 2), 256>>>(qkv16, cosb, sinb, qw, kw, qh, kh, vh);

    // 3) flash attention -> att single fp16
    flash_hmma<<<dim3(BHTOT, NSEQ / 128), 256, FA_SMEM>>>(qh, kh, vh, att16);

    // 4) out = att @ w_proj^T + b (fp16 in, fp32 out)
    gemm_hmma<true, false><<<dim3(CDIM / 128, MROWS / 128), 256, GEMM_SMEM>>>(
        att16, wp16, b_proj, out, CDIM);
}